// round 1
// baseline (speedup 1.0000x reference)
#include <cuda_runtime.h>
#include <math.h>
#include <stdint.h>

// ---------------- problem constants ----------------
#define BATCH   16
#define IMG     112
#define CC      192
#define NHEADS  6
#define DHEAD   32
#define WSZ     7
#define NTOK    49          // tokens per window
#define NWIN    4096        // total windows = 16 * 256
#define MROWS   200704      // total tokens = 16*112*112
#define HID     768

// ---------------- scratch (device globals; no allocation allowed) ----------------
__device__ float g_xw[(size_t)MROWS * CC];                    // LN'd shifted windowed x  (also reused for LN2 output)
__device__ float g_q[(size_t)NWIN * NHEADS * NTOK * DHEAD];
__device__ float g_k[(size_t)NWIN * NHEADS * NTOK * DHEAD];
__device__ float g_v[(size_t)NWIN * NHEADS * NTOK * DHEAD];
__device__ float g_ao[(size_t)MROWS * CC];                    // attention out (window-token order)
__device__ float g_x2[(size_t)MROWS * CC];                    // shortcut + proj (pixel order)
__device__ float g_h[(size_t)MROWS * HID];                    // gelu(fc1)

// ---------------- f32x2 helpers (Blackwell FFMA2) ----------------
__device__ __forceinline__ void fma2(unsigned long long &c, unsigned long long a, unsigned long long b) {
    asm("fma.rn.f32x2 %0, %1, %2, %0;" : "+l"(c) : "l"(a), "l"(b));
}
__device__ __forceinline__ float2 up2(unsigned long long v) {
    float2 r; asm("mov.b64 {%0, %1}, %2;" : "=f"(r.x), "=f"(r.y) : "l"(v)); return r;
}

// ---------------- LN kernel (optionally fused shift + window partition) ----------------
// one warp per token; 192 channels -> 6 per lane
template<bool WINDOWED>
__global__ __launch_bounds__(256) void ln_kernel(const float* __restrict__ src_full,
                                                 const float* __restrict__ gam,
                                                 const float* __restrict__ bet,
                                                 float* __restrict__ out) {
    int t = blockIdx.x * 8 + (threadIdx.x >> 5);
    int lane = threadIdx.x & 31;
    const float* src;
    if (WINDOWED) {
        int win = t / NTOK, n = t - win * NTOK;
        int b = win >> 8, wi = win & 255;
        int hh = (wi >> 4) * WSZ + n / WSZ;
        int ww = (wi & 15) * WSZ + n % WSZ;
        int sh = hh + 3; if (sh >= IMG) sh -= IMG;
        int sw = ww + 3; if (sw >= IMG) sw -= IMG;
        src = src_full + (size_t)((b * IMG + sh) * IMG + sw) * CC;
    } else {
        src = src_full + (size_t)t * CC;
    }
    float v[6]; float s = 0.f, s2 = 0.f;
    #pragma unroll
    for (int i = 0; i < 6; i++) { float a = src[lane * 6 + i]; v[i] = a; s += a; s2 += a * a; }
    #pragma unroll
    for (int o = 16; o; o >>= 1) {
        s  += __shfl_xor_sync(0xffffffffu, s,  o);
        s2 += __shfl_xor_sync(0xffffffffu, s2, o);
    }
    float mean = s * (1.f / 192.f);
    float var  = s2 * (1.f / 192.f) - mean * mean;
    float rstd = rsqrtf(var + 1e-5f);
    float* dst = out + (size_t)t * CC;
    #pragma unroll
    for (int i = 0; i < 6; i++) {
        int c = lane * 6 + i;
        dst[c] = (v[i] - mean) * rstd * gam[c] + bet[c];
    }
}

// ---------------- generic fp32 GEMM with FFMA2 inner loop + fused epilogues ----------------
// C(M,N) = A(M,K) @ W(K,N) + bias, epilogue variants.
// BM=64 BN=64 BK=16, 256 threads, 4x4 per thread.
// EPI: 1 = qkv scatter (q scaled), 2 = proj -> unshift/unwindow + shortcut -> x2,
//      3 = gelu -> out, 4 = out = addsrc + val
#define BM 64
#define BN 64
#define BK 16

__device__ __forceinline__ float gelu_exact(float x) {
    return 0.5f * x * (1.f + erff(x * 0.70710678118654752f));
}

template<int EPI>
__global__ __launch_bounds__(256) void gemm_kernel(const float* __restrict__ A,
                                                   const float* __restrict__ Wm,
                                                   const float* __restrict__ bias,
                                                   float* __restrict__ Cout,
                                                   int K, int Nn,
                                                   const float* __restrict__ addsrc) {
    __shared__ float As[BK][BM + 4];          // transposed A tile
    __shared__ float Bsd[BK][2 * BN + 8];     // B tile, each value duplicated pairwise
    int tid = threadIdx.x;
    int bm = blockIdx.y * BM;
    int bn = blockIdx.x * BN;
    int a_row = tid >> 2, a_k = (tid & 3) << 2;
    int b_k = tid >> 4,  b_n = (tid & 15) << 2;
    int tr = (tid >> 4) << 2, tc = (tid & 15) << 2;
    unsigned long long acc[2][4] = {{0ull,0ull,0ull,0ull},{0ull,0ull,0ull,0ull}};

    const float* Aptr = A + (size_t)(bm + a_row) * K + a_k;
    const float* Bptr = Wm + (size_t)b_k * Nn + bn + b_n;

    for (int k0 = 0; k0 < K; k0 += BK) {
        float4 av = *(const float4*)(Aptr + k0);
        float4 bv = *(const float4*)(Bptr + (size_t)k0 * Nn);
        As[a_k + 0][a_row] = av.x; As[a_k + 1][a_row] = av.y;
        As[a_k + 2][a_row] = av.z; As[a_k + 3][a_row] = av.w;
        *(float4*)&Bsd[b_k][2 * b_n]     = make_float4(bv.x, bv.x, bv.y, bv.y);
        *(float4*)&Bsd[b_k][2 * b_n + 4] = make_float4(bv.z, bv.z, bv.w, bv.w);
        __syncthreads();
        #pragma unroll
        for (int k = 0; k < BK; k++) {
            ulonglong2 a  = *(const ulonglong2*)&As[k][tr];        // rows (tr,tr+1),(tr+2,tr+3)
            ulonglong2 p0 = *(const ulonglong2*)&Bsd[k][2 * tc];       // (b0,b0),(b1,b1)
            ulonglong2 p1 = *(const ulonglong2*)&Bsd[k][2 * tc + 4];   // (b2,b2),(b3,b3)
            fma2(acc[0][0], a.x, p0.x); fma2(acc[0][1], a.x, p0.y);
            fma2(acc[0][2], a.x, p1.x); fma2(acc[0][3], a.x, p1.y);
            fma2(acc[1][0], a.y, p0.x); fma2(acc[1][1], a.y, p0.y);
            fma2(acc[1][2], a.y, p1.x); fma2(acc[1][3], a.y, p1.y);
        }
        __syncthreads();
    }

    float vals[4][4];
    #pragma unroll
    for (int pi = 0; pi < 2; pi++)
        #pragma unroll
        for (int j = 0; j < 4; j++) {
            float2 f = up2(acc[pi][j]);
            vals[2 * pi + 0][j] = f.x;
            vals[2 * pi + 1][j] = f.y;
        }

    float4 bv4 = *(const float4*)&bias[bn + tc];
    float bcol[4] = {bv4.x, bv4.y, bv4.z, bv4.w};

    if constexpr (EPI == 1) {
        // qkv scatter: col -> (t3, head, dd)
        int colb = bn + tc;
        int t3 = colb / 192;
        int head = (colb % 192) >> 5;
        int dd = colb & 31;
        float* dst0 = (t3 == 0) ? g_q : ((t3 == 1) ? g_k : g_v);
        float scale = (t3 == 0) ? 0.17677669529663687f : 1.f;
        #pragma unroll
        for (int i = 0; i < 4; i++) {
            int row = bm + tr + i;
            int win = row / NTOK, n = row - win * NTOK;
            float4 o;
            o.x = (vals[i][0] + bcol[0]) * scale;
            o.y = (vals[i][1] + bcol[1]) * scale;
            o.z = (vals[i][2] + bcol[2]) * scale;
            o.w = (vals[i][3] + bcol[3]) * scale;
            *(float4*)&dst0[(((size_t)win * NHEADS + head) * NTOK + n) * DHEAD + dd] = o;
        }
    } else if constexpr (EPI == 2) {
        // proj: window-token row -> pixel, add shortcut x, write x2
        #pragma unroll
        for (int i = 0; i < 4; i++) {
            int row = bm + tr + i;
            int win = row / NTOK, n = row - win * NTOK;
            int b = win >> 8, wi = win & 255;
            int hh = (wi >> 4) * WSZ + n / WSZ;
            int ww = (wi & 15) * WSZ + n % WSZ;
            int p = hh + 3; if (p >= IMG) p -= IMG;
            int q = ww + 3; if (q >= IMG) q -= IMG;
            size_t base = (size_t)((b * IMG + p) * IMG + q) * CC + bn + tc;
            float4 sc = *(const float4*)&addsrc[base];
            float4 o;
            o.x = vals[i][0] + bcol[0] + sc.x;
            o.y = vals[i][1] + bcol[1] + sc.y;
            o.z = vals[i][2] + bcol[2] + sc.z;
            o.w = vals[i][3] + bcol[3] + sc.w;
            *(float4*)&Cout[base] = o;
        }
    } else if constexpr (EPI == 3) {
        #pragma unroll
        for (int i = 0; i < 4; i++) {
            int row = bm + tr + i;
            size_t base = (size_t)row * Nn + bn + tc;
            float4 o;
            o.x = gelu_exact(vals[i][0] + bcol[0]);
            o.y = gelu_exact(vals[i][1] + bcol[1]);
            o.z = gelu_exact(vals[i][2] + bcol[2]);
            o.w = gelu_exact(vals[i][3] + bcol[3]);
            *(float4*)&Cout[base] = o;
        }
    } else if constexpr (EPI == 4) {
        #pragma unroll
        for (int i = 0; i < 4; i++) {
            int row = bm + tr + i;
            size_t base = (size_t)row * Nn + bn + tc;
            float4 sc = *(const float4*)&addsrc[base];
            float4 o;
            o.x = vals[i][0] + bcol[0] + sc.x;
            o.y = vals[i][1] + bcol[1] + sc.y;
            o.z = vals[i][2] + bcol[2] + sc.z;
            o.w = vals[i][3] + bcol[3] + sc.w;
            *(float4*)&Cout[base] = o;
        }
    } else {
        #pragma unroll
        for (int i = 0; i < 4; i++) {
            int row = bm + tr + i;
            size_t base = (size_t)row * Nn + bn + tc;
            float4 o;
            o.x = vals[i][0] + bcol[0]; o.y = vals[i][1] + bcol[1];
            o.z = vals[i][2] + bcol[2]; o.w = vals[i][3] + bcol[3];
            *(float4*)&Cout[base] = o;
        }
    }
}

// ---------------- windowed attention ----------------
// one block per (window, head); 128 threads (4 warps), warp processes rows r, r+4, ...
__global__ __launch_bounds__(128) void attn_kernel(const float* __restrict__ mask,
                                                   const float* __restrict__ rpb,
                                                   float* __restrict__ out) {
    int wh = blockIdx.x;
    int win = wh / NHEADS, head = wh - win * NHEADS;
    __shared__ float sq[NTOK * 36], sk[NTOK * 36], sv[NTOK * 36];
    __shared__ float sp[4][64];
    int tid = threadIdx.x;
    const float* qb = g_q + (size_t)wh * (NTOK * DHEAD);
    const float* kb = g_k + (size_t)wh * (NTOK * DHEAD);
    const float* vb = g_v + (size_t)wh * (NTOK * DHEAD);
    for (int i = tid; i < NTOK * DHEAD; i += 128) {
        int r = i >> 5, c = i & 31;
        sq[r * 36 + c] = qb[i];
        sk[r * 36 + c] = kb[i];
        sv[r * 36 + c] = vb[i];
    }
    __syncthreads();
    int warp = tid >> 5, lane = tid & 31;
    const float* mrow = mask + (size_t)(win & 255) * (NTOK * NTOK);
    int i2a = lane / WSZ, j2a = lane - i2a * WSZ;
    int m1 = lane + 32;
    int i2b = m1 / WSZ, j2b = m1 - i2b * WSZ;   // valid only when lane < 17

    for (int r = warp; r < NTOK; r += 4) {
        float s0 = 0.f, s1 = 0.f;
        #pragma unroll
        for (int dd = 0; dd < DHEAD; dd += 4) {
            float4 q4 = *(const float4*)&sq[r * 36 + dd];
            float4 k4 = *(const float4*)&sk[lane * 36 + dd];
            s0 = fmaf(q4.x, k4.x, fmaf(q4.y, k4.y, fmaf(q4.z, k4.z, fmaf(q4.w, k4.w, s0))));
            if (lane < 17) {
                float4 k4b = *(const float4*)&sk[m1 * 36 + dd];
                s1 = fmaf(q4.x, k4b.x, fmaf(q4.y, k4b.y, fmaf(q4.z, k4b.z, fmaf(q4.w, k4b.w, s1))));
            }
        }
        int i1 = r / WSZ, j1 = r - i1 * WSZ;
        int rel0 = (i1 - i2a + 6) * 13 + (j1 - j2a + 6);
        s0 += rpb[rel0 * NHEADS + head] + mrow[r * NTOK + lane];
        if (lane < 17) {
            int rel1 = (i1 - i2b + 6) * 13 + (j1 - j2b + 6);
            s1 += rpb[rel1 * NHEADS + head] + mrow[r * NTOK + m1];
        } else {
            s1 = -1e30f;
        }
        float mx = fmaxf(s0, s1);
        #pragma unroll
        for (int o = 16; o; o >>= 1) mx = fmaxf(mx, __shfl_xor_sync(0xffffffffu, mx, o));
        float e0 = __expf(s0 - mx);
        float e1 = (lane < 17) ? __expf(s1 - mx) : 0.f;
        float sum = e0 + e1;
        #pragma unroll
        for (int o = 16; o; o >>= 1) sum += __shfl_xor_sync(0xffffffffu, sum, o);
        float inv = 1.f / sum;
        sp[warp][lane] = e0 * inv;
        if (lane < 17) sp[warp][lane + 32] = e1 * inv;
        __syncwarp();
        float acc = 0.f;
        #pragma unroll
        for (int m = 0; m < NTOK; m++)
            acc = fmaf(sp[warp][m], sv[m * 36 + lane], acc);
        out[((size_t)win * NTOK + r) * CC + head * DHEAD + lane] = acc;
        __syncwarp();
    }
}

// ---------------- launch ----------------
extern "C" void kernel_launch(void* const* d_in, const int* in_sizes, int n_in,
                              void* d_out, int out_size) {
    const float* x      = (const float*)d_in[0];
    const float* amask  = (const float*)d_in[1];
    const float* n1g    = (const float*)d_in[2];
    const float* n1b    = (const float*)d_in[3];
    const float* qkv_w  = (const float*)d_in[4];
    const float* qkv_b  = (const float*)d_in[5];
    const float* rpb    = (const float*)d_in[6];
    const float* proj_w = (const float*)d_in[7];
    const float* proj_b = (const float*)d_in[8];
    const float* n2g    = (const float*)d_in[9];
    const float* n2b    = (const float*)d_in[10];
    const float* fc1_w  = (const float*)d_in[11];
    const float* fc1_b  = (const float*)d_in[12];
    const float* fc2_w  = (const float*)d_in[13];
    const float* fc2_b  = (const float*)d_in[14];
    float* out = (float*)d_out;

    float *xw, *ao, *x2, *hbuf;
    cudaGetSymbolAddress((void**)&xw,   g_xw);
    cudaGetSymbolAddress((void**)&ao,   g_ao);
    cudaGetSymbolAddress((void**)&x2,   g_x2);
    cudaGetSymbolAddress((void**)&hbuf, g_h);

    const int MB = MROWS / BM;  // 3136

    // 1) LN1 + shift + window partition
    ln_kernel<true><<<MROWS / 8, 256>>>(x, n1g, n1b, xw);
    // 2) QKV GEMM (M,192)x(192,576) -> scatter q/k/v (q scaled)
    gemm_kernel<1><<<dim3(576 / BN, MB), 256>>>(xw, qkv_w, qkv_b, nullptr, CC, 3 * CC, nullptr);
    // 3) attention per (window, head)
    attn_kernel<<<NWIN * NHEADS, 128>>>(amask, rpb, ao);
    // 4) proj GEMM + window reverse + unshift + shortcut -> x2
    gemm_kernel<2><<<dim3(CC / BN, MB), 256>>>(ao, proj_w, proj_b, x2, CC, CC, x);
    // 5) LN2 (pixel order) -> xw (reused)
    ln_kernel<false><<<MROWS / 8, 256>>>(x2, n2g, n2b, xw);
    // 6) fc1 GEMM + exact GELU -> h
    gemm_kernel<3><<<dim3(HID / BN, MB), 256>>>(xw, fc1_w, fc1_b, hbuf, CC, HID, nullptr);
    // 7) fc2 GEMM + residual(x2) -> out
    gemm_kernel<4><<<dim3(CC / BN, MB), 256>>>(hbuf, fc2_w, fc2_b, out, HID, CC, x2);
}

// round 3
// speedup vs baseline: 6.2006x; 6.2006x over previous
#include <cuda_runtime.h>
#include <cuda_bf16.h>
#include <math.h>
#include <stdint.h>

// ---------------- problem constants ----------------
#define BATCH   16
#define IMG     112
#define CC      192
#define NHEADS  6
#define DHEAD   32
#define WSZ     7
#define NTOK    49
#define NWIN    4096
#define MROWS   200704
#define HID     768

// ---------------- device scratch ----------------
__device__ __nv_bfloat16 g_xs [(size_t)MROWS * 384];   // LN1/LN2 output split [hi(192)|lo(192)]
__device__ __nv_bfloat16 g_aos[(size_t)MROWS * 384];   // attention out split
__device__ __nv_bfloat16 g_hs [(size_t)MROWS * 1536];  // gelu(fc1) split [hi(768)|lo(768)]
__device__ float g_q[(size_t)NWIN * NHEADS * NTOK * DHEAD];
__device__ float g_k[(size_t)NWIN * NHEADS * NTOK * DHEAD];
__device__ float g_v[(size_t)NWIN * NHEADS * NTOK * DHEAD];
__device__ float g_x2[(size_t)MROWS * CC];
// transposed + split weights: [N, 2K] bf16
__device__ __nv_bfloat16 g_wqkv [(size_t)576 * 384];
__device__ __nv_bfloat16 g_wproj[(size_t)192 * 384];
__device__ __nv_bfloat16 g_wfc1 [(size_t)768 * 384];
__device__ __nv_bfloat16 g_wfc2 [(size_t)192 * 1536];

// ---------------- helpers ----------------
__device__ __forceinline__ uint32_t smem_to_u32(const void* p) {
    uint32_t a;
    asm("{ .reg .u64 t; cvta.to.shared.u64 t, %1; cvt.u32.u64 %0, t; }" : "=r"(a) : "l"(p));
    return a;
}
__device__ __forceinline__ void cp16(uint32_t sm, const void* gp) {
    asm volatile("cp.async.cg.shared.global [%0], [%1], 16;" :: "r"(sm), "l"(gp));
}
__device__ __forceinline__ void cp_commit() { asm volatile("cp.async.commit_group;"); }
__device__ __forceinline__ void cp_wait1()  { asm volatile("cp.async.wait_group 1;"); }
__device__ __forceinline__ void cp_wait0()  { asm volatile("cp.async.wait_group 0;"); }

__device__ __forceinline__ void ldm4(uint32_t& x0, uint32_t& x1, uint32_t& x2, uint32_t& x3, uint32_t addr) {
    asm volatile("ldmatrix.sync.aligned.m8n8.x4.shared.b16 {%0,%1,%2,%3}, [%4];"
                 : "=r"(x0), "=r"(x1), "=r"(x2), "=r"(x3) : "r"(addr));
}
__device__ __forceinline__ void mma16816(float& d0, float& d1, float& d2, float& d3,
                                         uint32_t a0, uint32_t a1, uint32_t a2, uint32_t a3,
                                         uint32_t b0, uint32_t b1) {
    asm volatile("mma.sync.aligned.m16n8k16.row.col.f32.bf16.bf16.f32 "
                 "{%0,%1,%2,%3},{%4,%5,%6,%7},{%8,%9},{%0,%1,%2,%3};"
                 : "+f"(d0), "+f"(d1), "+f"(d2), "+f"(d3)
                 : "r"(a0), "r"(a1), "r"(a2), "r"(a3), "r"(b0), "r"(b1));
}

// smem tile addressing: rows of 32 bf16 (64B = 4 x 16B chunks), XOR swizzle for
// conflict-free ldmatrix (8 rows of one piece hit 8 distinct 16B bank-phases)
__device__ __forceinline__ uint32_t tile_addr(uint32_t base, int row, int chunk) {
    return base + row * 64 + ((chunk ^ ((row >> 1) & 3)) << 4);
}

__device__ __forceinline__ float gelu_exact(float x) {
    return 0.5f * x * (1.f + erff(x * 0.70710678118654752f));
}
__device__ __forceinline__ void split_bf16(float v, __nv_bfloat16& hi, __nv_bfloat16& lo) {
    hi = __float2bfloat16(v);
    lo = __float2bfloat16(v - __bfloat162float(hi));
}

// ---------------- weight prep: W[K,N] f32 -> B2[N, 2K] bf16 ([Bh | Bl]) ----------------
__global__ void prep_w(const float* __restrict__ W, __nv_bfloat16* __restrict__ B2, int K, int N) {
    int i = blockIdx.x * 256 + threadIdx.x;
    if (i >= K * N) return;
    int k = i / N, n = i - k * N;
    float v = W[i];
    __nv_bfloat16 hi, lo;
    split_bf16(v, hi, lo);
    B2[(size_t)n * (2 * K) + k] = hi;
    B2[(size_t)n * (2 * K) + K + k] = lo;
}

// ---------------- LN (optionally fused shift + window partition), split bf16 out ----------------
template<bool WINDOWED>
__global__ __launch_bounds__(256) void ln_kernel(const float* __restrict__ src_full,
                                                 const float* __restrict__ gam,
                                                 const float* __restrict__ bet,
                                                 __nv_bfloat16* __restrict__ out) {
    int t = blockIdx.x * 8 + (threadIdx.x >> 5);
    int lane = threadIdx.x & 31;
    const float* src;
    if (WINDOWED) {
        int win = t / NTOK, n = t - win * NTOK;
        int b = win >> 8, wi = win & 255;
        int hh = (wi >> 4) * WSZ + n / WSZ;
        int ww = (wi & 15) * WSZ + n % WSZ;
        int sh = hh + 3; if (sh >= IMG) sh -= IMG;
        int sw = ww + 3; if (sw >= IMG) sw -= IMG;
        src = src_full + (size_t)((b * IMG + sh) * IMG + sw) * CC;
    } else {
        src = src_full + (size_t)t * CC;
    }
    float v[6]; float s = 0.f, s2 = 0.f;
    #pragma unroll
    for (int i = 0; i < 6; i++) { float a = src[lane * 6 + i]; v[i] = a; s += a; s2 += a * a; }
    #pragma unroll
    for (int o = 16; o; o >>= 1) {
        s  += __shfl_xor_sync(0xffffffffu, s,  o);
        s2 += __shfl_xor_sync(0xffffffffu, s2, o);
    }
    float mean = s * (1.f / 192.f);
    float var  = s2 * (1.f / 192.f) - mean * mean;
    float rstd = rsqrtf(var + 1e-5f);
    __nv_bfloat16* dst = out + (size_t)t * 384;
    #pragma unroll
    for (int i = 0; i < 6; i++) {
        int c = lane * 6 + i;
        float y = (v[i] - mean) * rstd * gam[c] + bet[c];
        __nv_bfloat16 hi, lo; split_bf16(y, hi, lo);
        dst[c] = hi; dst[c + 192] = lo;
    }
}

// ---------------- mma.sync GEMM: C[M,Nn] = A[M,K] W[K,Nn] via split-bf16 ----------------
// A2: [M, 2K] bf16 ([Ah|Al]); B2: [Nn, 2K] bf16 ([Bh|Bl]).
// 3 K-passes: Ah*Bh, Al*Bh, Ah*Bl accumulated in f32.
// BM=128, BN=192, BK=32; 256 threads = 8 warps (2x4), warp tile 64x48.
// EPI: 1=qkv scatter (q scaled), 2=proj+unshift+shortcut->x2, 3=gelu->split bf16, 4=+bias+x2->out
template<int EPI>
__global__ __launch_bounds__(256)
void gemm_mma(const __nv_bfloat16* __restrict__ A2, const __nv_bfloat16* __restrict__ B2,
              const float* __restrict__ bias, float* __restrict__ outF,
              const float* __restrict__ addsrc, __nv_bfloat16* __restrict__ outS,
              int K32, int Kp2, int Nn) {
    __shared__ __align__(16) __nv_bfloat16 As[2][128 * 32];
    __shared__ __align__(16) __nv_bfloat16 Bs[2][192 * 32];
    uint32_t a_base = smem_to_u32(&As[0][0]);
    uint32_t b_base = smem_to_u32(&Bs[0][0]);

    int tid = threadIdx.x, lane = tid & 31, wid = tid >> 5;
    int wm = wid >> 2, wn = wid & 3;
    int bm = blockIdx.y * 128, bn = blockIdx.x * 192;
    const int NC = 3 * K32;

    float acc[4][6][4] = {};

    auto issue = [&](int buf, int cc) {
        int cr = cc, p = 0;
        if (cr >= K32) { cr -= K32; p = 1; }
        if (cr >= K32) { cr -= K32; p = 2; }
        int cA = cr + (p == 1 ? K32 : 0);
        int cB = cr + (p == 2 ? K32 : 0);
        const __nv_bfloat16* Ag = A2 + (size_t)bm * Kp2 + cA * 32;
        const __nv_bfloat16* Bg = B2 + (size_t)bn * Kp2 + cB * 32;
        uint32_t ab = a_base + buf * 8192;
        uint32_t bb = b_base + buf * 12288;
        #pragma unroll
        for (int i = 0; i < 2; i++) {
            int t = tid + i * 256, row = t >> 2, c = t & 3;
            cp16(tile_addr(ab, row, c), Ag + (size_t)row * Kp2 + c * 8);
        }
        #pragma unroll
        for (int i = 0; i < 3; i++) {
            int t = tid + i * 256, row = t >> 2, c = t & 3;
            cp16(tile_addr(bb, row, c), Bg + (size_t)row * Kp2 + c * 8);
        }
    };

    issue(0, 0);
    cp_commit();

    int buf = 0;
    for (int cc = 0; cc < NC; cc++) {
        bool more = (cc + 1 < NC);
        if (more) issue(buf ^ 1, cc + 1);
        cp_commit();
        if (more) cp_wait1(); else cp_wait0();
        __syncthreads();

        uint32_t ab = a_base + buf * 8192;
        uint32_t bb = b_base + buf * 12288;
        int arow = wm * 64 + (lane & 15);
        int bnrow = wn * 48 + (lane & 7) + ((lane >> 4) << 3);
        int bk8 = (lane >> 3) & 1;
        #pragma unroll
        for (int ks = 0; ks < 2; ks++) {
            uint32_t af[4][4];
            #pragma unroll
            for (int mt = 0; mt < 4; mt++)
                ldm4(af[mt][0], af[mt][1], af[mt][2], af[mt][3],
                     tile_addr(ab, arow + mt * 16, ks * 2 + (lane >> 4)));
            uint32_t bf[6][2];
            #pragma unroll
            for (int pr = 0; pr < 3; pr++)
                ldm4(bf[2 * pr][0], bf[2 * pr][1], bf[2 * pr + 1][0], bf[2 * pr + 1][1],
                     tile_addr(bb, bnrow + pr * 16, ks * 2 + bk8));
            #pragma unroll
            for (int mt = 0; mt < 4; mt++)
                #pragma unroll
                for (int nt = 0; nt < 6; nt++)
                    mma16816(acc[mt][nt][0], acc[mt][nt][1], acc[mt][nt][2], acc[mt][nt][3],
                             af[mt][0], af[mt][1], af[mt][2], af[mt][3],
                             bf[nt][0], bf[nt][1]);
        }
        __syncthreads();
        buf ^= 1;
    }

    // ---- epilogue ----
    float2 bcol[6];
    #pragma unroll
    for (int nt = 0; nt < 6; nt++) {
        int col = bn + wn * 48 + nt * 8 + 2 * (lane & 3);
        bcol[nt] = *(const float2*)&bias[col];
    }

    #pragma unroll
    for (int mt = 0; mt < 4; mt++) {
        #pragma unroll
        for (int half = 0; half < 2; half++) {
            int row = bm + wm * 64 + mt * 16 + (lane >> 2) + half * 8;
            if constexpr (EPI == 1) {
                int t3 = bn / 192;
                float scale = (t3 == 0) ? 0.17677669529663687f : 1.f;
                float* dst = (t3 == 0) ? g_q : ((t3 == 1) ? g_k : g_v);
                int win = row / NTOK, n = row - win * NTOK;
                #pragma unroll
                for (int nt = 0; nt < 6; nt++) {
                    int col = wn * 48 + nt * 8 + 2 * (lane & 3);
                    int head = col >> 5, dd = col & 31;
                    float vx = (acc[mt][nt][half * 2] + bcol[nt].x) * scale;
                    float vy = (acc[mt][nt][half * 2 + 1] + bcol[nt].y) * scale;
                    *(float2*)&dst[(((size_t)win * NHEADS + head) * NTOK + n) * DHEAD + dd] = make_float2(vx, vy);
                }
            } else if constexpr (EPI == 2) {
                int win = row / NTOK, n = row - win * NTOK;
                int b = win >> 8, wi = win & 255;
                int hh = (wi >> 4) * WSZ + n / WSZ;
                int ww = (wi & 15) * WSZ + n % WSZ;
                int p = hh + 3; if (p >= IMG) p -= IMG;
                int q = ww + 3; if (q >= IMG) q -= IMG;
                size_t pixbase = (size_t)((b * IMG + p) * IMG + q) * CC;
                #pragma unroll
                for (int nt = 0; nt < 6; nt++) {
                    int col = bn + wn * 48 + nt * 8 + 2 * (lane & 3);
                    float2 s = *(const float2*)&addsrc[pixbase + col];
                    float vx = acc[mt][nt][half * 2] + bcol[nt].x + s.x;
                    float vy = acc[mt][nt][half * 2 + 1] + bcol[nt].y + s.y;
                    *(float2*)&outF[pixbase + col] = make_float2(vx, vy);
                }
            } else if constexpr (EPI == 3) {
                size_t rb = (size_t)row * 1536;
                #pragma unroll
                for (int nt = 0; nt < 6; nt++) {
                    int col = bn + wn * 48 + nt * 8 + 2 * (lane & 3);
                    float gx = gelu_exact(acc[mt][nt][half * 2] + bcol[nt].x);
                    float gy = gelu_exact(acc[mt][nt][half * 2 + 1] + bcol[nt].y);
                    __nv_bfloat16 hx, lx, hy, ly;
                    split_bf16(gx, hx, lx);
                    split_bf16(gy, hy, ly);
                    *(__nv_bfloat162*)&outS[rb + col] = __nv_bfloat162(hx, hy);
                    *(__nv_bfloat162*)&outS[rb + 768 + col] = __nv_bfloat162(lx, ly);
                }
            } else {
                size_t rb = (size_t)row * 192;
                #pragma unroll
                for (int nt = 0; nt < 6; nt++) {
                    int col = bn + wn * 48 + nt * 8 + 2 * (lane & 3);
                    float2 s = *(const float2*)&addsrc[rb + col];
                    float vx = acc[mt][nt][half * 2] + bcol[nt].x + s.x;
                    float vy = acc[mt][nt][half * 2 + 1] + bcol[nt].y + s.y;
                    *(float2*)&outF[rb + col] = make_float2(vx, vy);
                }
            }
        }
    }
}

// ---------------- windowed attention (output: split bf16) ----------------
__global__ __launch_bounds__(128) void attn_kernel(const float* __restrict__ mask,
                                                   const float* __restrict__ rpb,
                                                   __nv_bfloat16* __restrict__ outs) {
    int wh = blockIdx.x;
    int win = wh / NHEADS, head = wh - win * NHEADS;
    __shared__ float sq[NTOK * 36], sk[NTOK * 36], sv[NTOK * 36];
    __shared__ float sp[4][64];
    int tid = threadIdx.x;
    const float* qb = g_q + (size_t)wh * (NTOK * DHEAD);
    const float* kb = g_k + (size_t)wh * (NTOK * DHEAD);
    const float* vb = g_v + (size_t)wh * (NTOK * DHEAD);
    for (int i = tid; i < NTOK * DHEAD; i += 128) {
        int r = i >> 5, c = i & 31;
        sq[r * 36 + c] = qb[i];
        sk[r * 36 + c] = kb[i];
        sv[r * 36 + c] = vb[i];
    }
    __syncthreads();
    int warp = tid >> 5, lane = tid & 31;
    const float* mrow = mask + (size_t)(win & 255) * (NTOK * NTOK);
    int i2a = lane / WSZ, j2a = lane - i2a * WSZ;
    int m1 = lane + 32;
    int i2b = m1 / WSZ, j2b = m1 - i2b * WSZ;

    for (int r = warp; r < NTOK; r += 4) {
        float s0 = 0.f, s1 = 0.f;
        #pragma unroll
        for (int dd = 0; dd < DHEAD; dd += 4) {
            float4 q4 = *(const float4*)&sq[r * 36 + dd];
            float4 k4 = *(const float4*)&sk[lane * 36 + dd];
            s0 = fmaf(q4.x, k4.x, fmaf(q4.y, k4.y, fmaf(q4.z, k4.z, fmaf(q4.w, k4.w, s0))));
            if (lane < 17) {
                float4 k4b = *(const float4*)&sk[m1 * 36 + dd];
                s1 = fmaf(q4.x, k4b.x, fmaf(q4.y, k4b.y, fmaf(q4.z, k4b.z, fmaf(q4.w, k4b.w, s1))));
            }
        }
        int i1 = r / WSZ, j1 = r - i1 * WSZ;
        int rel0 = (i1 - i2a + 6) * 13 + (j1 - j2a + 6);
        s0 += rpb[rel0 * NHEADS + head] + mrow[r * NTOK + lane];
        if (lane < 17) {
            int rel1 = (i1 - i2b + 6) * 13 + (j1 - j2b + 6);
            s1 += rpb[rel1 * NHEADS + head] + mrow[r * NTOK + m1];
        } else {
            s1 = -1e30f;
        }
        float mx = fmaxf(s0, s1);
        #pragma unroll
        for (int o = 16; o; o >>= 1) mx = fmaxf(mx, __shfl_xor_sync(0xffffffffu, mx, o));
        float e0 = __expf(s0 - mx);
        float e1 = (lane < 17) ? __expf(s1 - mx) : 0.f;
        float sum = e0 + e1;
        #pragma unroll
        for (int o = 16; o; o >>= 1) sum += __shfl_xor_sync(0xffffffffu, sum, o);
        float inv = 1.f / sum;
        sp[warp][lane] = e0 * inv;
        if (lane < 17) sp[warp][lane + 32] = e1 * inv;
        __syncwarp();
        float acc = 0.f;
        #pragma unroll
        for (int m = 0; m < NTOK; m++)
            acc = fmaf(sp[warp][m], sv[m * 36 + lane], acc);
        size_t base = ((size_t)win * NTOK + r) * 384 + head * DHEAD + lane;
        __nv_bfloat16 hi, lo; split_bf16(acc, hi, lo);
        outs[base] = hi;
        outs[base + 192] = lo;
        __syncwarp();
    }
}

// ---------------- launch ----------------
extern "C" void kernel_launch(void* const* d_in, const int* in_sizes, int n_in,
                              void* d_out, int out_size) {
    const float* x      = (const float*)d_in[0];
    const float* amask  = (const float*)d_in[1];
    const float* n1g    = (const float*)d_in[2];
    const float* n1b    = (const float*)d_in[3];
    const float* qkv_w  = (const float*)d_in[4];
    const float* qkv_b  = (const float*)d_in[5];
    const float* rpb    = (const float*)d_in[6];
    const float* proj_w = (const float*)d_in[7];
    const float* proj_b = (const float*)d_in[8];
    const float* n2g    = (const float*)d_in[9];
    const float* n2b    = (const float*)d_in[10];
    const float* fc1_w  = (const float*)d_in[11];
    const float* fc1_b  = (const float*)d_in[12];
    const float* fc2_w  = (const float*)d_in[13];
    const float* fc2_b  = (const float*)d_in[14];
    float* out = (float*)d_out;

    __nv_bfloat16 *xs, *aos, *hs, *wqkv, *wproj, *wfc1, *wfc2;
    float *x2;
    cudaGetSymbolAddress((void**)&xs,    g_xs);
    cudaGetSymbolAddress((void**)&aos,   g_aos);
    cudaGetSymbolAddress((void**)&hs,    g_hs);
    cudaGetSymbolAddress((void**)&x2,    g_x2);
    cudaGetSymbolAddress((void**)&wqkv,  g_wqkv);
    cudaGetSymbolAddress((void**)&wproj, g_wproj);
    cudaGetSymbolAddress((void**)&wfc1,  g_wfc1);
    cudaGetSymbolAddress((void**)&wfc2,  g_wfc2);

    // weight prep (split + transpose)
    prep_w<<<(192 * 576 + 255) / 256, 256>>>(qkv_w,  wqkv,  192, 576);
    prep_w<<<(192 * 192 + 255) / 256, 256>>>(proj_w, wproj, 192, 192);
    prep_w<<<(192 * 768 + 255) / 256, 256>>>(fc1_w,  wfc1,  192, 768);
    prep_w<<<(768 * 192 + 255) / 256, 256>>>(fc2_w,  wfc2,  768, 192);

    const int MB = MROWS / 128;  // 1568

    // 1) LN1 + shift + window partition -> split bf16
    ln_kernel<true><<<MROWS / 8, 256>>>(x, n1g, n1b, xs);
    // 2) QKV GEMM -> q/k/v (f32)
    gemm_mma<1><<<dim3(3, MB), 256>>>(xs, wqkv, qkv_b, nullptr, nullptr, nullptr, 6, 384, 576);
    // 3) attention -> split bf16
    attn_kernel<<<NWIN * NHEADS, 128>>>(amask, rpb, aos);
    // 4) proj GEMM + unwindow/unshift + shortcut -> x2 (f32)
    gemm_mma<2><<<dim3(1, MB), 256>>>(aos, wproj, proj_b, x2, x, nullptr, 6, 384, 192);
    // 5) LN2 -> split bf16
    ln_kernel<false><<<MROWS / 8, 256>>>(x2, n2g, n2b, xs);
    // 6) fc1 GEMM + gelu -> split bf16
    gemm_mma<3><<<dim3(4, MB), 256>>>(xs, wfc1, fc1_b, nullptr, nullptr, hs, 6, 384, 768);
    // 7) fc2 GEMM + residual -> out (f32)
    gemm_mma<4><<<dim3(1, MB), 256>>>(hs, wfc2, fc2_b, out, x2, nullptr, 24, 1536, 192);
}

// round 4
// speedup vs baseline: 10.9957x; 1.7733x over previous
#include <cuda_runtime.h>
#include <cuda_fp16.h>
#include <math.h>
#include <stdint.h>

// ---------------- problem constants ----------------
#define BATCH   16
#define IMG     112
#define CC      192
#define NHEADS  6
#define DHEAD   32
#define WSZ     7
#define NTOK    49
#define NWIN    4096
#define MROWS   200704
#define HID     768

// ---------------- device scratch ----------------
__device__ __half g_xs [(size_t)MROWS * CC];     // LN1/LN2 output fp16
__device__ __half g_aos[(size_t)MROWS * CC];     // attention out fp16
__device__ __half g_hs [(size_t)MROWS * HID];    // gelu(fc1) fp16
__device__ __half g_q[(size_t)NWIN * NHEADS * NTOK * DHEAD];
__device__ __half g_k[(size_t)NWIN * NHEADS * NTOK * DHEAD];
__device__ __half g_v[(size_t)NWIN * NHEADS * NTOK * DHEAD];
__device__ float g_x2[(size_t)MROWS * CC];
// transposed weights: [N, K] fp16
__device__ __half g_wqkv [(size_t)576 * 192];
__device__ __half g_wproj[(size_t)192 * 192];
__device__ __half g_wfc1 [(size_t)768 * 192];
__device__ __half g_wfc2 [(size_t)192 * 768];

// ---------------- helpers ----------------
__device__ __forceinline__ uint32_t smem_to_u32(const void* p) {
    uint32_t a;
    asm("{ .reg .u64 t; cvta.to.shared.u64 t, %1; cvt.u32.u64 %0, t; }" : "=r"(a) : "l"(p));
    return a;
}
__device__ __forceinline__ void cp16(uint32_t sm, const void* gp) {
    asm volatile("cp.async.cg.shared.global [%0], [%1], 16;" :: "r"(sm), "l"(gp));
}
__device__ __forceinline__ void cp_commit() { asm volatile("cp.async.commit_group;"); }
__device__ __forceinline__ void cp_wait1()  { asm volatile("cp.async.wait_group 1;"); }
__device__ __forceinline__ void cp_wait0()  { asm volatile("cp.async.wait_group 0;"); }

__device__ __forceinline__ void ldm4(uint32_t& x0, uint32_t& x1, uint32_t& x2, uint32_t& x3, uint32_t addr) {
    asm volatile("ldmatrix.sync.aligned.m8n8.x4.shared.b16 {%0,%1,%2,%3}, [%4];"
                 : "=r"(x0), "=r"(x1), "=r"(x2), "=r"(x3) : "r"(addr));
}
__device__ __forceinline__ void mma16816(float& d0, float& d1, float& d2, float& d3,
                                         uint32_t a0, uint32_t a1, uint32_t a2, uint32_t a3,
                                         uint32_t b0, uint32_t b1) {
    asm volatile("mma.sync.aligned.m16n8k16.row.col.f32.f16.f16.f32 "
                 "{%0,%1,%2,%3},{%4,%5,%6,%7},{%8,%9},{%0,%1,%2,%3};"
                 : "+f"(d0), "+f"(d1), "+f"(d2), "+f"(d3)
                 : "r"(a0), "r"(a1), "r"(a2), "r"(a3), "r"(b0), "r"(b1));
}

// smem tile addressing: rows of 32 halves (64B = 4 x 16B chunks), XOR swizzle for
// conflict-free ldmatrix
__device__ __forceinline__ uint32_t tile_addr(uint32_t base, int row, int chunk) {
    return base + row * 64 + ((chunk ^ ((row >> 1) & 3)) << 4);
}

__device__ __forceinline__ float gelu_exact(float x) {
    return 0.5f * x * (1.f + erff(x * 0.70710678118654752f));
}

// ---------------- weight prep: W[K,N] f32 -> B[N, K] fp16 ----------------
__global__ void prep_w(const float* __restrict__ W, __half* __restrict__ B2, int K, int N) {
    int i = blockIdx.x * 256 + threadIdx.x;
    if (i >= K * N) return;
    int k = i / N, n = i - k * N;
    B2[(size_t)n * K + k] = __float2half(W[i]);
}

// ---------------- LN (optionally fused shift + window partition), fp16 out ----------------
template<bool WINDOWED>
__global__ __launch_bounds__(256) void ln_kernel(const float* __restrict__ src_full,
                                                 const float* __restrict__ gam,
                                                 const float* __restrict__ bet,
                                                 __half* __restrict__ out) {
    int t = blockIdx.x * 8 + (threadIdx.x >> 5);
    int lane = threadIdx.x & 31;
    const float* src;
    if (WINDOWED) {
        int win = t / NTOK, n = t - win * NTOK;
        int b = win >> 8, wi = win & 255;
        int hh = (wi >> 4) * WSZ + n / WSZ;
        int ww = (wi & 15) * WSZ + n % WSZ;
        int sh = hh + 3; if (sh >= IMG) sh -= IMG;
        int sw = ww + 3; if (sw >= IMG) sw -= IMG;
        src = src_full + (size_t)((b * IMG + sh) * IMG + sw) * CC;
    } else {
        src = src_full + (size_t)t * CC;
    }
    float v[6]; float s = 0.f, s2 = 0.f;
    #pragma unroll
    for (int i = 0; i < 6; i++) { float a = src[i * 32 + lane]; v[i] = a; s += a; s2 += a * a; }
    #pragma unroll
    for (int o = 16; o; o >>= 1) {
        s  += __shfl_xor_sync(0xffffffffu, s,  o);
        s2 += __shfl_xor_sync(0xffffffffu, s2, o);
    }
    float mean = s * (1.f / 192.f);
    float var  = s2 * (1.f / 192.f) - mean * mean;
    float rstd = rsqrtf(var + 1e-5f);
    __half* dst = out + (size_t)t * CC;
    #pragma unroll
    for (int i = 0; i < 6; i++) {
        int c = i * 32 + lane;
        dst[c] = __float2half((v[i] - mean) * rstd * gam[c] + bet[c]);
    }
}

// ---------------- mma.sync GEMM: C[M,Nn] = A[M,K] W[K,Nn], fp16 x fp16 -> f32 ----------------
// A2: [M, K] fp16; B2: [Nn, K] fp16.
// BM=128, BN=192, BK=32; 256 threads = 8 warps (2x4), warp tile 64x48.
// EPI: 1=qkv scatter (q scaled), 2=proj+unshift+shortcut->x2, 3=gelu->fp16, 4=+bias+x2->out
template<int EPI>
__global__ __launch_bounds__(256)
void gemm_mma(const __half* __restrict__ A2, const __half* __restrict__ B2,
              const float* __restrict__ bias, float* __restrict__ outF,
              const float* __restrict__ addsrc, __half* __restrict__ outS,
              int K, int Nn) {
    __shared__ __align__(16) __half As[2][128 * 32];
    __shared__ __align__(16) __half Bs[2][192 * 32];
    uint32_t a_base = smem_to_u32(&As[0][0]);
    uint32_t b_base = smem_to_u32(&Bs[0][0]);

    int tid = threadIdx.x, lane = tid & 31, wid = tid >> 5;
    int wm = wid >> 2, wn = wid & 3;
    int bm = blockIdx.y * 128, bn = blockIdx.x * 192;
    const int NC = K >> 5;

    float acc[4][6][4] = {};

    auto issue = [&](int buf, int cc) {
        const __half* Ag = A2 + (size_t)bm * K + cc * 32;
        const __half* Bg = B2 + (size_t)bn * K + cc * 32;
        uint32_t ab = a_base + buf * 8192;
        uint32_t bb = b_base + buf * 12288;
        #pragma unroll
        for (int i = 0; i < 2; i++) {
            int t = tid + i * 256, row = t >> 2, c = t & 3;
            cp16(tile_addr(ab, row, c), Ag + (size_t)row * K + c * 8);
        }
        #pragma unroll
        for (int i = 0; i < 3; i++) {
            int t = tid + i * 256, row = t >> 2, c = t & 3;
            cp16(tile_addr(bb, row, c), Bg + (size_t)row * K + c * 8);
        }
    };

    issue(0, 0);
    cp_commit();

    int buf = 0;
    for (int cc = 0; cc < NC; cc++) {
        bool more = (cc + 1 < NC);
        if (more) issue(buf ^ 1, cc + 1);
        cp_commit();
        if (more) cp_wait1(); else cp_wait0();
        __syncthreads();

        uint32_t ab = a_base + buf * 8192;
        uint32_t bb = b_base + buf * 12288;
        int arow = wm * 64 + (lane & 15);
        int bnrow = wn * 48 + (lane & 7) + ((lane >> 4) << 3);
        int bk8 = (lane >> 3) & 1;
        #pragma unroll
        for (int ks = 0; ks < 2; ks++) {
            uint32_t af[4][4];
            #pragma unroll
            for (int mt = 0; mt < 4; mt++)
                ldm4(af[mt][0], af[mt][1], af[mt][2], af[mt][3],
                     tile_addr(ab, arow + mt * 16, ks * 2 + (lane >> 4)));
            uint32_t bf[6][2];
            #pragma unroll
            for (int pr = 0; pr < 3; pr++)
                ldm4(bf[2 * pr][0], bf[2 * pr][1], bf[2 * pr + 1][0], bf[2 * pr + 1][1],
                     tile_addr(bb, bnrow + pr * 16, ks * 2 + bk8));
            #pragma unroll
            for (int mt = 0; mt < 4; mt++)
                #pragma unroll
                for (int nt = 0; nt < 6; nt++)
                    mma16816(acc[mt][nt][0], acc[mt][nt][1], acc[mt][nt][2], acc[mt][nt][3],
                             af[mt][0], af[mt][1], af[mt][2], af[mt][3],
                             bf[nt][0], bf[nt][1]);
        }
        __syncthreads();
        buf ^= 1;
    }

    // ---- epilogue ----
    float2 bcol[6];
    #pragma unroll
    for (int nt = 0; nt < 6; nt++) {
        int col = bn + wn * 48 + nt * 8 + 2 * (lane & 3);
        bcol[nt] = *(const float2*)&bias[col];
    }

    #pragma unroll
    for (int mt = 0; mt < 4; mt++) {
        #pragma unroll
        for (int half = 0; half < 2; half++) {
            int row = bm + wm * 64 + mt * 16 + (lane >> 2) + half * 8;
            if constexpr (EPI == 1) {
                int t3 = bn / 192;
                float scale = (t3 == 0) ? 0.17677669529663687f : 1.f;
                __half* dst = (t3 == 0) ? g_q : ((t3 == 1) ? g_k : g_v);
                int win = row / NTOK, n = row - win * NTOK;
                #pragma unroll
                for (int nt = 0; nt < 6; nt++) {
                    int col = wn * 48 + nt * 8 + 2 * (lane & 3);
                    int head = col >> 5, dd = col & 31;
                    float vx = (acc[mt][nt][half * 2] + bcol[nt].x) * scale;
                    float vy = (acc[mt][nt][half * 2 + 1] + bcol[nt].y) * scale;
                    *(__half2*)&dst[(((size_t)win * NHEADS + head) * NTOK + n) * DHEAD + dd] =
                        __floats2half2_rn(vx, vy);
                }
            } else if constexpr (EPI == 2) {
                int win = row / NTOK, n = row - win * NTOK;
                int b = win >> 8, wi = win & 255;
                int hh = (wi >> 4) * WSZ + n / WSZ;
                int ww = (wi & 15) * WSZ + n % WSZ;
                int p = hh + 3; if (p >= IMG) p -= IMG;
                int q = ww + 3; if (q >= IMG) q -= IMG;
                size_t pixbase = (size_t)((b * IMG + p) * IMG + q) * CC;
                #pragma unroll
                for (int nt = 0; nt < 6; nt++) {
                    int col = bn + wn * 48 + nt * 8 + 2 * (lane & 3);
                    float2 s = *(const float2*)&addsrc[pixbase + col];
                    float vx = acc[mt][nt][half * 2] + bcol[nt].x + s.x;
                    float vy = acc[mt][nt][half * 2 + 1] + bcol[nt].y + s.y;
                    *(float2*)&outF[pixbase + col] = make_float2(vx, vy);
                }
            } else if constexpr (EPI == 3) {
                size_t rb = (size_t)row * HID;
                #pragma unroll
                for (int nt = 0; nt < 6; nt++) {
                    int col = bn + wn * 48 + nt * 8 + 2 * (lane & 3);
                    float gx = gelu_exact(acc[mt][nt][half * 2] + bcol[nt].x);
                    float gy = gelu_exact(acc[mt][nt][half * 2 + 1] + bcol[nt].y);
                    *(__half2*)&outS[rb + col] = __floats2half2_rn(gx, gy);
                }
            } else {
                size_t rb = (size_t)row * 192;
                #pragma unroll
                for (int nt = 0; nt < 6; nt++) {
                    int col = bn + wn * 48 + nt * 8 + 2 * (lane & 3);
                    float2 s = *(const float2*)&addsrc[rb + col];
                    float vx = acc[mt][nt][half * 2] + bcol[nt].x + s.x;
                    float vy = acc[mt][nt][half * 2 + 1] + bcol[nt].y + s.y;
                    *(float2*)&outF[rb + col] = make_float2(vx, vy);
                }
            }
        }
    }
}

// ---------------- windowed attention (fp16 in, fp16 out, f32 math) ----------------
__global__ __launch_bounds__(128) void attn_kernel(const float* __restrict__ mask,
                                                   const float* __restrict__ rpb,
                                                   __half* __restrict__ outs) {
    int wh = blockIdx.x;
    int win = wh / NHEADS, head = wh - win * NHEADS;
    __shared__ float sq[NTOK * 36], sk[NTOK * 36], sv[NTOK * 36];
    __shared__ float sp[4][64];
    int tid = threadIdx.x;
    const __half2* qb = (const __half2*)(g_q + (size_t)wh * (NTOK * DHEAD));
    const __half2* kb = (const __half2*)(g_k + (size_t)wh * (NTOK * DHEAD));
    const __half2* vb = (const __half2*)(g_v + (size_t)wh * (NTOK * DHEAD));
    for (int i = tid; i < NTOK * 16; i += 128) {
        int r = i >> 4, c = (i & 15) << 1;
        float2 q2 = __half22float2(qb[i]);
        float2 k2 = __half22float2(kb[i]);
        float2 v2 = __half22float2(vb[i]);
        sq[r * 36 + c] = q2.x; sq[r * 36 + c + 1] = q2.y;
        sk[r * 36 + c] = k2.x; sk[r * 36 + c + 1] = k2.y;
        sv[r * 36 + c] = v2.x; sv[r * 36 + c + 1] = v2.y;
    }
    __syncthreads();
    int warp = tid >> 5, lane = tid & 31;
    const float* mrow = mask + (size_t)(win & 255) * (NTOK * NTOK);
    int i2a = lane / WSZ, j2a = lane - i2a * WSZ;
    int m1 = lane + 32;
    int i2b = m1 / WSZ, j2b = m1 - i2b * WSZ;

    for (int r = warp; r < NTOK; r += 4) {
        float s0 = 0.f, s1 = 0.f;
        #pragma unroll
        for (int dd = 0; dd < DHEAD; dd += 4) {
            float4 q4 = *(const float4*)&sq[r * 36 + dd];
            float4 k4 = *(const float4*)&sk[lane * 36 + dd];
            s0 = fmaf(q4.x, k4.x, fmaf(q4.y, k4.y, fmaf(q4.z, k4.z, fmaf(q4.w, k4.w, s0))));
            if (lane < 17) {
                float4 k4b = *(const float4*)&sk[m1 * 36 + dd];
                s1 = fmaf(q4.x, k4b.x, fmaf(q4.y, k4b.y, fmaf(q4.z, k4b.z, fmaf(q4.w, k4b.w, s1))));
            }
        }
        int i1 = r / WSZ, j1 = r - i1 * WSZ;
        int rel0 = (i1 - i2a + 6) * 13 + (j1 - j2a + 6);
        s0 += rpb[rel0 * NHEADS + head] + mrow[r * NTOK + lane];
        if (lane < 17) {
            int rel1 = (i1 - i2b + 6) * 13 + (j1 - j2b + 6);
            s1 += rpb[rel1 * NHEADS + head] + mrow[r * NTOK + m1];
        } else {
            s1 = -1e30f;
        }
        float mx = fmaxf(s0, s1);
        #pragma unroll
        for (int o = 16; o; o >>= 1) mx = fmaxf(mx, __shfl_xor_sync(0xffffffffu, mx, o));
        float e0 = __expf(s0 - mx);
        float e1 = (lane < 17) ? __expf(s1 - mx) : 0.f;
        float sum = e0 + e1;
        #pragma unroll
        for (int o = 16; o; o >>= 1) sum += __shfl_xor_sync(0xffffffffu, sum, o);
        float inv = 1.f / sum;
        sp[warp][lane] = e0 * inv;
        if (lane < 17) sp[warp][lane + 32] = e1 * inv;
        __syncwarp();
        float acc = 0.f;
        #pragma unroll
        for (int m = 0; m < NTOK; m++)
            acc = fmaf(sp[warp][m], sv[m * 36 + lane], acc);
        outs[((size_t)win * NTOK + r) * CC + head * DHEAD + lane] = __float2half(acc);
        __syncwarp();
    }
}

// ---------------- launch ----------------
extern "C" void kernel_launch(void* const* d_in, const int* in_sizes, int n_in,
                              void* d_out, int out_size) {
    const float* x      = (const float*)d_in[0];
    const float* amask  = (const float*)d_in[1];
    const float* n1g    = (const float*)d_in[2];
    const float* n1b    = (const float*)d_in[3];
    const float* qkv_w  = (const float*)d_in[4];
    const float* qkv_b  = (const float*)d_in[5];
    const float* rpb    = (const float*)d_in[6];
    const float* proj_w = (const float*)d_in[7];
    const float* proj_b = (const float*)d_in[8];
    const float* n2g    = (const float*)d_in[9];
    const float* n2b    = (const float*)d_in[10];
    const float* fc1_w  = (const float*)d_in[11];
    const float* fc1_b  = (const float*)d_in[12];
    const float* fc2_w  = (const float*)d_in[13];
    const float* fc2_b  = (const float*)d_in[14];
    float* out = (float*)d_out;

    __half *xs, *aos, *hs, *wqkv, *wproj, *wfc1, *wfc2;
    float *x2;
    cudaGetSymbolAddress((void**)&xs,    g_xs);
    cudaGetSymbolAddress((void**)&aos,   g_aos);
    cudaGetSymbolAddress((void**)&hs,    g_hs);
    cudaGetSymbolAddress((void**)&x2,    g_x2);
    cudaGetSymbolAddress((void**)&wqkv,  g_wqkv);
    cudaGetSymbolAddress((void**)&wproj, g_wproj);
    cudaGetSymbolAddress((void**)&wfc1,  g_wfc1);
    cudaGetSymbolAddress((void**)&wfc2,  g_wfc2);

    // weight prep (transpose + fp16)
    prep_w<<<(192 * 576 + 255) / 256, 256>>>(qkv_w,  wqkv,  192, 576);
    prep_w<<<(192 * 192 + 255) / 256, 256>>>(proj_w, wproj, 192, 192);
    prep_w<<<(192 * 768 + 255) / 256, 256>>>(fc1_w,  wfc1,  192, 768);
    prep_w<<<(768 * 192 + 255) / 256, 256>>>(fc2_w,  wfc2,  768, 192);

    const int MB = MROWS / 128;  // 1568

    // 1) LN1 + shift + window partition -> fp16
    ln_kernel<true><<<MROWS / 8, 256>>>(x, n1g, n1b, xs);
    // 2) QKV GEMM -> q/k/v (fp16)
    gemm_mma<1><<<dim3(3, MB), 256>>>(xs, wqkv, qkv_b, nullptr, nullptr, nullptr, 192, 576);
    // 3) attention -> fp16
    attn_kernel<<<NWIN * NHEADS, 128>>>(amask, rpb, aos);
    // 4) proj GEMM + unwindow/unshift + shortcut -> x2 (f32)
    gemm_mma<2><<<dim3(1, MB), 256>>>(aos, wproj, proj_b, x2, x, nullptr, 192, 192);
    // 5) LN2 -> fp16
    ln_kernel<false><<<MROWS / 8, 256>>>(x2, n2g, n2b, xs);
    // 6) fc1 GEMM + gelu -> fp16
    gemm_mma<3><<<dim3(4, MB), 256>>>(xs, wfc1, fc1_b, nullptr, nullptr, hs, 192, 768);
    // 7) fc2 GEMM + residual -> out (f32)
    gemm_mma<4><<<dim3(1, MB), 256>>>(hs, wfc2, fc2_b, out, x2, nullptr, 768, 192);
}

// round 5
// speedup vs baseline: 12.1169x; 1.1020x over previous
#include <cuda_runtime.h>
#include <cuda_fp16.h>
#include <math.h>
#include <stdint.h>

// ---------------- problem constants ----------------
#define BATCH   16
#define IMG     112
#define CC      192
#define NHEADS  6
#define DHEAD   32
#define WSZ     7
#define NTOK    49
#define NWIN    4096
#define MROWS   200704
#define HID     768

// ---------------- device scratch ----------------
__device__ __half g_xs [(size_t)MROWS * CC];     // LN1/LN2 output fp16
__device__ __half g_aos[(size_t)MROWS * CC];     // attention out fp16
__device__ __half g_hs [(size_t)MROWS * HID];    // gelu(fc1) fp16
__device__ __half g_q[(size_t)NWIN * NHEADS * NTOK * DHEAD];
__device__ __half g_k[(size_t)NWIN * NHEADS * NTOK * DHEAD];
__device__ __half g_v[(size_t)NWIN * NHEADS * NTOK * DHEAD];
__device__ float g_x2[(size_t)MROWS * CC];
// transposed weights: [N, K] fp16
__device__ __half g_wqkv [(size_t)576 * 192];
__device__ __half g_wproj[(size_t)192 * 192];
__device__ __half g_wfc1 [(size_t)768 * 192];
__device__ __half g_wfc2 [(size_t)192 * 768];

// ---------------- helpers ----------------
__device__ __forceinline__ uint32_t smem_to_u32(const void* p) {
    uint32_t a;
    asm("{ .reg .u64 t; cvta.to.shared.u64 t, %1; cvt.u32.u64 %0, t; }" : "=r"(a) : "l"(p));
    return a;
}
__device__ __forceinline__ void cp16(uint32_t sm, const void* gp) {
    asm volatile("cp.async.cg.shared.global [%0], [%1], 16;" :: "r"(sm), "l"(gp));
}
__device__ __forceinline__ void cp_commit() { asm volatile("cp.async.commit_group;"); }
__device__ __forceinline__ void cp_wait2()  { asm volatile("cp.async.wait_group 2;"); }

__device__ __forceinline__ void ldm4(uint32_t& x0, uint32_t& x1, uint32_t& x2, uint32_t& x3, uint32_t addr) {
    asm volatile("ldmatrix.sync.aligned.m8n8.x4.shared.b16 {%0,%1,%2,%3}, [%4];"
                 : "=r"(x0), "=r"(x1), "=r"(x2), "=r"(x3) : "r"(addr));
}
__device__ __forceinline__ void mma16816(float& d0, float& d1, float& d2, float& d3,
                                         uint32_t a0, uint32_t a1, uint32_t a2, uint32_t a3,
                                         uint32_t b0, uint32_t b1) {
    asm volatile("mma.sync.aligned.m16n8k16.row.col.f32.f16.f16.f32 "
                 "{%0,%1,%2,%3},{%4,%5,%6,%7},{%8,%9},{%0,%1,%2,%3};"
                 : "+f"(d0), "+f"(d1), "+f"(d2), "+f"(d3)
                 : "r"(a0), "r"(a1), "r"(a2), "r"(a3), "r"(b0), "r"(b1));
}

// smem tile addressing: rows of 32 halves (64B = 4 x 16B chunks), XOR swizzle
__device__ __forceinline__ uint32_t tile_addr(uint32_t base, int row, int chunk) {
    return base + row * 64 + ((chunk ^ ((row >> 1) & 3)) << 4);
}

__device__ __forceinline__ float gelu_exact(float x) {
    return 0.5f * x * (1.f + erff(x * 0.70710678118654752f));
}

// ---------------- merged weight prep: W[K,N] f32 -> [N,K] fp16 (4 weights in one) ----------------
__global__ void prep_all(const float* __restrict__ qkv_w, const float* __restrict__ proj_w,
                         const float* __restrict__ fc1_w, const float* __restrict__ fc2_w) {
    int i = blockIdx.x * 256 + threadIdx.x;
    const float* W; __half* D; int K, N, off;
    if (i < 110592)      { W = qkv_w;  D = g_wqkv;  K = 192; N = 576; off = i; }
    else if (i < 147456) { W = proj_w; D = g_wproj; K = 192; N = 192; off = i - 110592; }
    else if (i < 294912) { W = fc1_w;  D = g_wfc1;  K = 192; N = 768; off = i - 147456; }
    else if (i < 442368) { W = fc2_w;  D = g_wfc2;  K = 768; N = 192; off = i - 294912; }
    else return;
    int k = off / N, n = off - k * N;
    D[(size_t)n * K + k] = __float2half(W[off]);
}

// ---------------- LN1 (fused shift + window partition), fp16 out ----------------
__global__ __launch_bounds__(256) void ln1_kernel(const float* __restrict__ src_full,
                                                  const float* __restrict__ gam,
                                                  const float* __restrict__ bet,
                                                  __half* __restrict__ out) {
    int t = blockIdx.x * 8 + (threadIdx.x >> 5);
    int lane = threadIdx.x & 31;
    int win = t / NTOK, n = t - win * NTOK;
    int b = win >> 8, wi = win & 255;
    int hh = (wi >> 4) * WSZ + n / WSZ;
    int ww = (wi & 15) * WSZ + n % WSZ;
    int sh = hh + 3; if (sh >= IMG) sh -= IMG;
    int sw = ww + 3; if (sw >= IMG) sw -= IMG;
    const float* src = src_full + (size_t)((b * IMG + sh) * IMG + sw) * CC;

    float v[6]; float s = 0.f, s2 = 0.f;
    #pragma unroll
    for (int i = 0; i < 6; i++) { float a = src[i * 32 + lane]; v[i] = a; s += a; s2 += a * a; }
    #pragma unroll
    for (int o = 16; o; o >>= 1) {
        s  += __shfl_xor_sync(0xffffffffu, s,  o);
        s2 += __shfl_xor_sync(0xffffffffu, s2, o);
    }
    float mean = s * (1.f / 192.f);
    float var  = s2 * (1.f / 192.f) - mean * mean;
    float rstd = rsqrtf(var + 1e-5f);
    __half* dst = out + (size_t)t * CC;
    #pragma unroll
    for (int i = 0; i < 6; i++) {
        int c = i * 32 + lane;
        dst[c] = __float2half((v[i] - mean) * rstd * gam[c] + bet[c]);
    }
}

// ---------------- mma.sync GEMM, 3-stage cp.async pipeline ----------------
// A2: [M, K] fp16; B2: [Nn, K] fp16. BM=128, BN=192, BK=32; 8 warps, warp tile 64x48.
// EPI: 1=qkv scatter (q scaled), 2=proj+unshift+shortcut->x2 + FUSED LN2->xs fp16,
//      3=gelu->fp16, 4=+bias+x2->out
#define SMEM_DYN 61440   // 3*(128*32 + 192*32)*2 bytes
template<int EPI>
__global__ __launch_bounds__(256)
void gemm_mma(const __half* __restrict__ A2, const __half* __restrict__ B2,
              const float* __restrict__ bias, float* __restrict__ outF,
              const float* __restrict__ addsrc, __half* __restrict__ outS,
              int K, int Nn,
              const float* __restrict__ g2, const float* __restrict__ b2,
              __half* __restrict__ xsOut) {
    extern __shared__ __align__(16) char sm_dyn[];
    uint32_t a_base = smem_to_u32(sm_dyn);
    uint32_t b_base = a_base + 24576;   // 3 A-buffers of 8192B

    int tid = threadIdx.x, lane = tid & 31, wid = tid >> 5;
    int wm = wid >> 2, wn = wid & 3;
    int bm = blockIdx.y * 128, bn = blockIdx.x * 192;
    const int NC = K >> 5;

    float acc[4][6][4] = {};

    auto issue = [&](int buf, int cc) {
        const __half* Ag = A2 + (size_t)bm * K + cc * 32;
        const __half* Bg = B2 + (size_t)bn * K + cc * 32;
        uint32_t ab = a_base + buf * 8192;
        uint32_t bb = b_base + buf * 12288;
        #pragma unroll
        for (int i = 0; i < 2; i++) {
            int t = tid + i * 256, row = t >> 2, c = t & 3;
            cp16(tile_addr(ab, row, c), Ag + (size_t)row * K + c * 8);
        }
        #pragma unroll
        for (int i = 0; i < 3; i++) {
            int t = tid + i * 256, row = t >> 2, c = t & 3;
            cp16(tile_addr(bb, row, c), Bg + (size_t)row * K + c * 8);
        }
    };

    issue(0, 0); cp_commit();
    issue(1, 1); cp_commit();

    int buf = 0;
    for (int cc = 0; cc < NC; cc++) {
        if (cc + 2 < NC) issue((cc + 2) % 3, cc + 2);
        cp_commit();
        cp_wait2();
        __syncthreads();

        uint32_t ab = a_base + buf * 8192;
        uint32_t bb = b_base + buf * 12288;
        int arow = wm * 64 + (lane & 15);
        int bnrow = wn * 48 + (lane & 7) + ((lane >> 4) << 3);
        int bk8 = (lane >> 3) & 1;
        #pragma unroll
        for (int ks = 0; ks < 2; ks++) {
            uint32_t af[4][4];
            #pragma unroll
            for (int mt = 0; mt < 4; mt++)
                ldm4(af[mt][0], af[mt][1], af[mt][2], af[mt][3],
                     tile_addr(ab, arow + mt * 16, ks * 2 + (lane >> 4)));
            uint32_t bf[6][2];
            #pragma unroll
            for (int pr = 0; pr < 3; pr++)
                ldm4(bf[2 * pr][0], bf[2 * pr][1], bf[2 * pr + 1][0], bf[2 * pr + 1][1],
                     tile_addr(bb, bnrow + pr * 16, ks * 2 + bk8));
            #pragma unroll
            for (int mt = 0; mt < 4; mt++)
                #pragma unroll
                for (int nt = 0; nt < 6; nt++)
                    mma16816(acc[mt][nt][0], acc[mt][nt][1], acc[mt][nt][2], acc[mt][nt][3],
                             af[mt][0], af[mt][1], af[mt][2], af[mt][3],
                             bf[nt][0], bf[nt][1]);
        }
        __syncthreads();
        buf = (buf == 2) ? 0 : buf + 1;
    }

    // ---- epilogue ----
    float2 bcol[6];
    #pragma unroll
    for (int nt = 0; nt < 6; nt++) {
        int col = bn + wn * 48 + nt * 8 + 2 * (lane & 3);
        bcol[nt] = *(const float2*)&bias[col];
    }

    if constexpr (EPI == 2) {
        // proj + unshift/unwindow + shortcut -> x2, then fused LN2 -> xs (fp16)
        float* red  = (float*)sm_dyn;          // [128][17] row partial sums
        float* redq = red + 128 * 17;          // [128][17] row partial sumsq
        int slot = wn * 4 + (lane & 3);

        #pragma unroll
        for (int mt = 0; mt < 4; mt++) {
            #pragma unroll
            for (int half = 0; half < 2; half++) {
                int rl = wm * 64 + mt * 16 + (lane >> 2) + half * 8;
                int row = bm + rl;
                int win = row / NTOK, n = row - win * NTOK;
                int b = win >> 8, wi = win & 255;
                int hh = (wi >> 4) * WSZ + n / WSZ;
                int ww = (wi & 15) * WSZ + n % WSZ;
                int p = hh + 3; if (p >= IMG) p -= IMG;
                int q = ww + 3; if (q >= IMG) q -= IMG;
                size_t pixbase = (size_t)((b * IMG + p) * IMG + q) * CC;
                float s = 0.f, sq2 = 0.f;
                #pragma unroll
                for (int nt = 0; nt < 6; nt++) {
                    int col = wn * 48 + nt * 8 + 2 * (lane & 3);
                    float2 sc = *(const float2*)&addsrc[pixbase + col];
                    float vx = acc[mt][nt][half * 2] + bcol[nt].x + sc.x;
                    float vy = acc[mt][nt][half * 2 + 1] + bcol[nt].y + sc.y;
                    acc[mt][nt][half * 2] = vx;
                    acc[mt][nt][half * 2 + 1] = vy;
                    *(float2*)&outF[pixbase + col] = make_float2(vx, vy);
                    s += vx + vy;
                    sq2 += vx * vx + vy * vy;
                }
                red [rl * 17 + slot] = s;
                redq[rl * 17 + slot] = sq2;
            }
        }
        __syncthreads();
        if (tid < 128) {
            float s = 0.f, qq = 0.f;
            #pragma unroll
            for (int i = 0; i < 16; i++) { s += red[tid * 17 + i]; qq += redq[tid * 17 + i]; }
            float mean = s * (1.f / 192.f);
            float var = qq * (1.f / 192.f) - mean * mean;
            red [tid * 17 + 16] = mean;
            redq[tid * 17 + 16] = rsqrtf(var + 1e-5f);
        }
        __syncthreads();
        #pragma unroll
        for (int mt = 0; mt < 4; mt++) {
            #pragma unroll
            for (int half = 0; half < 2; half++) {
                int rl = wm * 64 + mt * 16 + (lane >> 2) + half * 8;
                int row = bm + rl;
                int win = row / NTOK, n = row - win * NTOK;
                int b = win >> 8, wi = win & 255;
                int hh = (wi >> 4) * WSZ + n / WSZ;
                int ww = (wi & 15) * WSZ + n % WSZ;
                int p = hh + 3; if (p >= IMG) p -= IMG;
                int q = ww + 3; if (q >= IMG) q -= IMG;
                size_t pixbase = (size_t)((b * IMG + p) * IMG + q) * CC;
                float mean = red [rl * 17 + 16];
                float rstd = redq[rl * 17 + 16];
                #pragma unroll
                for (int nt = 0; nt < 6; nt++) {
                    int col = wn * 48 + nt * 8 + 2 * (lane & 3);
                    float2 gv = *(const float2*)&g2[col];
                    float2 bv = *(const float2*)&b2[col];
                    float yx = (acc[mt][nt][half * 2] - mean) * rstd * gv.x + bv.x;
                    float yy = (acc[mt][nt][half * 2 + 1] - mean) * rstd * gv.y + bv.y;
                    *(__half2*)&xsOut[pixbase + col] = __floats2half2_rn(yx, yy);
                }
            }
        }
    } else {
        #pragma unroll
        for (int mt = 0; mt < 4; mt++) {
            #pragma unroll
            for (int half = 0; half < 2; half++) {
                int row = bm + wm * 64 + mt * 16 + (lane >> 2) + half * 8;
                if constexpr (EPI == 1) {
                    int t3 = bn / 192;
                    float scale = (t3 == 0) ? 0.17677669529663687f : 1.f;
                    __half* dst = (t3 == 0) ? g_q : ((t3 == 1) ? g_k : g_v);
                    int win = row / NTOK, n = row - win * NTOK;
                    #pragma unroll
                    for (int nt = 0; nt < 6; nt++) {
                        int col = wn * 48 + nt * 8 + 2 * (lane & 3);
                        int head = col >> 5, dd = col & 31;
                        float vx = (acc[mt][nt][half * 2] + bcol[nt].x) * scale;
                        float vy = (acc[mt][nt][half * 2 + 1] + bcol[nt].y) * scale;
                        *(__half2*)&dst[(((size_t)win * NHEADS + head) * NTOK + n) * DHEAD + dd] =
                            __floats2half2_rn(vx, vy);
                    }
                } else if constexpr (EPI == 3) {
                    size_t rb = (size_t)row * HID;
                    #pragma unroll
                    for (int nt = 0; nt < 6; nt++) {
                        int col = bn + wn * 48 + nt * 8 + 2 * (lane & 3);
                        float gx = gelu_exact(acc[mt][nt][half * 2] + bcol[nt].x);
                        float gy = gelu_exact(acc[mt][nt][half * 2 + 1] + bcol[nt].y);
                        *(__half2*)&outS[rb + col] = __floats2half2_rn(gx, gy);
                    }
                } else {
                    size_t rb = (size_t)row * 192;
                    #pragma unroll
                    for (int nt = 0; nt < 6; nt++) {
                        int col = bn + wn * 48 + nt * 8 + 2 * (lane & 3);
                        float2 s = *(const float2*)&addsrc[rb + col];
                        float vx = acc[mt][nt][half * 2] + bcol[nt].x + s.x;
                        float vy = acc[mt][nt][half * 2 + 1] + bcol[nt].y + s.y;
                        *(float2*)&outF[rb + col] = make_float2(vx, vy);
                    }
                }
            }
        }
    }
}

// ---------------- windowed attention (K rows hoisted to registers) ----------------
__global__ __launch_bounds__(128) void attn_kernel(const float* __restrict__ mask,
                                                   const float* __restrict__ rpb,
                                                   __half* __restrict__ outs) {
    int wh = blockIdx.x;
    int win = wh / NHEADS, head = wh - win * NHEADS;
    __shared__ float sq[NTOK * 36], sk[NTOK * 36], sv[NTOK * 36];
    __shared__ float sp[4][64];
    int tid = threadIdx.x;
    const __half2* qb = (const __half2*)(g_q + (size_t)wh * (NTOK * DHEAD));
    const __half2* kb = (const __half2*)(g_k + (size_t)wh * (NTOK * DHEAD));
    const __half2* vb = (const __half2*)(g_v + (size_t)wh * (NTOK * DHEAD));
    for (int i = tid; i < NTOK * 16; i += 128) {
        int r = i >> 4, c = (i & 15) << 1;
        float2 q2 = __half22float2(qb[i]);
        float2 k2 = __half22float2(kb[i]);
        float2 v2 = __half22float2(vb[i]);
        sq[r * 36 + c] = q2.x; sq[r * 36 + c + 1] = q2.y;
        sk[r * 36 + c] = k2.x; sk[r * 36 + c + 1] = k2.y;
        sv[r * 36 + c] = v2.x; sv[r * 36 + c + 1] = v2.y;
    }
    __syncthreads();
    int warp = tid >> 5, lane = tid & 31;
    const float* mrow = mask + (size_t)(win & 255) * (NTOK * NTOK);
    bool has2 = (lane < 17);
    int i2a = lane / WSZ, j2a = lane - i2a * WSZ;
    int m1 = lane + 32;
    int i2b = m1 / WSZ, j2b = m1 - i2b * WSZ;

    // hoist K rows (loop-invariant per lane) into registers
    float4 kr0[8], kr1[8];
    #pragma unroll
    for (int d8 = 0; d8 < 8; d8++) kr0[d8] = *(const float4*)&sk[lane * 36 + d8 * 4];
    if (has2) {
        #pragma unroll
        for (int d8 = 0; d8 < 8; d8++) kr1[d8] = *(const float4*)&sk[m1 * 36 + d8 * 4];
    }

    for (int r = warp; r < NTOK; r += 4) {
        float s0 = 0.f, s1 = 0.f;
        #pragma unroll
        for (int d8 = 0; d8 < 8; d8++) {
            float4 q4 = *(const float4*)&sq[r * 36 + d8 * 4];   // broadcast
            s0 = fmaf(q4.x, kr0[d8].x, fmaf(q4.y, kr0[d8].y,
                 fmaf(q4.z, kr0[d8].z, fmaf(q4.w, kr0[d8].w, s0))));
            if (has2)
                s1 = fmaf(q4.x, kr1[d8].x, fmaf(q4.y, kr1[d8].y,
                     fmaf(q4.z, kr1[d8].z, fmaf(q4.w, kr1[d8].w, s1))));
        }
        int i1 = r / WSZ, j1 = r - i1 * WSZ;
        int rel0 = (i1 - i2a + 6) * 13 + (j1 - j2a + 6);
        s0 += rpb[rel0 * NHEADS + head] + mrow[r * NTOK + lane];
        if (has2) {
            int rel1 = (i1 - i2b + 6) * 13 + (j1 - j2b + 6);
            s1 += rpb[rel1 * NHEADS + head] + mrow[r * NTOK + m1];
        } else {
            s1 = -1e30f;
        }
        float mx = fmaxf(s0, s1);
        #pragma unroll
        for (int o = 16; o; o >>= 1) mx = fmaxf(mx, __shfl_xor_sync(0xffffffffu, mx, o));
        float e0 = __expf(s0 - mx);
        float e1 = has2 ? __expf(s1 - mx) : 0.f;
        float sum = e0 + e1;
        #pragma unroll
        for (int o = 16; o; o >>= 1) sum += __shfl_xor_sync(0xffffffffu, sum, o);
        float inv = 1.f / sum;
        sp[warp][lane] = e0 * inv;
        if (has2) sp[warp][lane + 32] = e1 * inv;
        __syncwarp();
        float acc = 0.f;
        #pragma unroll
        for (int m = 0; m < NTOK; m++)
            acc = fmaf(sp[warp][m], sv[m * 36 + lane], acc);
        outs[((size_t)win * NTOK + r) * CC + head * DHEAD + lane] = __float2half(acc);
        __syncwarp();
    }
}

// ---------------- launch ----------------
extern "C" void kernel_launch(void* const* d_in, const int* in_sizes, int n_in,
                              void* d_out, int out_size) {
    const float* x      = (const float*)d_in[0];
    const float* amask  = (const float*)d_in[1];
    const float* n1g    = (const float*)d_in[2];
    const float* n1b    = (const float*)d_in[3];
    const float* qkv_w  = (const float*)d_in[4];
    const float* qkv_b  = (const float*)d_in[5];
    const float* rpb    = (const float*)d_in[6];
    const float* proj_w = (const float*)d_in[7];
    const float* proj_b = (const float*)d_in[8];
    const float* n2g    = (const float*)d_in[9];
    const float* n2b    = (const float*)d_in[10];
    const float* fc1_w  = (const float*)d_in[11];
    const float* fc1_b  = (const float*)d_in[12];
    const float* fc2_w  = (const float*)d_in[13];
    const float* fc2_b  = (const float*)d_in[14];
    float* out = (float*)d_out;

    __half *xs, *aos, *hs, *wqkv, *wproj, *wfc1, *wfc2;
    float *x2;
    cudaGetSymbolAddress((void**)&xs,    g_xs);
    cudaGetSymbolAddress((void**)&aos,   g_aos);
    cudaGetSymbolAddress((void**)&hs,    g_hs);
    cudaGetSymbolAddress((void**)&x2,    g_x2);
    cudaGetSymbolAddress((void**)&wqkv,  g_wqkv);
    cudaGetSymbolAddress((void**)&wproj, g_wproj);
    cudaGetSymbolAddress((void**)&wfc1,  g_wfc1);
    cudaGetSymbolAddress((void**)&wfc2,  g_wfc2);

    cudaFuncSetAttribute(gemm_mma<1>, cudaFuncAttributeMaxDynamicSharedMemorySize, SMEM_DYN);
    cudaFuncSetAttribute(gemm_mma<2>, cudaFuncAttributeMaxDynamicSharedMemorySize, SMEM_DYN);
    cudaFuncSetAttribute(gemm_mma<3>, cudaFuncAttributeMaxDynamicSharedMemorySize, SMEM_DYN);
    cudaFuncSetAttribute(gemm_mma<4>, cudaFuncAttributeMaxDynamicSharedMemorySize, SMEM_DYN);

    const int MB = MROWS / 128;  // 1568

    // 0) weight prep (single merged kernel)
    prep_all<<<1728, 256>>>(qkv_w, proj_w, fc1_w, fc2_w);
    // 1) LN1 + shift + window partition -> fp16
    ln1_kernel<<<MROWS / 8, 256>>>(x, n1g, n1b, xs);
    // 2) QKV GEMM -> q/k/v (fp16)
    gemm_mma<1><<<dim3(3, MB), 256, SMEM_DYN>>>(xs, wqkv, qkv_b, nullptr, nullptr, nullptr, 192, 576,
                                                nullptr, nullptr, nullptr);
    // 3) attention -> fp16
    attn_kernel<<<NWIN * NHEADS, 128>>>(amask, rpb, aos);
    // 4) proj GEMM + unwindow/unshift + shortcut -> x2, fused LN2 -> xs (fp16)
    gemm_mma<2><<<dim3(1, MB), 256, SMEM_DYN>>>(aos, wproj, proj_b, x2, x, nullptr, 192, 192,
                                                n2g, n2b, xs);
    // 5) fc1 GEMM + gelu -> fp16
    gemm_mma<3><<<dim3(4, MB), 256, SMEM_DYN>>>(xs, wfc1, fc1_b, nullptr, nullptr, hs, 192, 768,
                                                nullptr, nullptr, nullptr);
    // 6) fc2 GEMM + residual -> out (f32)
    gemm_mma<4><<<dim3(1, MB), 256, SMEM_DYN>>>(hs, wfc2, fc2_b, out, x2, nullptr, 768, 192,
                                                nullptr, nullptr, nullptr);
}

// round 6
// speedup vs baseline: 16.2694x; 1.3427x over previous
#include <cuda_runtime.h>
#include <cuda_fp16.h>
#include <math.h>
#include <stdint.h>

// ---------------- problem constants ----------------
#define BATCH   16
#define IMG     112
#define CC      192
#define NHEADS  6
#define DHEAD   32
#define WSZ     7
#define NTOK    49
#define NWIN    4096
#define MROWS   200704
#define HID     768

// ---------------- device scratch ----------------
__device__ __half g_xs [(size_t)MROWS * CC];
__device__ __half g_aos[(size_t)MROWS * CC];
__device__ __half g_hs [(size_t)MROWS * HID];
__device__ __half g_q[(size_t)NWIN * NHEADS * NTOK * DHEAD];
__device__ __half g_k[(size_t)NWIN * NHEADS * NTOK * DHEAD];
__device__ __half g_v[(size_t)NWIN * NHEADS * NTOK * DHEAD];
__device__ float g_x2[(size_t)MROWS * CC];
__device__ __half g_wqkv [(size_t)576 * 192];
__device__ __half g_wproj[(size_t)192 * 192];
__device__ __half g_wfc1 [(size_t)768 * 192];
__device__ __half g_wfc2 [(size_t)192 * 768];
// combined rpb+mask table: [4 classes][6 heads][64 rows][56 cols] fp16
__device__ __half g_cmb[(size_t)4 * NHEADS * 64 * 56];

// ---------------- helpers ----------------
__device__ __forceinline__ uint32_t smem_to_u32(const void* p) {
    uint32_t a;
    asm("{ .reg .u64 t; cvta.to.shared.u64 t, %1; cvt.u32.u64 %0, t; }" : "=r"(a) : "l"(p));
    return a;
}
__device__ __forceinline__ void cp16(uint32_t sm, const void* gp) {
    asm volatile("cp.async.cg.shared.global [%0], [%1], 16;" :: "r"(sm), "l"(gp));
}
__device__ __forceinline__ void cp_commit() { asm volatile("cp.async.commit_group;"); }
__device__ __forceinline__ void cp_wait2()  { asm volatile("cp.async.wait_group 2;"); }

__device__ __forceinline__ void ldm4(uint32_t& x0, uint32_t& x1, uint32_t& x2, uint32_t& x3, uint32_t addr) {
    asm volatile("ldmatrix.sync.aligned.m8n8.x4.shared.b16 {%0,%1,%2,%3}, [%4];"
                 : "=r"(x0), "=r"(x1), "=r"(x2), "=r"(x3) : "r"(addr));
}
__device__ __forceinline__ void ldm4t(uint32_t& x0, uint32_t& x1, uint32_t& x2, uint32_t& x3, uint32_t addr) {
    asm volatile("ldmatrix.sync.aligned.m8n8.x4.trans.shared.b16 {%0,%1,%2,%3}, [%4];"
                 : "=r"(x0), "=r"(x1), "=r"(x2), "=r"(x3) : "r"(addr));
}
__device__ __forceinline__ void mma16816(float& d0, float& d1, float& d2, float& d3,
                                         uint32_t a0, uint32_t a1, uint32_t a2, uint32_t a3,
                                         uint32_t b0, uint32_t b1) {
    asm volatile("mma.sync.aligned.m16n8k16.row.col.f32.f16.f16.f32 "
                 "{%0,%1,%2,%3},{%4,%5,%6,%7},{%8,%9},{%0,%1,%2,%3};"
                 : "+f"(d0), "+f"(d1), "+f"(d2), "+f"(d3)
                 : "r"(a0), "r"(a1), "r"(a2), "r"(a3), "r"(b0), "r"(b1));
}
__device__ __forceinline__ uint32_t f22u(float a, float b) {
    __half2 h = __floats2half2_rn(a, b);
    return *(uint32_t*)&h;
}

__device__ __forceinline__ uint32_t tile_addr(uint32_t base, int row, int chunk) {
    return base + row * 64 + ((chunk ^ ((row >> 1) & 3)) << 4);
}
__device__ __forceinline__ float gelu_exact(float x) {
    return 0.5f * x * (1.f + erff(x * 0.70710678118654752f));
}

// ---------------- merged weight prep ----------------
__global__ void prep_all(const float* __restrict__ qkv_w, const float* __restrict__ proj_w,
                         const float* __restrict__ fc1_w, const float* __restrict__ fc2_w) {
    int i = blockIdx.x * 256 + threadIdx.x;
    const float* W; __half* D; int K, N, off;
    if (i < 110592)      { W = qkv_w;  D = g_wqkv;  K = 192; N = 576; off = i; }
    else if (i < 147456) { W = proj_w; D = g_wproj; K = 192; N = 192; off = i - 110592; }
    else if (i < 294912) { W = fc1_w;  D = g_wfc1;  K = 192; N = 768; off = i - 147456; }
    else if (i < 442368) { W = fc2_w;  D = g_wfc2;  K = 768; N = 192; off = i - 294912; }
    else return;
    int k = off / N, n = off - k * N;
    D[(size_t)n * K + k] = __float2half(W[off]);
}

// ---------------- bias+mask table prep: 4 classes x 6 heads x 64 x 56 ----------------
__global__ void prep_cmb(const float* __restrict__ amask, const float* __restrict__ rpb) {
    int ch = blockIdx.x;                 // cls*6 + head
    int cls = ch / NHEADS, head = ch - cls * NHEADS;
    int wi_rep = (cls >> 1 ? 240 : 0) + ((cls & 1) ? 15 : 0);
    __half* dst = g_cmb + (size_t)ch * (64 * 56);
    for (int idx = threadIdx.x; idx < 64 * 56; idx += 256) {
        int r = idx / 56, c = idx - r * 56;
        float v;
        if (r < NTOK && c < NTOK) {
            int i1 = r / WSZ, j1 = r - i1 * WSZ;
            int i2 = c / WSZ, j2 = c - i2 * WSZ;
            int rel = (i1 - i2 + 6) * 13 + (j1 - j2 + 6);
            v = rpb[rel * NHEADS + head] + amask[((size_t)wi_rep * NTOK + r) * NTOK + c];
        } else {
            v = -100.f;
        }
        dst[idx] = __float2half(v);
    }
}

// ---------------- LN1 (fused shift + window partition), fp16 out ----------------
__global__ __launch_bounds__(256) void ln1_kernel(const float* __restrict__ src_full,
                                                  const float* __restrict__ gam,
                                                  const float* __restrict__ bet,
                                                  __half* __restrict__ out) {
    int t = blockIdx.x * 8 + (threadIdx.x >> 5);
    int lane = threadIdx.x & 31;
    int win = t / NTOK, n = t - win * NTOK;
    int b = win >> 8, wi = win & 255;
    int hh = (wi >> 4) * WSZ + n / WSZ;
    int ww = (wi & 15) * WSZ + n % WSZ;
    int sh = hh + 3; if (sh >= IMG) sh -= IMG;
    int sw = ww + 3; if (sw >= IMG) sw -= IMG;
    const float* src = src_full + (size_t)((b * IMG + sh) * IMG + sw) * CC;

    float v[6]; float s = 0.f, s2 = 0.f;
    #pragma unroll
    for (int i = 0; i < 6; i++) { float a = src[i * 32 + lane]; v[i] = a; s += a; s2 += a * a; }
    #pragma unroll
    for (int o = 16; o; o >>= 1) {
        s  += __shfl_xor_sync(0xffffffffu, s,  o);
        s2 += __shfl_xor_sync(0xffffffffu, s2, o);
    }
    float mean = s * (1.f / 192.f);
    float var  = s2 * (1.f / 192.f) - mean * mean;
    float rstd = rsqrtf(var + 1e-5f);
    __half* dst = out + (size_t)t * CC;
    #pragma unroll
    for (int i = 0; i < 6; i++) {
        int c = i * 32 + lane;
        dst[c] = __float2half((v[i] - mean) * rstd * gam[c] + bet[c]);
    }
}

// ---------------- mma.sync GEMM, 3-stage cp.async pipeline ----------------
#define SMEM_DYN 61440
template<int EPI>
__global__ __launch_bounds__(256)
void gemm_mma(const __half* __restrict__ A2, const __half* __restrict__ B2,
              const float* __restrict__ bias, float* __restrict__ outF,
              const float* __restrict__ addsrc, __half* __restrict__ outS,
              int K, int Nn,
              const float* __restrict__ g2, const float* __restrict__ b2,
              __half* __restrict__ xsOut) {
    extern __shared__ __align__(16) char sm_dyn[];
    uint32_t a_base = smem_to_u32(sm_dyn);
    uint32_t b_base = a_base + 24576;

    int tid = threadIdx.x, lane = tid & 31, wid = tid >> 5;
    int wm = wid >> 2, wn = wid & 3;
    int bm = blockIdx.y * 128, bn = blockIdx.x * 192;
    const int NC = K >> 5;

    float acc[4][6][4] = {};

    auto issue = [&](int buf, int cc) {
        const __half* Ag = A2 + (size_t)bm * K + cc * 32;
        const __half* Bg = B2 + (size_t)bn * K + cc * 32;
        uint32_t ab = a_base + buf * 8192;
        uint32_t bb = b_base + buf * 12288;
        #pragma unroll
        for (int i = 0; i < 2; i++) {
            int t = tid + i * 256, row = t >> 2, c = t & 3;
            cp16(tile_addr(ab, row, c), Ag + (size_t)row * K + c * 8);
        }
        #pragma unroll
        for (int i = 0; i < 3; i++) {
            int t = tid + i * 256, row = t >> 2, c = t & 3;
            cp16(tile_addr(bb, row, c), Bg + (size_t)row * K + c * 8);
        }
    };

    issue(0, 0); cp_commit();
    issue(1, 1); cp_commit();

    int buf = 0;
    for (int cc = 0; cc < NC; cc++) {
        if (cc + 2 < NC) issue((cc + 2) % 3, cc + 2);
        cp_commit();
        cp_wait2();
        __syncthreads();

        uint32_t ab = a_base + buf * 8192;
        uint32_t bb = b_base + buf * 12288;
        int arow = wm * 64 + (lane & 15);
        int bnrow = wn * 48 + (lane & 7) + ((lane >> 4) << 3);
        int bk8 = (lane >> 3) & 1;
        #pragma unroll
        for (int ks = 0; ks < 2; ks++) {
            uint32_t af[4][4];
            #pragma unroll
            for (int mt = 0; mt < 4; mt++)
                ldm4(af[mt][0], af[mt][1], af[mt][2], af[mt][3],
                     tile_addr(ab, arow + mt * 16, ks * 2 + (lane >> 4)));
            uint32_t bf[6][2];
            #pragma unroll
            for (int pr = 0; pr < 3; pr++)
                ldm4(bf[2 * pr][0], bf[2 * pr][1], bf[2 * pr + 1][0], bf[2 * pr + 1][1],
                     tile_addr(bb, bnrow + pr * 16, ks * 2 + bk8));
            #pragma unroll
            for (int mt = 0; mt < 4; mt++)
                #pragma unroll
                for (int nt = 0; nt < 6; nt++)
                    mma16816(acc[mt][nt][0], acc[mt][nt][1], acc[mt][nt][2], acc[mt][nt][3],
                             af[mt][0], af[mt][1], af[mt][2], af[mt][3],
                             bf[nt][0], bf[nt][1]);
        }
        __syncthreads();
        buf = (buf == 2) ? 0 : buf + 1;
    }

    float2 bcol[6];
    #pragma unroll
    for (int nt = 0; nt < 6; nt++) {
        int col = bn + wn * 48 + nt * 8 + 2 * (lane & 3);
        bcol[nt] = *(const float2*)&bias[col];
    }

    if constexpr (EPI == 2) {
        float* red  = (float*)sm_dyn;
        float* redq = red + 128 * 17;
        int slot = wn * 4 + (lane & 3);

        #pragma unroll
        for (int mt = 0; mt < 4; mt++) {
            #pragma unroll
            for (int half = 0; half < 2; half++) {
                int rl = wm * 64 + mt * 16 + (lane >> 2) + half * 8;
                int row = bm + rl;
                int win = row / NTOK, n = row - win * NTOK;
                int b = win >> 8, wi = win & 255;
                int hh = (wi >> 4) * WSZ + n / WSZ;
                int ww = (wi & 15) * WSZ + n % WSZ;
                int p = hh + 3; if (p >= IMG) p -= IMG;
                int q = ww + 3; if (q >= IMG) q -= IMG;
                size_t pixbase = (size_t)((b * IMG + p) * IMG + q) * CC;
                float s = 0.f, sq2 = 0.f;
                #pragma unroll
                for (int nt = 0; nt < 6; nt++) {
                    int col = wn * 48 + nt * 8 + 2 * (lane & 3);
                    float2 sc = *(const float2*)&addsrc[pixbase + col];
                    float vx = acc[mt][nt][half * 2] + bcol[nt].x + sc.x;
                    float vy = acc[mt][nt][half * 2 + 1] + bcol[nt].y + sc.y;
                    acc[mt][nt][half * 2] = vx;
                    acc[mt][nt][half * 2 + 1] = vy;
                    *(float2*)&outF[pixbase + col] = make_float2(vx, vy);
                    s += vx + vy;
                    sq2 += vx * vx + vy * vy;
                }
                red [rl * 17 + slot] = s;
                redq[rl * 17 + slot] = sq2;
            }
        }
        __syncthreads();
        if (tid < 128) {
            float s = 0.f, qq = 0.f;
            #pragma unroll
            for (int i = 0; i < 16; i++) { s += red[tid * 17 + i]; qq += redq[tid * 17 + i]; }
            float mean = s * (1.f / 192.f);
            float var = qq * (1.f / 192.f) - mean * mean;
            red [tid * 17 + 16] = mean;
            redq[tid * 17 + 16] = rsqrtf(var + 1e-5f);
        }
        __syncthreads();
        #pragma unroll
        for (int mt = 0; mt < 4; mt++) {
            #pragma unroll
            for (int half = 0; half < 2; half++) {
                int rl = wm * 64 + mt * 16 + (lane >> 2) + half * 8;
                int row = bm + rl;
                int win = row / NTOK, n = row - win * NTOK;
                int b = win >> 8, wi = win & 255;
                int hh = (wi >> 4) * WSZ + n / WSZ;
                int ww = (wi & 15) * WSZ + n % WSZ;
                int p = hh + 3; if (p >= IMG) p -= IMG;
                int q = ww + 3; if (q >= IMG) q -= IMG;
                size_t pixbase = (size_t)((b * IMG + p) * IMG + q) * CC;
                float mean = red [rl * 17 + 16];
                float rstd = redq[rl * 17 + 16];
                #pragma unroll
                for (int nt = 0; nt < 6; nt++) {
                    int col = wn * 48 + nt * 8 + 2 * (lane & 3);
                    float2 gv = *(const float2*)&g2[col];
                    float2 bv = *(const float2*)&b2[col];
                    float yx = (acc[mt][nt][half * 2] - mean) * rstd * gv.x + bv.x;
                    float yy = (acc[mt][nt][half * 2 + 1] - mean) * rstd * gv.y + bv.y;
                    *(__half2*)&xsOut[pixbase + col] = __floats2half2_rn(yx, yy);
                }
            }
        }
    } else {
        #pragma unroll
        for (int mt = 0; mt < 4; mt++) {
            #pragma unroll
            for (int half = 0; half < 2; half++) {
                int row = bm + wm * 64 + mt * 16 + (lane >> 2) + half * 8;
                if constexpr (EPI == 1) {
                    int t3 = bn / 192;
                    float scale = (t3 == 0) ? 0.17677669529663687f : 1.f;
                    __half* dst = (t3 == 0) ? g_q : ((t3 == 1) ? g_k : g_v);
                    int win = row / NTOK, n = row - win * NTOK;
                    #pragma unroll
                    for (int nt = 0; nt < 6; nt++) {
                        int col = wn * 48 + nt * 8 + 2 * (lane & 3);
                        int head = col >> 5, dd = col & 31;
                        float vx = (acc[mt][nt][half * 2] + bcol[nt].x) * scale;
                        float vy = (acc[mt][nt][half * 2 + 1] + bcol[nt].y) * scale;
                        *(__half2*)&dst[(((size_t)win * NHEADS + head) * NTOK + n) * DHEAD + dd] =
                            __floats2half2_rn(vx, vy);
                    }
                } else if constexpr (EPI == 3) {
                    size_t rb = (size_t)row * HID;
                    #pragma unroll
                    for (int nt = 0; nt < 6; nt++) {
                        int col = bn + wn * 48 + nt * 8 + 2 * (lane & 3);
                        float gx = gelu_exact(acc[mt][nt][half * 2] + bcol[nt].x);
                        float gy = gelu_exact(acc[mt][nt][half * 2 + 1] + bcol[nt].y);
                        *(__half2*)&outS[rb + col] = __floats2half2_rn(gx, gy);
                    }
                } else {
                    size_t rb = (size_t)row * 192;
                    #pragma unroll
                    for (int nt = 0; nt < 6; nt++) {
                        int col = bn + wn * 48 + nt * 8 + 2 * (lane & 3);
                        float2 s = *(const float2*)&addsrc[rb + col];
                        float vx = acc[mt][nt][half * 2] + bcol[nt].x + s.x;
                        float vy = acc[mt][nt][half * 2 + 1] + bcol[nt].y + s.y;
                        *(float2*)&outF[rb + col] = make_float2(vx, vy);
                    }
                }
            }
        }
    }
}

// ---------------- tensor-core windowed attention ----------------
// one block per window, 4 warps; warp handles 16-row m-tile; loops 6 heads.
// smem strides: Q/K/V 40 halves (80B), cmb 56 halves (112B) — ldmatrix conflict-free.
__global__ __launch_bounds__(128) void attn_mma(__half* __restrict__ outs) {
    int win = blockIdx.x;
    int wi = win & 255;
    int cls = (((wi >> 4) == 15) ? 2 : 0) + (((wi & 15) == 15) ? 1 : 0);
    __shared__ __align__(16) __half sQ[64 * 40], sK[64 * 40], sV[64 * 40];
    __shared__ __align__(16) __half sC[64 * 56];
    int tid = threadIdx.x, lane = tid & 31, wm = tid >> 5;
    int g = lane >> 3, r8 = lane & 7;
    int mr = wm * 16;
    uint32_t qbase = smem_to_u32(sQ), kbase = smem_to_u32(sK);
    uint32_t vbase = smem_to_u32(sV), cbase = smem_to_u32(sC);

    // zero-fill pads once (rows >= 49 stay zero across heads)
    uint4 z = make_uint4(0, 0, 0, 0);
    for (int i = tid; i < 320; i += 128) {
        ((uint4*)sQ)[i] = z; ((uint4*)sK)[i] = z; ((uint4*)sV)[i] = z;
    }
    __syncthreads();

    for (int h = 0; h < NHEADS; h++) {
        // ---- load Q/K/V (49x32 fp16 each) + cmb table ----
        {
            const uint4* qg = (const uint4*)(g_q + (size_t)(win * NHEADS + h) * (NTOK * DHEAD));
            const uint4* kg = (const uint4*)(g_k + (size_t)(win * NHEADS + h) * (NTOK * DHEAD));
            const uint4* vg = (const uint4*)(g_v + (size_t)(win * NHEADS + h) * (NTOK * DHEAD));
            for (int i = tid; i < 196; i += 128) {
                int r = i >> 2, c = i & 3;
                *(uint4*)(sQ + r * 40 + c * 8) = qg[i];
                *(uint4*)(sK + r * 40 + c * 8) = kg[i];
                *(uint4*)(sV + r * 40 + c * 8) = vg[i];
            }
            const uint4* cg = (const uint4*)(g_cmb + (size_t)(cls * NHEADS + h) * (64 * 56));
            for (int i = tid; i < 448; i += 128) ((uint4*)sC)[i] = cg[i];
        }
        __syncthreads();

        // ---- Q A-frags (2 k-steps) ----
        uint32_t qf[2][4];
        #pragma unroll
        for (int ks = 0; ks < 2; ks++) {
            int row = mr + (g & 1) * 8 + r8;
            int col = ks * 16 + (g >> 1) * 8;
            ldm4(qf[ks][0], qf[ks][1], qf[ks][2], qf[ks][3], qbase + row * 80 + col * 2);
        }

        // ---- S = Q K^T (7 n-tiles of 8 tokens) ----
        float sacc[7][4] = {};
        #pragma unroll
        for (int ks = 0; ks < 2; ks++) {
            #pragma unroll
            for (int np = 0; np < 4; np++) {
                int row = np * 16 + ((g >> 1) & 1) * 8 + r8;
                int col = ks * 16 + (g & 1) * 8;
                uint32_t b0, b1, b2, b3;
                ldm4(b0, b1, b2, b3, kbase + row * 80 + col * 2);
                mma16816(sacc[2 * np][0], sacc[2 * np][1], sacc[2 * np][2], sacc[2 * np][3],
                         qf[ks][0], qf[ks][1], qf[ks][2], qf[ks][3], b0, b1);
                if (np < 3)
                    mma16816(sacc[2 * np + 1][0], sacc[2 * np + 1][1], sacc[2 * np + 1][2], sacc[2 * np + 1][3],
                             qf[ks][0], qf[ks][1], qf[ks][2], qf[ks][3], b2, b3);
            }
        }

        // ---- add bias+mask (C-fragment layout via ldmatrix) ----
        #pragma unroll
        for (int np = 0; np < 4; np++) {
            int row = mr + (g & 1) * 8 + r8;
            int colc = 2 * np + ((g >> 1) & 1); if (colc > 6) colc = 6;
            uint32_t c0, c1, c2, c3;
            ldm4(c0, c1, c2, c3, cbase + row * 112 + colc * 8 * 2);
            float2 f;
            f = __half22float2(*(__half2*)&c0); sacc[2 * np][0] += f.x; sacc[2 * np][1] += f.y;
            f = __half22float2(*(__half2*)&c1); sacc[2 * np][2] += f.x; sacc[2 * np][3] += f.y;
            if (np < 3) {
                f = __half22float2(*(__half2*)&c2); sacc[2 * np + 1][0] += f.x; sacc[2 * np + 1][1] += f.y;
                f = __half22float2(*(__half2*)&c3); sacc[2 * np + 1][2] += f.x; sacc[2 * np + 1][3] += f.y;
            }
        }

        // ---- softmax over 2 rows (r0, r0+8), cols spread over quad ----
        float mx0 = -1e30f, mx8 = -1e30f;
        #pragma unroll
        for (int nt = 0; nt < 7; nt++) {
            mx0 = fmaxf(mx0, fmaxf(sacc[nt][0], sacc[nt][1]));
            mx8 = fmaxf(mx8, fmaxf(sacc[nt][2], sacc[nt][3]));
        }
        #pragma unroll
        for (int o = 1; o <= 2; o <<= 1) {
            mx0 = fmaxf(mx0, __shfl_xor_sync(0xffffffffu, mx0, o));
            mx8 = fmaxf(mx8, __shfl_xor_sync(0xffffffffu, mx8, o));
        }
        float s0 = 0.f, s8 = 0.f;
        #pragma unroll
        for (int nt = 0; nt < 7; nt++) {
            sacc[nt][0] = __expf(sacc[nt][0] - mx0); s0 += sacc[nt][0];
            sacc[nt][1] = __expf(sacc[nt][1] - mx0); s0 += sacc[nt][1];
            sacc[nt][2] = __expf(sacc[nt][2] - mx8); s8 += sacc[nt][2];
            sacc[nt][3] = __expf(sacc[nt][3] - mx8); s8 += sacc[nt][3];
        }
        #pragma unroll
        for (int o = 1; o <= 2; o <<= 1) {
            s0 += __shfl_xor_sync(0xffffffffu, s0, o);
            s8 += __shfl_xor_sync(0xffffffffu, s8, o);
        }
        float inv0 = 1.f / s0, inv8 = 1.f / s8;
        #pragma unroll
        for (int nt = 0; nt < 7; nt++) {
            sacc[nt][0] *= inv0; sacc[nt][1] *= inv0;
            sacc[nt][2] *= inv8; sacc[nt][3] *= inv8;
        }

        // ---- O = P V (P in registers as A-frags; V via ldmatrix.trans) ----
        float oacc[4][4] = {};
        #pragma unroll
        for (int kt = 0; kt < 4; kt++) {
            uint32_t a0 = f22u(sacc[2 * kt][0], sacc[2 * kt][1]);
            uint32_t a1 = f22u(sacc[2 * kt][2], sacc[2 * kt][3]);
            uint32_t a2 = 0, a3 = 0;
            if (kt < 3) {
                a2 = f22u(sacc[2 * kt + 1][0], sacc[2 * kt + 1][1]);
                a3 = f22u(sacc[2 * kt + 1][2], sacc[2 * kt + 1][3]);
            }
            #pragma unroll
            for (int dp = 0; dp < 2; dp++) {
                int row = kt * 16 + (g & 1) * 8 + r8;
                int col = dp * 16 + ((g >> 1) & 1) * 8;
                uint32_t b0, b1, b2, b3;
                ldm4t(b0, b1, b2, b3, vbase + row * 80 + col * 2);
                mma16816(oacc[2 * dp][0], oacc[2 * dp][1], oacc[2 * dp][2], oacc[2 * dp][3],
                         a0, a1, a2, a3, b0, b1);
                mma16816(oacc[2 * dp + 1][0], oacc[2 * dp + 1][1], oacc[2 * dp + 1][2], oacc[2 * dp + 1][3],
                         a0, a1, a2, a3, b2, b3);
            }
        }

        // ---- store (rows < 49 only) ----
        int r0 = mr + (lane >> 2);
        int cbase2 = h * DHEAD + 2 * (lane & 3);
        if (r0 < NTOK) {
            size_t ob = ((size_t)win * NTOK + r0) * CC + cbase2;
            #pragma unroll
            for (int dn = 0; dn < 4; dn++)
                *(__half2*)&outs[ob + dn * 8] = __floats2half2_rn(oacc[dn][0], oacc[dn][1]);
        }
        int r1 = r0 + 8;
        if (r1 < NTOK) {
            size_t ob = ((size_t)win * NTOK + r1) * CC + cbase2;
            #pragma unroll
            for (int dn = 0; dn < 4; dn++)
                *(__half2*)&outs[ob + dn * 8] = __floats2half2_rn(oacc[dn][2], oacc[dn][3]);
        }
        __syncthreads();
    }
}

// ---------------- launch ----------------
extern "C" void kernel_launch(void* const* d_in, const int* in_sizes, int n_in,
                              void* d_out, int out_size) {
    const float* x      = (const float*)d_in[0];
    const float* amask  = (const float*)d_in[1];
    const float* n1g    = (const float*)d_in[2];
    const float* n1b    = (const float*)d_in[3];
    const float* qkv_w  = (const float*)d_in[4];
    const float* qkv_b  = (const float*)d_in[5];
    const float* rpb    = (const float*)d_in[6];
    const float* proj_w = (const float*)d_in[7];
    const float* proj_b = (const float*)d_in[8];
    const float* n2g    = (const float*)d_in[9];
    const float* n2b    = (const float*)d_in[10];
    const float* fc1_w  = (const float*)d_in[11];
    const float* fc1_b  = (const float*)d_in[12];
    const float* fc2_w  = (const float*)d_in[13];
    const float* fc2_b  = (const float*)d_in[14];
    float* out = (float*)d_out;

    __half *xs, *aos, *hs, *wqkv, *wproj, *wfc1, *wfc2;
    float *x2;
    cudaGetSymbolAddress((void**)&xs,    g_xs);
    cudaGetSymbolAddress((void**)&aos,   g_aos);
    cudaGetSymbolAddress((void**)&hs,    g_hs);
    cudaGetSymbolAddress((void**)&x2,    g_x2);
    cudaGetSymbolAddress((void**)&wqkv,  g_wqkv);
    cudaGetSymbolAddress((void**)&wproj, g_wproj);
    cudaGetSymbolAddress((void**)&wfc1,  g_wfc1);
    cudaGetSymbolAddress((void**)&wfc2,  g_wfc2);

    cudaFuncSetAttribute(gemm_mma<1>, cudaFuncAttributeMaxDynamicSharedMemorySize, SMEM_DYN);
    cudaFuncSetAttribute(gemm_mma<2>, cudaFuncAttributeMaxDynamicSharedMemorySize, SMEM_DYN);
    cudaFuncSetAttribute(gemm_mma<3>, cudaFuncAttributeMaxDynamicSharedMemorySize, SMEM_DYN);
    cudaFuncSetAttribute(gemm_mma<4>, cudaFuncAttributeMaxDynamicSharedMemorySize, SMEM_DYN);

    const int MB = MROWS / 128;  // 1568

    prep_all<<<1728, 256>>>(qkv_w, proj_w, fc1_w, fc2_w);
    prep_cmb<<<24, 256>>>(amask, rpb);
    ln1_kernel<<<MROWS / 8, 256>>>(x, n1g, n1b, xs);
    gemm_mma<1><<<dim3(3, MB), 256, SMEM_DYN>>>(xs, wqkv, qkv_b, nullptr, nullptr, nullptr, 192, 576,
                                                nullptr, nullptr, nullptr);
    attn_mma<<<NWIN, 128>>>(aos);
    gemm_mma<2><<<dim3(1, MB), 256, SMEM_DYN>>>(aos, wproj, proj_b, x2, x, nullptr, 192, 192,
                                                n2g, n2b, xs);
    gemm_mma<3><<<dim3(4, MB), 256, SMEM_DYN>>>(xs, wfc1, fc1_b, nullptr, nullptr, hs, 192, 768,
                                                nullptr, nullptr, nullptr);
    gemm_mma<4><<<dim3(1, MB), 256, SMEM_DYN>>>(hs, wfc2, fc2_b, out, x2, nullptr, 768, 192,
                                                nullptr, nullptr, nullptr);
}

// round 7
// speedup vs baseline: 16.4636x; 1.0119x over previous
#include <cuda_runtime.h>
#include <cuda_fp16.h>
#include <math.h>
#include <stdint.h>

// ---------------- problem constants ----------------
#define BATCH   16
#define IMG     112
#define CC      192
#define NHEADS  6
#define DHEAD   32
#define WSZ     7
#define NTOK    49
#define NWIN    4096
#define MROWS   200704
#define HID     768

// ---------------- device scratch ----------------
__device__ __half g_xs [(size_t)MROWS * CC];
__device__ __half g_aos[(size_t)MROWS * CC];
__device__ __half g_hs [(size_t)MROWS * HID];
__device__ __half g_q[(size_t)NWIN * NHEADS * NTOK * DHEAD];
__device__ __half g_k[(size_t)NWIN * NHEADS * NTOK * DHEAD];
__device__ __half g_v[(size_t)NWIN * NHEADS * NTOK * DHEAD];
__device__ float g_x2[(size_t)MROWS * CC];
__device__ __half g_wqkv [(size_t)576 * 192];
__device__ __half g_wproj[(size_t)192 * 192];
__device__ __half g_wfc1 [(size_t)768 * 192];
__device__ __half g_wfc2 [(size_t)192 * 768];
__device__ __half g_cmb[(size_t)4 * NHEADS * 64 * 56];

// ---------------- helpers ----------------
__device__ __forceinline__ uint32_t smem_to_u32(const void* p) {
    uint32_t a;
    asm("{ .reg .u64 t; cvta.to.shared.u64 t, %1; cvt.u32.u64 %0, t; }" : "=r"(a) : "l"(p));
    return a;
}
__device__ __forceinline__ void cp16(uint32_t sm, const void* gp) {
    asm volatile("cp.async.cg.shared.global [%0], [%1], 16;" :: "r"(sm), "l"(gp));
}
__device__ __forceinline__ void cp_commit() { asm volatile("cp.async.commit_group;"); }
__device__ __forceinline__ void cp_wait2()  { asm volatile("cp.async.wait_group 2;"); }

__device__ __forceinline__ void ldm4(uint32_t& x0, uint32_t& x1, uint32_t& x2, uint32_t& x3, uint32_t addr) {
    asm volatile("ldmatrix.sync.aligned.m8n8.x4.shared.b16 {%0,%1,%2,%3}, [%4];"
                 : "=r"(x0), "=r"(x1), "=r"(x2), "=r"(x3) : "r"(addr));
}
__device__ __forceinline__ void ldm4t(uint32_t& x0, uint32_t& x1, uint32_t& x2, uint32_t& x3, uint32_t addr) {
    asm volatile("ldmatrix.sync.aligned.m8n8.x4.trans.shared.b16 {%0,%1,%2,%3}, [%4];"
                 : "=r"(x0), "=r"(x1), "=r"(x2), "=r"(x3) : "r"(addr));
}
__device__ __forceinline__ void mma16816(float& d0, float& d1, float& d2, float& d3,
                                         uint32_t a0, uint32_t a1, uint32_t a2, uint32_t a3,
                                         uint32_t b0, uint32_t b1) {
    asm volatile("mma.sync.aligned.m16n8k16.row.col.f32.f16.f16.f32 "
                 "{%0,%1,%2,%3},{%4,%5,%6,%7},{%8,%9},{%0,%1,%2,%3};"
                 : "+f"(d0), "+f"(d1), "+f"(d2), "+f"(d3)
                 : "r"(a0), "r"(a1), "r"(a2), "r"(a3), "r"(b0), "r"(b1));
}
__device__ __forceinline__ uint32_t f22u(float a, float b) {
    __half2 h = __floats2half2_rn(a, b);
    return *(uint32_t*)&h;
}
__device__ __forceinline__ uint32_t tile_addr(uint32_t base, int row, int chunk) {
    return base + row * 64 + ((chunk ^ ((row >> 1) & 3)) << 4);
}
__device__ __forceinline__ float gelu_exact(float x) {
    return 0.5f * x * (1.f + erff(x * 0.70710678118654752f));
}

// ---------------- merged weight prep ----------------
__global__ void prep_all(const float* __restrict__ qkv_w, const float* __restrict__ proj_w,
                         const float* __restrict__ fc1_w, const float* __restrict__ fc2_w) {
    int i = blockIdx.x * 256 + threadIdx.x;
    const float* W; __half* D; int K, N, off;
    if (i < 110592)      { W = qkv_w;  D = g_wqkv;  K = 192; N = 576; off = i; }
    else if (i < 147456) { W = proj_w; D = g_wproj; K = 192; N = 192; off = i - 110592; }
    else if (i < 294912) { W = fc1_w;  D = g_wfc1;  K = 192; N = 768; off = i - 147456; }
    else if (i < 442368) { W = fc2_w;  D = g_wfc2;  K = 768; N = 192; off = i - 294912; }
    else return;
    int k = off / N, n = off - k * N;
    D[(size_t)n * K + k] = __float2half(W[off]);
}

// ---------------- bias+mask table prep ----------------
__global__ void prep_cmb(const float* __restrict__ amask, const float* __restrict__ rpb) {
    int ch = blockIdx.x;
    int cls = ch / NHEADS, head = ch - cls * NHEADS;
    int wi_rep = (cls >> 1 ? 240 : 0) + ((cls & 1) ? 15 : 0);
    __half* dst = g_cmb + (size_t)ch * (64 * 56);
    for (int idx = threadIdx.x; idx < 64 * 56; idx += 256) {
        int r = idx / 56, c = idx - r * 56;
        float v;
        if (r < NTOK && c < NTOK) {
            int i1 = r / WSZ, j1 = r - i1 * WSZ;
            int i2 = c / WSZ, j2 = c - i2 * WSZ;
            int rel = (i1 - i2 + 6) * 13 + (j1 - j2 + 6);
            v = rpb[rel * NHEADS + head] + amask[((size_t)wi_rep * NTOK + r) * NTOK + c];
        } else {
            v = -100.f;
        }
        dst[idx] = __float2half(v);
    }
}

// ---------------- LN1 (fused shift + window partition) ----------------
__global__ __launch_bounds__(256) void ln1_kernel(const float* __restrict__ src_full,
                                                  const float* __restrict__ gam,
                                                  const float* __restrict__ bet,
                                                  __half* __restrict__ out) {
    int t = blockIdx.x * 8 + (threadIdx.x >> 5);
    int lane = threadIdx.x & 31;
    int win = t / NTOK, n = t - win * NTOK;
    int b = win >> 8, wi = win & 255;
    int hh = (wi >> 4) * WSZ + n / WSZ;
    int ww = (wi & 15) * WSZ + n % WSZ;
    int sh = hh + 3; if (sh >= IMG) sh -= IMG;
    int sw = ww + 3; if (sw >= IMG) sw -= IMG;
    const float* src = src_full + (size_t)((b * IMG + sh) * IMG + sw) * CC;

    float v[6]; float s = 0.f, s2 = 0.f;
    #pragma unroll
    for (int i = 0; i < 6; i++) { float a = src[i * 32 + lane]; v[i] = a; s += a; s2 += a * a; }
    #pragma unroll
    for (int o = 16; o; o >>= 1) {
        s  += __shfl_xor_sync(0xffffffffu, s,  o);
        s2 += __shfl_xor_sync(0xffffffffu, s2, o);
    }
    float mean = s * (1.f / 192.f);
    float var  = s2 * (1.f / 192.f) - mean * mean;
    float rstd = rsqrtf(var + 1e-5f);
    __half* dst = out + (size_t)t * CC;
    #pragma unroll
    for (int i = 0; i < 6; i++) {
        int c = i * 32 + lane;
        dst[c] = __float2half((v[i] - mean) * rstd * gam[c] + bet[c]);
    }
}

// ---------------- mma.sync GEMM, 512 threads (16 warps 4x4), 3-stage pipeline ----------------
// BM=128, BN=192, BK=32; warp tile 32x48.
#define SMEM_DYN 61440
template<int EPI>
__global__ __launch_bounds__(512)
void gemm_mma(const __half* __restrict__ A2, const __half* __restrict__ B2,
              const float* __restrict__ bias, float* __restrict__ outF,
              const float* __restrict__ addsrc, __half* __restrict__ outS,
              int K, int Nn,
              const float* __restrict__ g2, const float* __restrict__ b2,
              __half* __restrict__ xsOut) {
    extern __shared__ __align__(16) char sm_dyn[];
    uint32_t a_base = smem_to_u32(sm_dyn);
    uint32_t b_base = a_base + 24576;

    int tid = threadIdx.x, lane = tid & 31, wid = tid >> 5;
    int wm = wid >> 2, wn = wid & 3;            // 4x4 warp grid
    int bm = blockIdx.y * 128, bn = blockIdx.x * 192;
    const int NC = K >> 5;

    float acc[2][6][4] = {};

    auto issue = [&](int buf, int cc) {
        const __half* Ag = A2 + (size_t)bm * K + cc * 32;
        const __half* Bg = B2 + (size_t)bn * K + cc * 32;
        uint32_t ab = a_base + buf * 8192;
        uint32_t bb = b_base + buf * 12288;
        {   // A: 512 chunks, exactly 1 per thread
            int row = tid >> 2, c = tid & 3;
            cp16(tile_addr(ab, row, c), Ag + (size_t)row * K + c * 8);
        }
        for (int t = tid; t < 768; t += 512) {   // B: 768 chunks
            int row = t >> 2, c = t & 3;
            cp16(tile_addr(bb, row, c), Bg + (size_t)row * K + c * 8);
        }
    };

    issue(0, 0); cp_commit();
    issue(1, 1); cp_commit();

    int buf = 0;
    for (int cc = 0; cc < NC; cc++) {
        if (cc + 2 < NC) issue((cc + 2) % 3, cc + 2);
        cp_commit();
        cp_wait2();
        __syncthreads();

        uint32_t ab = a_base + buf * 8192;
        uint32_t bb = b_base + buf * 12288;
        int arow = wm * 32 + (lane & 15);
        int bnrow = wn * 48 + (lane & 7) + ((lane >> 4) << 3);
        int bk8 = (lane >> 3) & 1;
        #pragma unroll
        for (int ks = 0; ks < 2; ks++) {
            uint32_t af[2][4];
            #pragma unroll
            for (int mt = 0; mt < 2; mt++)
                ldm4(af[mt][0], af[mt][1], af[mt][2], af[mt][3],
                     tile_addr(ab, arow + mt * 16, ks * 2 + (lane >> 4)));
            uint32_t bf[6][2];
            #pragma unroll
            for (int pr = 0; pr < 3; pr++)
                ldm4(bf[2 * pr][0], bf[2 * pr][1], bf[2 * pr + 1][0], bf[2 * pr + 1][1],
                     tile_addr(bb, bnrow + pr * 16, ks * 2 + bk8));
            #pragma unroll
            for (int mt = 0; mt < 2; mt++)
                #pragma unroll
                for (int nt = 0; nt < 6; nt++)
                    mma16816(acc[mt][nt][0], acc[mt][nt][1], acc[mt][nt][2], acc[mt][nt][3],
                             af[mt][0], af[mt][1], af[mt][2], af[mt][3],
                             bf[nt][0], bf[nt][1]);
        }
        __syncthreads();
        buf = (buf == 2) ? 0 : buf + 1;
    }

    float2 bcol[6];
    #pragma unroll
    for (int nt = 0; nt < 6; nt++) {
        int col = bn + wn * 48 + nt * 8 + 2 * (lane & 3);
        bcol[nt] = *(const float2*)&bias[col];
    }

    if constexpr (EPI == 2) {
        float* red  = (float*)sm_dyn;
        float* redq = red + 128 * 17;
        int slot = wn * 4 + (lane & 3);

        #pragma unroll
        for (int mt = 0; mt < 2; mt++) {
            #pragma unroll
            for (int half = 0; half < 2; half++) {
                int rl = wm * 32 + mt * 16 + (lane >> 2) + half * 8;
                int row = bm + rl;
                int win = row / NTOK, n = row - win * NTOK;
                int b = win >> 8, wi = win & 255;
                int hh = (wi >> 4) * WSZ + n / WSZ;
                int ww = (wi & 15) * WSZ + n % WSZ;
                int p = hh + 3; if (p >= IMG) p -= IMG;
                int q = ww + 3; if (q >= IMG) q -= IMG;
                size_t pixbase = (size_t)((b * IMG + p) * IMG + q) * CC;
                float s = 0.f, sq2 = 0.f;
                #pragma unroll
                for (int nt = 0; nt < 6; nt++) {
                    int col = wn * 48 + nt * 8 + 2 * (lane & 3);
                    float2 sc = *(const float2*)&addsrc[pixbase + col];
                    float vx = acc[mt][nt][half * 2] + bcol[nt].x + sc.x;
                    float vy = acc[mt][nt][half * 2 + 1] + bcol[nt].y + sc.y;
                    acc[mt][nt][half * 2] = vx;
                    acc[mt][nt][half * 2 + 1] = vy;
                    *(float2*)&outF[pixbase + col] = make_float2(vx, vy);
                    s += vx + vy;
                    sq2 += vx * vx + vy * vy;
                }
                red [rl * 17 + slot] = s;
                redq[rl * 17 + slot] = sq2;
            }
        }
        __syncthreads();
        if (tid < 128) {
            float s = 0.f, qq = 0.f;
            #pragma unroll
            for (int i = 0; i < 16; i++) { s += red[tid * 17 + i]; qq += redq[tid * 17 + i]; }
            float mean = s * (1.f / 192.f);
            float var = qq * (1.f / 192.f) - mean * mean;
            red [tid * 17 + 16] = mean;
            redq[tid * 17 + 16] = rsqrtf(var + 1e-5f);
        }
        __syncthreads();
        #pragma unroll
        for (int mt = 0; mt < 2; mt++) {
            #pragma unroll
            for (int half = 0; half < 2; half++) {
                int rl = wm * 32 + mt * 16 + (lane >> 2) + half * 8;
                int row = bm + rl;
                int win = row / NTOK, n = row - win * NTOK;
                int b = win >> 8, wi = win & 255;
                int hh = (wi >> 4) * WSZ + n / WSZ;
                int ww = (wi & 15) * WSZ + n % WSZ;
                int p = hh + 3; if (p >= IMG) p -= IMG;
                int q = ww + 3; if (q >= IMG) q -= IMG;
                size_t pixbase = (size_t)((b * IMG + p) * IMG + q) * CC;
                float mean = red [rl * 17 + 16];
                float rstd = redq[rl * 17 + 16];
                #pragma unroll
                for (int nt = 0; nt < 6; nt++) {
                    int col = wn * 48 + nt * 8 + 2 * (lane & 3);
                    float2 gv = *(const float2*)&g2[col];
                    float2 bv = *(const float2*)&b2[col];
                    float yx = (acc[mt][nt][half * 2] - mean) * rstd * gv.x + bv.x;
                    float yy = (acc[mt][nt][half * 2 + 1] - mean) * rstd * gv.y + bv.y;
                    *(__half2*)&xsOut[pixbase + col] = __floats2half2_rn(yx, yy);
                }
            }
        }
    } else {
        #pragma unroll
        for (int mt = 0; mt < 2; mt++) {
            #pragma unroll
            for (int half = 0; half < 2; half++) {
                int row = bm + wm * 32 + mt * 16 + (lane >> 2) + half * 8;
                if constexpr (EPI == 1) {
                    int t3 = bn / 192;
                    float scale = (t3 == 0) ? 0.17677669529663687f : 1.f;
                    __half* dst = (t3 == 0) ? g_q : ((t3 == 1) ? g_k : g_v);
                    int win = row / NTOK, n = row - win * NTOK;
                    #pragma unroll
                    for (int nt = 0; nt < 6; nt++) {
                        int col = wn * 48 + nt * 8 + 2 * (lane & 3);
                        int head = col >> 5, dd = col & 31;
                        float vx = (acc[mt][nt][half * 2] + bcol[nt].x) * scale;
                        float vy = (acc[mt][nt][half * 2 + 1] + bcol[nt].y) * scale;
                        *(__half2*)&dst[(((size_t)win * NHEADS + head) * NTOK + n) * DHEAD + dd] =
                            __floats2half2_rn(vx, vy);
                    }
                } else if constexpr (EPI == 3) {
                    size_t rb = (size_t)row * HID;
                    #pragma unroll
                    for (int nt = 0; nt < 6; nt++) {
                        int col = bn + wn * 48 + nt * 8 + 2 * (lane & 3);
                        float gx = gelu_exact(acc[mt][nt][half * 2] + bcol[nt].x);
                        float gy = gelu_exact(acc[mt][nt][half * 2 + 1] + bcol[nt].y);
                        *(__half2*)&outS[rb + col] = __floats2half2_rn(gx, gy);
                    }
                } else {
                    size_t rb = (size_t)row * 192;
                    #pragma unroll
                    for (int nt = 0; nt < 6; nt++) {
                        int col = bn + wn * 48 + nt * 8 + 2 * (lane & 3);
                        float2 s = *(const float2*)&addsrc[rb + col];
                        float vx = acc[mt][nt][half * 2] + bcol[nt].x + s.x;
                        float vy = acc[mt][nt][half * 2 + 1] + bcol[nt].y + s.y;
                        *(float2*)&outF[rb + col] = make_float2(vx, vy);
                    }
                }
            }
        }
    }
}

// ---------------- tensor-core windowed attention ----------------
__global__ __launch_bounds__(128) void attn_mma(__half* __restrict__ outs) {
    int win = blockIdx.x;
    int wi = win & 255;
    int cls = (((wi >> 4) == 15) ? 2 : 0) + (((wi & 15) == 15) ? 1 : 0);
    __shared__ __align__(16) __half sQ[64 * 40], sK[64 * 40], sV[64 * 40];
    __shared__ __align__(16) __half sC[64 * 56];
    int tid = threadIdx.x, lane = tid & 31, wm = tid >> 5;
    int g = lane >> 3, r8 = lane & 7;
    int mr = wm * 16;
    uint32_t qbase = smem_to_u32(sQ), kbase = smem_to_u32(sK);
    uint32_t vbase = smem_to_u32(sV), cbase = smem_to_u32(sC);

    uint4 z = make_uint4(0, 0, 0, 0);
    for (int i = tid; i < 320; i += 128) {
        ((uint4*)sQ)[i] = z; ((uint4*)sK)[i] = z; ((uint4*)sV)[i] = z;
    }
    __syncthreads();

    for (int h = 0; h < NHEADS; h++) {
        {
            const uint4* qg = (const uint4*)(g_q + (size_t)(win * NHEADS + h) * (NTOK * DHEAD));
            const uint4* kg = (const uint4*)(g_k + (size_t)(win * NHEADS + h) * (NTOK * DHEAD));
            const uint4* vg = (const uint4*)(g_v + (size_t)(win * NHEADS + h) * (NTOK * DHEAD));
            for (int i = tid; i < 196; i += 128) {
                int r = i >> 2, c = i & 3;
                *(uint4*)(sQ + r * 40 + c * 8) = qg[i];
                *(uint4*)(sK + r * 40 + c * 8) = kg[i];
                *(uint4*)(sV + r * 40 + c * 8) = vg[i];
            }
            const uint4* cg = (const uint4*)(g_cmb + (size_t)(cls * NHEADS + h) * (64 * 56));
            for (int i = tid; i < 448; i += 128) ((uint4*)sC)[i] = cg[i];
        }
        __syncthreads();

        uint32_t qf[2][4];
        #pragma unroll
        for (int ks = 0; ks < 2; ks++) {
            int row = mr + (g & 1) * 8 + r8;
            int col = ks * 16 + (g >> 1) * 8;
            ldm4(qf[ks][0], qf[ks][1], qf[ks][2], qf[ks][3], qbase + row * 80 + col * 2);
        }

        float sacc[7][4] = {};
        #pragma unroll
        for (int ks = 0; ks < 2; ks++) {
            #pragma unroll
            for (int np = 0; np < 4; np++) {
                int row = np * 16 + ((g >> 1) & 1) * 8 + r8;
                int col = ks * 16 + (g & 1) * 8;
                uint32_t b0, b1, b2, b3;
                ldm4(b0, b1, b2, b3, kbase + row * 80 + col * 2);
                mma16816(sacc[2 * np][0], sacc[2 * np][1], sacc[2 * np][2], sacc[2 * np][3],
                         qf[ks][0], qf[ks][1], qf[ks][2], qf[ks][3], b0, b1);
                if (np < 3)
                    mma16816(sacc[2 * np + 1][0], sacc[2 * np + 1][1], sacc[2 * np + 1][2], sacc[2 * np + 1][3],
                             qf[ks][0], qf[ks][1], qf[ks][2], qf[ks][3], b2, b3);
            }
        }

        #pragma unroll
        for (int np = 0; np < 4; np++) {
            int row = mr + (g & 1) * 8 + r8;
            int colc = 2 * np + ((g >> 1) & 1); if (colc > 6) colc = 6;
            uint32_t c0, c1, c2, c3;
            ldm4(c0, c1, c2, c3, cbase + row * 112 + colc * 8 * 2);
            float2 f;
            f = __half22float2(*(__half2*)&c0); sacc[2 * np][0] += f.x; sacc[2 * np][1] += f.y;
            f = __half22float2(*(__half2*)&c1); sacc[2 * np][2] += f.x; sacc[2 * np][3] += f.y;
            if (np < 3) {
                f = __half22float2(*(__half2*)&c2); sacc[2 * np + 1][0] += f.x; sacc[2 * np + 1][1] += f.y;
                f = __half22float2(*(__half2*)&c3); sacc[2 * np + 1][2] += f.x; sacc[2 * np + 1][3] += f.y;
            }
        }

        float mx0 = -1e30f, mx8 = -1e30f;
        #pragma unroll
        for (int nt = 0; nt < 7; nt++) {
            mx0 = fmaxf(mx0, fmaxf(sacc[nt][0], sacc[nt][1]));
            mx8 = fmaxf(mx8, fmaxf(sacc[nt][2], sacc[nt][3]));
        }
        #pragma unroll
        for (int o = 1; o <= 2; o <<= 1) {
            mx0 = fmaxf(mx0, __shfl_xor_sync(0xffffffffu, mx0, o));
            mx8 = fmaxf(mx8, __shfl_xor_sync(0xffffffffu, mx8, o));
        }
        float s0 = 0.f, s8 = 0.f;
        #pragma unroll
        for (int nt = 0; nt < 7; nt++) {
            sacc[nt][0] = __expf(sacc[nt][0] - mx0); s0 += sacc[nt][0];
            sacc[nt][1] = __expf(sacc[nt][1] - mx0); s0 += sacc[nt][1];
            sacc[nt][2] = __expf(sacc[nt][2] - mx8); s8 += sacc[nt][2];
            sacc[nt][3] = __expf(sacc[nt][3] - mx8); s8 += sacc[nt][3];
        }
        #pragma unroll
        for (int o = 1; o <= 2; o <<= 1) {
            s0 += __shfl_xor_sync(0xffffffffu, s0, o);
            s8 += __shfl_xor_sync(0xffffffffu, s8, o);
        }
        float inv0 = 1.f / s0, inv8 = 1.f / s8;
        #pragma unroll
        for (int nt = 0; nt < 7; nt++) {
            sacc[nt][0] *= inv0; sacc[nt][1] *= inv0;
            sacc[nt][2] *= inv8; sacc[nt][3] *= inv8;
        }

        float oacc[4][4] = {};
        #pragma unroll
        for (int kt = 0; kt < 4; kt++) {
            uint32_t a0 = f22u(sacc[2 * kt][0], sacc[2 * kt][1]);
            uint32_t a1 = f22u(sacc[2 * kt][2], sacc[2 * kt][3]);
            uint32_t a2 = 0, a3 = 0;
            if (kt < 3) {
                a2 = f22u(sacc[2 * kt + 1][0], sacc[2 * kt + 1][1]);
                a3 = f22u(sacc[2 * kt + 1][2], sacc[2 * kt + 1][3]);
            }
            #pragma unroll
            for (int dp = 0; dp < 2; dp++) {
                int row = kt * 16 + (g & 1) * 8 + r8;
                int col = dp * 16 + ((g >> 1) & 1) * 8;
                uint32_t b0, b1, b2, b3;
                ldm4t(b0, b1, b2, b3, vbase + row * 80 + col * 2);
                mma16816(oacc[2 * dp][0], oacc[2 * dp][1], oacc[2 * dp][2], oacc[2 * dp][3],
                         a0, a1, a2, a3, b0, b1);
                mma16816(oacc[2 * dp + 1][0], oacc[2 * dp + 1][1], oacc[2 * dp + 1][2], oacc[2 * dp + 1][3],
                         a0, a1, a2, a3, b2, b3);
            }
        }

        int r0 = mr + (lane >> 2);
        int cbase2 = h * DHEAD + 2 * (lane & 3);
        if (r0 < NTOK) {
            size_t ob = ((size_t)win * NTOK + r0) * CC + cbase2;
            #pragma unroll
            for (int dn = 0; dn < 4; dn++)
                *(__half2*)&outs[ob + dn * 8] = __floats2half2_rn(oacc[dn][0], oacc[dn][1]);
        }
        int r1 = r0 + 8;
        if (r1 < NTOK) {
            size_t ob = ((size_t)win * NTOK + r1) * CC + cbase2;
            #pragma unroll
            for (int dn = 0; dn < 4; dn++)
                *(__half2*)&outs[ob + dn * 8] = __floats2half2_rn(oacc[dn][2], oacc[dn][3]);
        }
        __syncthreads();
    }
}

// ---------------- launch ----------------
extern "C" void kernel_launch(void* const* d_in, const int* in_sizes, int n_in,
                              void* d_out, int out_size) {
    const float* x      = (const float*)d_in[0];
    const float* amask  = (const float*)d_in[1];
    const float* n1g    = (const float*)d_in[2];
    const float* n1b    = (const float*)d_in[3];
    const float* qkv_w  = (const float*)d_in[4];
    const float* qkv_b  = (const float*)d_in[5];
    const float* rpb    = (const float*)d_in[6];
    const float* proj_w = (const float*)d_in[7];
    const float* proj_b = (const float*)d_in[8];
    const float* n2g    = (const float*)d_in[9];
    const float* n2b    = (const float*)d_in[10];
    const float* fc1_w  = (const float*)d_in[11];
    const float* fc1_b  = (const float*)d_in[12];
    const float* fc2_w  = (const float*)d_in[13];
    const float* fc2_b  = (const float*)d_in[14];
    float* out = (float*)d_out;

    __half *xs, *aos, *hs, *wqkv, *wproj, *wfc1, *wfc2;
    float *x2;
    cudaGetSymbolAddress((void**)&xs,    g_xs);
    cudaGetSymbolAddress((void**)&aos,   g_aos);
    cudaGetSymbolAddress((void**)&hs,    g_hs);
    cudaGetSymbolAddress((void**)&x2,    g_x2);
    cudaGetSymbolAddress((void**)&wqkv,  g_wqkv);
    cudaGetSymbolAddress((void**)&wproj, g_wproj);
    cudaGetSymbolAddress((void**)&wfc1,  g_wfc1);
    cudaGetSymbolAddress((void**)&wfc2,  g_wfc2);

    cudaFuncSetAttribute(gemm_mma<1>, cudaFuncAttributeMaxDynamicSharedMemorySize, SMEM_DYN);
    cudaFuncSetAttribute(gemm_mma<2>, cudaFuncAttributeMaxDynamicSharedMemorySize, SMEM_DYN);
    cudaFuncSetAttribute(gemm_mma<3>, cudaFuncAttributeMaxDynamicSharedMemorySize, SMEM_DYN);
    cudaFuncSetAttribute(gemm_mma<4>, cudaFuncAttributeMaxDynamicSharedMemorySize, SMEM_DYN);

    const int MB = MROWS / 128;  // 1568

    prep_all<<<1728, 256>>>(qkv_w, proj_w, fc1_w, fc2_w);
    prep_cmb<<<24, 256>>>(amask, rpb);
    ln1_kernel<<<MROWS / 8, 256>>>(x, n1g, n1b, xs);
    gemm_mma<1><<<dim3(3, MB), 512, SMEM_DYN>>>(xs, wqkv, qkv_b, nullptr, nullptr, nullptr, 192, 576,
                                                nullptr, nullptr, nullptr);
    attn_mma<<<NWIN, 128>>>(aos);
    gemm_mma<2><<<dim3(1, MB), 512, SMEM_DYN>>>(aos, wproj, proj_b, x2, x, nullptr, 192, 192,
                                                n2g, n2b, xs);
    gemm_mma<3><<<dim3(4, MB), 512, SMEM_DYN>>>(xs, wfc1, fc1_b, nullptr, nullptr, hs, 192, 768,
                                                nullptr, nullptr, nullptr);
    gemm_mma<4><<<dim3(1, MB), 512, SMEM_DYN>>>(hs, wfc2, fc2_b, out, x2, nullptr, 768, 192,
                                                nullptr, nullptr, nullptr);
}

// round 8
// speedup vs baseline: 18.7056x; 1.1362x over previous
#include <cuda_runtime.h>
#include <cuda_fp16.h>
#include <math.h>
#include <stdint.h>

// ---------------- problem constants ----------------
#define BATCH   16
#define IMG     112
#define CC      192
#define NHEADS  6
#define DHEAD   32
#define WSZ     7
#define NTOK    49
#define NWIN    4096
#define MROWS   200704
#define HID     768

// ---------------- device scratch ----------------
__device__ __half g_xs [(size_t)MROWS * CC];
__device__ __half g_aos[(size_t)MROWS * CC];
__device__ __half g_hs [(size_t)MROWS * HID];
__device__ __half g_q[(size_t)NWIN * NHEADS * NTOK * DHEAD];
__device__ __half g_k[(size_t)NWIN * NHEADS * NTOK * DHEAD];
__device__ __half g_v[(size_t)NWIN * NHEADS * NTOK * DHEAD];
__device__ float g_x2[(size_t)MROWS * CC];
__device__ __half g_wqkv [(size_t)576 * 192];
__device__ __half g_wproj[(size_t)192 * 192];
__device__ __half g_wfc1 [(size_t)768 * 192];
__device__ __half g_wfc2 [(size_t)192 * 768];
__device__ __half g_cmb[(size_t)4 * NHEADS * 64 * 56];

// ---------------- helpers ----------------
__device__ __forceinline__ uint32_t smem_to_u32(const void* p) {
    uint32_t a;
    asm("{ .reg .u64 t; cvta.to.shared.u64 t, %1; cvt.u32.u64 %0, t; }" : "=r"(a) : "l"(p));
    return a;
}
__device__ __forceinline__ void cp16(uint32_t sm, const void* gp) {
    asm volatile("cp.async.cg.shared.global [%0], [%1], 16;" :: "r"(sm), "l"(gp));
}
__device__ __forceinline__ void cp_commit() { asm volatile("cp.async.commit_group;"); }
__device__ __forceinline__ void cp_wait1()  { asm volatile("cp.async.wait_group 1;"); }
__device__ __forceinline__ void cp_wait0()  { asm volatile("cp.async.wait_group 0;"); }

__device__ __forceinline__ void ldm4(uint32_t& x0, uint32_t& x1, uint32_t& x2, uint32_t& x3, uint32_t addr) {
    asm volatile("ldmatrix.sync.aligned.m8n8.x4.shared.b16 {%0,%1,%2,%3}, [%4];"
                 : "=r"(x0), "=r"(x1), "=r"(x2), "=r"(x3) : "r"(addr));
}
__device__ __forceinline__ void ldm4t(uint32_t& x0, uint32_t& x1, uint32_t& x2, uint32_t& x3, uint32_t addr) {
    asm volatile("ldmatrix.sync.aligned.m8n8.x4.trans.shared.b16 {%0,%1,%2,%3}, [%4];"
                 : "=r"(x0), "=r"(x1), "=r"(x2), "=r"(x3) : "r"(addr));
}
__device__ __forceinline__ void mma16816(float& d0, float& d1, float& d2, float& d3,
                                         uint32_t a0, uint32_t a1, uint32_t a2, uint32_t a3,
                                         uint32_t b0, uint32_t b1) {
    asm volatile("mma.sync.aligned.m16n8k16.row.col.f32.f16.f16.f32 "
                 "{%0,%1,%2,%3},{%4,%5,%6,%7},{%8,%9},{%0,%1,%2,%3};"
                 : "+f"(d0), "+f"(d1), "+f"(d2), "+f"(d3)
                 : "r"(a0), "r"(a1), "r"(a2), "r"(a3), "r"(b0), "r"(b1));
}
__device__ __forceinline__ uint32_t f22u(float a, float b) {
    __half2 h = __floats2half2_rn(a, b);
    return *(uint32_t*)&h;
}
__device__ __forceinline__ uint32_t tile_addr(uint32_t base, int row, int chunk) {
    return base + row * 64 + ((chunk ^ ((row >> 1) & 3)) << 4);
}
__device__ __forceinline__ float gelu_exact(float x) {
    return 0.5f * x * (1.f + erff(x * 0.70710678118654752f));
}

// ---------------- merged weight prep ----------------
__global__ void prep_all(const float* __restrict__ qkv_w, const float* __restrict__ proj_w,
                         const float* __restrict__ fc1_w, const float* __restrict__ fc2_w) {
    int i = blockIdx.x * 256 + threadIdx.x;
    const float* W; __half* D; int K, N, off;
    if (i < 110592)      { W = qkv_w;  D = g_wqkv;  K = 192; N = 576; off = i; }
    else if (i < 147456) { W = proj_w; D = g_wproj; K = 192; N = 192; off = i - 110592; }
    else if (i < 294912) { W = fc1_w;  D = g_wfc1;  K = 192; N = 768; off = i - 147456; }
    else if (i < 442368) { W = fc2_w;  D = g_wfc2;  K = 768; N = 192; off = i - 294912; }
    else return;
    int k = off / N, n = off - k * N;
    D[(size_t)n * K + k] = __float2half(W[off]);
}

// ---------------- bias+mask table prep ----------------
__global__ void prep_cmb(const float* __restrict__ amask, const float* __restrict__ rpb) {
    int ch = blockIdx.x;
    int cls = ch / NHEADS, head = ch - cls * NHEADS;
    int wi_rep = (cls >> 1 ? 240 : 0) + ((cls & 1) ? 15 : 0);
    __half* dst = g_cmb + (size_t)ch * (64 * 56);
    for (int idx = threadIdx.x; idx < 64 * 56; idx += 256) {
        int r = idx / 56, c = idx - r * 56;
        float v;
        if (r < NTOK && c < NTOK) {
            int i1 = r / WSZ, j1 = r - i1 * WSZ;
            int i2 = c / WSZ, j2 = c - i2 * WSZ;
            int rel = (i1 - i2 + 6) * 13 + (j1 - j2 + 6);
            v = rpb[rel * NHEADS + head] + amask[((size_t)wi_rep * NTOK + r) * NTOK + c];
        } else {
            v = -100.f;
        }
        dst[idx] = __float2half(v);
    }
}

// ---------------- LN1 (fused shift + window partition) ----------------
__global__ __launch_bounds__(256) void ln1_kernel(const float* __restrict__ src_full,
                                                  const float* __restrict__ gam,
                                                  const float* __restrict__ bet,
                                                  __half* __restrict__ out) {
    int t = blockIdx.x * 8 + (threadIdx.x >> 5);
    int lane = threadIdx.x & 31;
    int win = t / NTOK, n = t - win * NTOK;
    int b = win >> 8, wi = win & 255;
    int hh = (wi >> 4) * WSZ + n / WSZ;
    int ww = (wi & 15) * WSZ + n % WSZ;
    int sh = hh + 3; if (sh >= IMG) sh -= IMG;
    int sw = ww + 3; if (sw >= IMG) sw -= IMG;
    const float* src = src_full + (size_t)((b * IMG + sh) * IMG + sw) * CC;

    float v[6]; float s = 0.f, s2 = 0.f;
    #pragma unroll
    for (int i = 0; i < 6; i++) { float a = src[i * 32 + lane]; v[i] = a; s += a; s2 += a * a; }
    #pragma unroll
    for (int o = 16; o; o >>= 1) {
        s  += __shfl_xor_sync(0xffffffffu, s,  o);
        s2 += __shfl_xor_sync(0xffffffffu, s2, o);
    }
    float mean = s * (1.f / 192.f);
    float var  = s2 * (1.f / 192.f) - mean * mean;
    float rstd = rsqrtf(var + 1e-5f);
    __half* dst = out + (size_t)t * CC;
    #pragma unroll
    for (int i = 0; i < 6; i++) {
        int c = i * 32 + lane;
        dst[c] = __float2half((v[i] - mean) * rstd * gam[c] + bet[c]);
    }
}

// ---------------- mma.sync GEMM: BM=64, BN=192, BK=32; 256 thr (8 warps 2x4), 2 CTA/SM ----------------
#define SMEM_DYN 49152   // 3*(64*32 + 192*32)*2
template<int EPI>
__global__ __launch_bounds__(256, 2)
void gemm_mma(const __half* __restrict__ A2, const __half* __restrict__ B2,
              const float* __restrict__ bias, float* __restrict__ outF,
              const float* __restrict__ addsrc, __half* __restrict__ outS,
              int K, int Nn,
              const float* __restrict__ g2, const float* __restrict__ b2,
              __half* __restrict__ xsOut) {
    extern __shared__ __align__(16) char sm_dyn[];
    uint32_t a_base = smem_to_u32(sm_dyn);
    uint32_t b_base = a_base + 12288;   // 3 A-buffers of 4096B

    int tid = threadIdx.x, lane = tid & 31, wid = tid >> 5;
    int wm = wid >> 2, wn = wid & 3;            // 2x4 warp grid
    int bm = blockIdx.y * 64, bn = blockIdx.x * 192;
    const int NC = K >> 5;

    float acc[2][6][4] = {};

    auto issue = [&](int buf, int cc) {
        const __half* Ag = A2 + (size_t)bm * K + cc * 32;
        const __half* Bg = B2 + (size_t)bn * K + cc * 32;
        uint32_t ab = a_base + buf * 4096;
        uint32_t bb = b_base + buf * 12288;
        {   // A: 256 chunks, 1 per thread
            int row = tid >> 2, c = tid & 3;
            cp16(tile_addr(ab, row, c), Ag + (size_t)row * K + c * 8);
        }
        #pragma unroll
        for (int i = 0; i < 3; i++) {   // B: 768 chunks
            int t = tid + i * 256, row = t >> 2, c = t & 3;
            cp16(tile_addr(bb, row, c), Bg + (size_t)row * K + c * 8);
        }
        cp_commit();
    };

    issue(0, 0);
    issue(1, 1);

    for (int cc = 0; cc < NC; cc++) {
        int buf = cc % 3;
        if (cc + 1 < NC) cp_wait1(); else cp_wait0();
        __syncthreads();
        if (cc + 2 < NC) issue((cc + 2) % 3, cc + 2);

        uint32_t ab = a_base + buf * 4096;
        uint32_t bb = b_base + buf * 12288;
        int arow = wm * 32 + (lane & 15);
        int bnrow = wn * 48 + (lane & 7) + ((lane >> 4) << 3);
        int bk8 = (lane >> 3) & 1;
        #pragma unroll
        for (int ks = 0; ks < 2; ks++) {
            uint32_t af[2][4];
            #pragma unroll
            for (int mt = 0; mt < 2; mt++)
                ldm4(af[mt][0], af[mt][1], af[mt][2], af[mt][3],
                     tile_addr(ab, arow + mt * 16, ks * 2 + (lane >> 4)));
            uint32_t bf[6][2];
            #pragma unroll
            for (int pr = 0; pr < 3; pr++)
                ldm4(bf[2 * pr][0], bf[2 * pr][1], bf[2 * pr + 1][0], bf[2 * pr + 1][1],
                     tile_addr(bb, bnrow + pr * 16, ks * 2 + bk8));
            #pragma unroll
            for (int mt = 0; mt < 2; mt++)
                #pragma unroll
                for (int nt = 0; nt < 6; nt++)
                    mma16816(acc[mt][nt][0], acc[mt][nt][1], acc[mt][nt][2], acc[mt][nt][3],
                             af[mt][0], af[mt][1], af[mt][2], af[mt][3],
                             bf[nt][0], bf[nt][1]);
        }
        __syncthreads();
    }

    float2 bcol[6];
    #pragma unroll
    for (int nt = 0; nt < 6; nt++) {
        int col = bn + wn * 48 + nt * 8 + 2 * (lane & 3);
        bcol[nt] = *(const float2*)&bias[col];
    }

    if constexpr (EPI == 2) {
        float* red  = (float*)sm_dyn;          // [64][17]
        float* redq = red + 64 * 17;
        int slot = wn * 4 + (lane & 3);

        #pragma unroll
        for (int mt = 0; mt < 2; mt++) {
            #pragma unroll
            for (int half = 0; half < 2; half++) {
                int rl = wm * 32 + mt * 16 + (lane >> 2) + half * 8;
                int row = bm + rl;
                int win = row / NTOK, n = row - win * NTOK;
                int b = win >> 8, wi = win & 255;
                int hh = (wi >> 4) * WSZ + n / WSZ;
                int ww = (wi & 15) * WSZ + n % WSZ;
                int p = hh + 3; if (p >= IMG) p -= IMG;
                int q = ww + 3; if (q >= IMG) q -= IMG;
                size_t pixbase = (size_t)((b * IMG + p) * IMG + q) * CC;
                float s = 0.f, sq2 = 0.f;
                #pragma unroll
                for (int nt = 0; nt < 6; nt++) {
                    int col = wn * 48 + nt * 8 + 2 * (lane & 3);
                    float2 sc = *(const float2*)&addsrc[pixbase + col];
                    float vx = acc[mt][nt][half * 2] + bcol[nt].x + sc.x;
                    float vy = acc[mt][nt][half * 2 + 1] + bcol[nt].y + sc.y;
                    acc[mt][nt][half * 2] = vx;
                    acc[mt][nt][half * 2 + 1] = vy;
                    *(float2*)&outF[pixbase + col] = make_float2(vx, vy);
                    s += vx + vy;
                    sq2 += vx * vx + vy * vy;
                }
                red [rl * 17 + slot] = s;
                redq[rl * 17 + slot] = sq2;
            }
        }
        __syncthreads();
        if (tid < 64) {
            float s = 0.f, qq = 0.f;
            #pragma unroll
            for (int i = 0; i < 16; i++) { s += red[tid * 17 + i]; qq += redq[tid * 17 + i]; }
            float mean = s * (1.f / 192.f);
            float var = qq * (1.f / 192.f) - mean * mean;
            red [tid * 17 + 16] = mean;
            redq[tid * 17 + 16] = rsqrtf(var + 1e-5f);
        }
        __syncthreads();
        #pragma unroll
        for (int mt = 0; mt < 2; mt++) {
            #pragma unroll
            for (int half = 0; half < 2; half++) {
                int rl = wm * 32 + mt * 16 + (lane >> 2) + half * 8;
                int row = bm + rl;
                int win = row / NTOK, n = row - win * NTOK;
                int b = win >> 8, wi = win & 255;
                int hh = (wi >> 4) * WSZ + n / WSZ;
                int ww = (wi & 15) * WSZ + n % WSZ;
                int p = hh + 3; if (p >= IMG) p -= IMG;
                int q = ww + 3; if (q >= IMG) q -= IMG;
                size_t pixbase = (size_t)((b * IMG + p) * IMG + q) * CC;
                float mean = red [rl * 17 + 16];
                float rstd = redq[rl * 17 + 16];
                #pragma unroll
                for (int nt = 0; nt < 6; nt++) {
                    int col = wn * 48 + nt * 8 + 2 * (lane & 3);
                    float2 gv = *(const float2*)&g2[col];
                    float2 bv = *(const float2*)&b2[col];
                    float yx = (acc[mt][nt][half * 2] - mean) * rstd * gv.x + bv.x;
                    float yy = (acc[mt][nt][half * 2 + 1] - mean) * rstd * gv.y + bv.y;
                    *(__half2*)&xsOut[pixbase + col] = __floats2half2_rn(yx, yy);
                }
            }
        }
    } else {
        #pragma unroll
        for (int mt = 0; mt < 2; mt++) {
            #pragma unroll
            for (int half = 0; half < 2; half++) {
                int row = bm + wm * 32 + mt * 16 + (lane >> 2) + half * 8;
                if constexpr (EPI == 1) {
                    int t3 = bn / 192;
                    float scale = (t3 == 0) ? 0.17677669529663687f : 1.f;
                    __half* dst = (t3 == 0) ? g_q : ((t3 == 1) ? g_k : g_v);
                    int win = row / NTOK, n = row - win * NTOK;
                    #pragma unroll
                    for (int nt = 0; nt < 6; nt++) {
                        int col = wn * 48 + nt * 8 + 2 * (lane & 3);
                        int head = col >> 5, dd = col & 31;
                        float vx = (acc[mt][nt][half * 2] + bcol[nt].x) * scale;
                        float vy = (acc[mt][nt][half * 2 + 1] + bcol[nt].y) * scale;
                        *(__half2*)&dst[(((size_t)win * NHEADS + head) * NTOK + n) * DHEAD + dd] =
                            __floats2half2_rn(vx, vy);
                    }
                } else if constexpr (EPI == 3) {
                    size_t rb = (size_t)row * HID;
                    #pragma unroll
                    for (int nt = 0; nt < 6; nt++) {
                        int col = bn + wn * 48 + nt * 8 + 2 * (lane & 3);
                        float gx = gelu_exact(acc[mt][nt][half * 2] + bcol[nt].x);
                        float gy = gelu_exact(acc[mt][nt][half * 2 + 1] + bcol[nt].y);
                        *(__half2*)&outS[rb + col] = __floats2half2_rn(gx, gy);
                    }
                } else {
                    size_t rb = (size_t)row * 192;
                    #pragma unroll
                    for (int nt = 0; nt < 6; nt++) {
                        int col = bn + wn * 48 + nt * 8 + 2 * (lane & 3);
                        float2 s = *(const float2*)&addsrc[rb + col];
                        float vx = acc[mt][nt][half * 2] + bcol[nt].x + s.x;
                        float vy = acc[mt][nt][half * 2 + 1] + bcol[nt].y + s.y;
                        *(float2*)&outF[rb + col] = make_float2(vx, vy);
                    }
                }
            }
        }
    }
}

// ---------------- tensor-core windowed attention: 256 thr, 2 heads in parallel ----------------
__global__ __launch_bounds__(256) void attn_mma(__half* __restrict__ outs) {
    int win = blockIdx.x;
    int wi = win & 255;
    int cls = (((wi >> 4) == 15) ? 2 : 0) + (((wi & 15) == 15) ? 1 : 0);
    __shared__ __align__(16) __half sQ[2][64 * 40], sK[2][64 * 40], sV[2][64 * 40];
    __shared__ __align__(16) __half sC[2][64 * 56];
    int tid = threadIdx.x;
    int wg = tid >> 7;              // head-group 0/1
    int t = tid & 127;
    int lane = t & 31, wmg = t >> 5;
    int g = lane >> 3, r8 = lane & 7;
    int mr = wmg * 16;
    uint32_t qbase = smem_to_u32(sQ[wg]), kbase = smem_to_u32(sK[wg]);
    uint32_t vbase = smem_to_u32(sV[wg]), cbase = smem_to_u32(sC[wg]);

    uint4 z = make_uint4(0, 0, 0, 0);
    for (int i = tid; i < 640; i += 256) {
        ((uint4*)sQ)[i] = z; ((uint4*)sK)[i] = z; ((uint4*)sV)[i] = z;
    }
    __syncthreads();

    for (int h2 = 0; h2 < 3; h2++) {
        int h = h2 * 2 + wg;
        {
            const uint4* qg = (const uint4*)(g_q + (size_t)(win * NHEADS + h) * (NTOK * DHEAD));
            const uint4* kg = (const uint4*)(g_k + (size_t)(win * NHEADS + h) * (NTOK * DHEAD));
            const uint4* vg = (const uint4*)(g_v + (size_t)(win * NHEADS + h) * (NTOK * DHEAD));
            for (int i = t; i < 196; i += 128) {
                int r = i >> 2, c = i & 3;
                *(uint4*)(sQ[wg] + r * 40 + c * 8) = qg[i];
                *(uint4*)(sK[wg] + r * 40 + c * 8) = kg[i];
                *(uint4*)(sV[wg] + r * 40 + c * 8) = vg[i];
            }
            const uint4* cg = (const uint4*)(g_cmb + (size_t)(cls * NHEADS + h) * (64 * 56));
            for (int i = t; i < 448; i += 128) ((uint4*)sC[wg])[i] = cg[i];
        }
        __syncthreads();

        uint32_t qf[2][4];
        #pragma unroll
        for (int ks = 0; ks < 2; ks++) {
            int row = mr + (g & 1) * 8 + r8;
            int col = ks * 16 + (g >> 1) * 8;
            ldm4(qf[ks][0], qf[ks][1], qf[ks][2], qf[ks][3], qbase + row * 80 + col * 2);
        }

        float sacc[7][4] = {};
        #pragma unroll
        for (int ks = 0; ks < 2; ks++) {
            #pragma unroll
            for (int np = 0; np < 4; np++) {
                int row = np * 16 + ((g >> 1) & 1) * 8 + r8;
                int col = ks * 16 + (g & 1) * 8;
                uint32_t b0, b1, b2, b3;
                ldm4(b0, b1, b2, b3, kbase + row * 80 + col * 2);
                mma16816(sacc[2 * np][0], sacc[2 * np][1], sacc[2 * np][2], sacc[2 * np][3],
                         qf[ks][0], qf[ks][1], qf[ks][2], qf[ks][3], b0, b1);
                if (np < 3)
                    mma16816(sacc[2 * np + 1][0], sacc[2 * np + 1][1], sacc[2 * np + 1][2], sacc[2 * np + 1][3],
                             qf[ks][0], qf[ks][1], qf[ks][2], qf[ks][3], b2, b3);
            }
        }

        #pragma unroll
        for (int np = 0; np < 4; np++) {
            int row = mr + (g & 1) * 8 + r8;
            int colc = 2 * np + ((g >> 1) & 1); if (colc > 6) colc = 6;
            uint32_t c0, c1, c2, c3;
            ldm4(c0, c1, c2, c3, cbase + row * 112 + colc * 8 * 2);
            float2 f;
            f = __half22float2(*(__half2*)&c0); sacc[2 * np][0] += f.x; sacc[2 * np][1] += f.y;
            f = __half22float2(*(__half2*)&c1); sacc[2 * np][2] += f.x; sacc[2 * np][3] += f.y;
            if (np < 3) {
                f = __half22float2(*(__half2*)&c2); sacc[2 * np + 1][0] += f.x; sacc[2 * np + 1][1] += f.y;
                f = __half22float2(*(__half2*)&c3); sacc[2 * np + 1][2] += f.x; sacc[2 * np + 1][3] += f.y;
            }
        }

        float mx0 = -1e30f, mx8 = -1e30f;
        #pragma unroll
        for (int nt = 0; nt < 7; nt++) {
            mx0 = fmaxf(mx0, fmaxf(sacc[nt][0], sacc[nt][1]));
            mx8 = fmaxf(mx8, fmaxf(sacc[nt][2], sacc[nt][3]));
        }
        #pragma unroll
        for (int o = 1; o <= 2; o <<= 1) {
            mx0 = fmaxf(mx0, __shfl_xor_sync(0xffffffffu, mx0, o));
            mx8 = fmaxf(mx8, __shfl_xor_sync(0xffffffffu, mx8, o));
        }
        float s0 = 0.f, s8 = 0.f;
        #pragma unroll
        for (int nt = 0; nt < 7; nt++) {
            sacc[nt][0] = __expf(sacc[nt][0] - mx0); s0 += sacc[nt][0];
            sacc[nt][1] = __expf(sacc[nt][1] - mx0); s0 += sacc[nt][1];
            sacc[nt][2] = __expf(sacc[nt][2] - mx8); s8 += sacc[nt][2];
            sacc[nt][3] = __expf(sacc[nt][3] - mx8); s8 += sacc[nt][3];
        }
        #pragma unroll
        for (int o = 1; o <= 2; o <<= 1) {
            s0 += __shfl_xor_sync(0xffffffffu, s0, o);
            s8 += __shfl_xor_sync(0xffffffffu, s8, o);
        }
        float inv0 = 1.f / s0, inv8 = 1.f / s8;
        #pragma unroll
        for (int nt = 0; nt < 7; nt++) {
            sacc[nt][0] *= inv0; sacc[nt][1] *= inv0;
            sacc[nt][2] *= inv8; sacc[nt][3] *= inv8;
        }

        float oacc[4][4] = {};
        #pragma unroll
        for (int kt = 0; kt < 4; kt++) {
            uint32_t a0 = f22u(sacc[2 * kt][0], sacc[2 * kt][1]);
            uint32_t a1 = f22u(sacc[2 * kt][2], sacc[2 * kt][3]);
            uint32_t a2 = 0, a3 = 0;
            if (kt < 3) {
                a2 = f22u(sacc[2 * kt + 1][0], sacc[2 * kt + 1][1]);
                a3 = f22u(sacc[2 * kt + 1][2], sacc[2 * kt + 1][3]);
            }
            #pragma unroll
            for (int dp = 0; dp < 2; dp++) {
                int row = kt * 16 + (g & 1) * 8 + r8;
                int col = dp * 16 + ((g >> 1) & 1) * 8;
                uint32_t b0, b1, b2, b3;
                ldm4t(b0, b1, b2, b3, vbase + row * 80 + col * 2);
                mma16816(oacc[2 * dp][0], oacc[2 * dp][1], oacc[2 * dp][2], oacc[2 * dp][3],
                         a0, a1, a2, a3, b0, b1);
                mma16816(oacc[2 * dp + 1][0], oacc[2 * dp + 1][1], oacc[2 * dp + 1][2], oacc[2 * dp + 1][3],
                         a0, a1, a2, a3, b2, b3);
            }
        }

        int r0 = mr + (lane >> 2);
        int cbase2 = h * DHEAD + 2 * (lane & 3);
        if (r0 < NTOK) {
            size_t ob = ((size_t)win * NTOK + r0) * CC + cbase2;
            #pragma unroll
            for (int dn = 0; dn < 4; dn++)
                *(__half2*)&outs[ob + dn * 8] = __floats2half2_rn(oacc[dn][0], oacc[dn][1]);
        }
        int r1 = r0 + 8;
        if (r1 < NTOK) {
            size_t ob = ((size_t)win * NTOK + r1) * CC + cbase2;
            #pragma unroll
            for (int dn = 0; dn < 4; dn++)
                *(__half2*)&outs[ob + dn * 8] = __floats2half2_rn(oacc[dn][2], oacc[dn][3]);
        }
        __syncthreads();
    }
}

// ---------------- launch ----------------
extern "C" void kernel_launch(void* const* d_in, const int* in_sizes, int n_in,
                              void* d_out, int out_size) {
    const float* x      = (const float*)d_in[0];
    const float* amask  = (const float*)d_in[1];
    const float* n1g    = (const float*)d_in[2];
    const float* n1b    = (const float*)d_in[3];
    const float* qkv_w  = (const float*)d_in[4];
    const float* qkv_b  = (const float*)d_in[5];
    const float* rpb    = (const float*)d_in[6];
    const float* proj_w = (const float*)d_in[7];
    const float* proj_b = (const float*)d_in[8];
    const float* n2g    = (const float*)d_in[9];
    const float* n2b    = (const float*)d_in[10];
    const float* fc1_w  = (const float*)d_in[11];
    const float* fc1_b  = (const float*)d_in[12];
    const float* fc2_w  = (const float*)d_in[13];
    const float* fc2_b  = (const float*)d_in[14];
    float* out = (float*)d_out;

    __half *xs, *aos, *hs, *wqkv, *wproj, *wfc1, *wfc2;
    float *x2;
    cudaGetSymbolAddress((void**)&xs,    g_xs);
    cudaGetSymbolAddress((void**)&aos,   g_aos);
    cudaGetSymbolAddress((void**)&hs,    g_hs);
    cudaGetSymbolAddress((void**)&x2,    g_x2);
    cudaGetSymbolAddress((void**)&wqkv,  g_wqkv);
    cudaGetSymbolAddress((void**)&wproj, g_wproj);
    cudaGetSymbolAddress((void**)&wfc1,  g_wfc1);
    cudaGetSymbolAddress((void**)&wfc2,  g_wfc2);

    cudaFuncSetAttribute(gemm_mma<1>, cudaFuncAttributeMaxDynamicSharedMemorySize, SMEM_DYN);
    cudaFuncSetAttribute(gemm_mma<2>, cudaFuncAttributeMaxDynamicSharedMemorySize, SMEM_DYN);
    cudaFuncSetAttribute(gemm_mma<3>, cudaFuncAttributeMaxDynamicSharedMemorySize, SMEM_DYN);
    cudaFuncSetAttribute(gemm_mma<4>, cudaFuncAttributeMaxDynamicSharedMemorySize, SMEM_DYN);

    const int MB = MROWS / 64;  // 3136

    prep_all<<<1728, 256>>>(qkv_w, proj_w, fc1_w, fc2_w);
    prep_cmb<<<24, 256>>>(amask, rpb);
    ln1_kernel<<<MROWS / 8, 256>>>(x, n1g, n1b, xs);
    gemm_mma<1><<<dim3(3, MB), 256, SMEM_DYN>>>(xs, wqkv, qkv_b, nullptr, nullptr, nullptr, 192, 576,
                                                nullptr, nullptr, nullptr);
    attn_mma<<<NWIN, 256>>>(aos);
    gemm_mma<2><<<dim3(1, MB), 256, SMEM_DYN>>>(aos, wproj, proj_b, x2, x, nullptr, 192, 192,
                                                n2g, n2b, xs);
    gemm_mma<3><<<dim3(4, MB), 256, SMEM_DYN>>>(xs, wfc1, fc1_b, nullptr, nullptr, hs, 192, 768,
                                                nullptr, nullptr, nullptr);
    gemm_mma<4><<<dim3(1, MB), 256, SMEM_DYN>>>(hs, wfc2, fc2_b, out, x2, nullptr, 768, 192,
                                                nullptr, nullptr, nullptr);
}

// round 9
// speedup vs baseline: 20.3460x; 1.0877x over previous
#include <cuda_runtime.h>
#include <cuda_fp16.h>
#include <math.h>
#include <stdint.h>

// ---------------- problem constants ----------------
#define BATCH   16
#define IMG     112
#define CC      192
#define NHEADS  6
#define DHEAD   32
#define WSZ     7
#define NTOK    49
#define NWIN    4096
#define MROWS   200704
#define HID     768

// ---------------- device scratch ----------------
__device__ __half g_xs [(size_t)MROWS * CC];
__device__ __half g_aos[(size_t)MROWS * CC];
__device__ __half g_hs [(size_t)MROWS * HID];
__device__ __half g_q[(size_t)NWIN * NHEADS * NTOK * DHEAD];
__device__ __half g_k[(size_t)NWIN * NHEADS * NTOK * DHEAD];
__device__ __half g_v[(size_t)NWIN * NHEADS * NTOK * DHEAD];
__device__ float g_x2[(size_t)MROWS * CC];
__device__ __half g_wqkv [(size_t)576 * 192];
__device__ __half g_wproj[(size_t)192 * 192];
__device__ __half g_wfc1 [(size_t)768 * 192];
__device__ __half g_wfc2 [(size_t)192 * 768];
__device__ __half g_cmb[(size_t)4 * NHEADS * 64 * 56];

// ---------------- helpers ----------------
__device__ __forceinline__ uint32_t smem_to_u32(const void* p) {
    uint32_t a;
    asm("{ .reg .u64 t; cvta.to.shared.u64 t, %1; cvt.u32.u64 %0, t; }" : "=r"(a) : "l"(p));
    return a;
}
__device__ __forceinline__ void cp16(uint32_t sm, const void* gp) {
    asm volatile("cp.async.cg.shared.global [%0], [%1], 16;" :: "r"(sm), "l"(gp));
}
__device__ __forceinline__ void cp_commit() { asm volatile("cp.async.commit_group;"); }
__device__ __forceinline__ void cp_wait1()  { asm volatile("cp.async.wait_group 1;"); }
__device__ __forceinline__ void cp_wait0()  { asm volatile("cp.async.wait_group 0;"); }

__device__ __forceinline__ void ldm4(uint32_t& x0, uint32_t& x1, uint32_t& x2, uint32_t& x3, uint32_t addr) {
    asm volatile("ldmatrix.sync.aligned.m8n8.x4.shared.b16 {%0,%1,%2,%3}, [%4];"
                 : "=r"(x0), "=r"(x1), "=r"(x2), "=r"(x3) : "r"(addr));
}
__device__ __forceinline__ void ldm4t(uint32_t& x0, uint32_t& x1, uint32_t& x2, uint32_t& x3, uint32_t addr) {
    asm volatile("ldmatrix.sync.aligned.m8n8.x4.trans.shared.b16 {%0,%1,%2,%3}, [%4];"
                 : "=r"(x0), "=r"(x1), "=r"(x2), "=r"(x3) : "r"(addr));
}
__device__ __forceinline__ void mma16816(float& d0, float& d1, float& d2, float& d3,
                                         uint32_t a0, uint32_t a1, uint32_t a2, uint32_t a3,
                                         uint32_t b0, uint32_t b1) {
    asm volatile("mma.sync.aligned.m16n8k16.row.col.f32.f16.f16.f32 "
                 "{%0,%1,%2,%3},{%4,%5,%6,%7},{%8,%9},{%0,%1,%2,%3};"
                 : "+f"(d0), "+f"(d1), "+f"(d2), "+f"(d3)
                 : "r"(a0), "r"(a1), "r"(a2), "r"(a3), "r"(b0), "r"(b1));
}
__device__ __forceinline__ uint32_t f22u(float a, float b) {
    __half2 h = __floats2half2_rn(a, b);
    return *(uint32_t*)&h;
}
// pipe-tile addressing (rows of 32 halves / 64B, 4 chunks)
__device__ __forceinline__ uint32_t tile_addr(uint32_t base, int row, int chunk) {
    return base + row * 64 + ((chunk ^ ((row >> 1) & 3)) << 4);
}
// full-tile addressing (rows of 192 halves / 384B, 24 chunks of 16B)
__device__ __forceinline__ uint32_t full_addr(uint32_t base, int row, int c) {
    return base + row * 384 + (((c & 24) | ((c ^ row) & 7)) << 4);
}
__device__ __forceinline__ float gelu_exact(float x) {
    return 0.5f * x * (1.f + erff(x * 0.70710678118654752f));
}

// ---------------- merged weight prep ----------------
__global__ void prep_all(const float* __restrict__ qkv_w, const float* __restrict__ proj_w,
                         const float* __restrict__ fc1_w, const float* __restrict__ fc2_w) {
    int i = blockIdx.x * 256 + threadIdx.x;
    const float* W; __half* D; int K, N, off;
    if (i < 110592)      { W = qkv_w;  D = g_wqkv;  K = 192; N = 576; off = i; }
    else if (i < 147456) { W = proj_w; D = g_wproj; K = 192; N = 192; off = i - 110592; }
    else if (i < 294912) { W = fc1_w;  D = g_wfc1;  K = 192; N = 768; off = i - 147456; }
    else if (i < 442368) { W = fc2_w;  D = g_wfc2;  K = 768; N = 192; off = i - 294912; }
    else return;
    int k = off / N, n = off - k * N;
    D[(size_t)n * K + k] = __float2half(W[off]);
}

// ---------------- bias+mask table prep ----------------
__global__ void prep_cmb(const float* __restrict__ amask, const float* __restrict__ rpb) {
    int ch = blockIdx.x;
    int cls = ch / NHEADS, head = ch - cls * NHEADS;
    int wi_rep = (cls >> 1 ? 240 : 0) + ((cls & 1) ? 15 : 0);
    __half* dst = g_cmb + (size_t)ch * (64 * 56);
    for (int idx = threadIdx.x; idx < 64 * 56; idx += 256) {
        int r = idx / 56, c = idx - r * 56;
        float v;
        if (r < NTOK && c < NTOK) {
            int i1 = r / WSZ, j1 = r - i1 * WSZ;
            int i2 = c / WSZ, j2 = c - i2 * WSZ;
            int rel = (i1 - i2 + 6) * 13 + (j1 - j2 + 6);
            v = rpb[rel * NHEADS + head] + amask[((size_t)wi_rep * NTOK + r) * NTOK + c];
        } else {
            v = -100.f;
        }
        dst[idx] = __float2half(v);
    }
}

// ---------------- LN1 (fused shift + window partition) ----------------
__global__ __launch_bounds__(256) void ln1_kernel(const float* __restrict__ src_full,
                                                  const float* __restrict__ gam,
                                                  const float* __restrict__ bet,
                                                  __half* __restrict__ out) {
    int t = blockIdx.x * 8 + (threadIdx.x >> 5);
    int lane = threadIdx.x & 31;
    int win = t / NTOK, n = t - win * NTOK;
    int b = win >> 8, wi = win & 255;
    int hh = (wi >> 4) * WSZ + n / WSZ;
    int ww = (wi & 15) * WSZ + n % WSZ;
    int sh = hh + 3; if (sh >= IMG) sh -= IMG;
    int sw = ww + 3; if (sw >= IMG) sw -= IMG;
    const float* src = src_full + (size_t)((b * IMG + sh) * IMG + sw) * CC;

    float v[6]; float s = 0.f, s2 = 0.f;
    #pragma unroll
    for (int i = 0; i < 6; i++) { float a = src[i * 32 + lane]; v[i] = a; s += a; s2 += a * a; }
    #pragma unroll
    for (int o = 16; o; o >>= 1) {
        s  += __shfl_xor_sync(0xffffffffu, s,  o);
        s2 += __shfl_xor_sync(0xffffffffu, s2, o);
    }
    float mean = s * (1.f / 192.f);
    float var  = s2 * (1.f / 192.f) - mean * mean;
    float rstd = rsqrtf(var + 1e-5f);
    __half* dst = out + (size_t)t * CC;
    #pragma unroll
    for (int i = 0; i < 6; i++) {
        int c = i * 32 + lane;
        dst[c] = __float2half((v[i] - mean) * rstd * gam[c] + bet[c]);
    }
}

// ================= gemm_full: K=192 resident in smem, no K-loop =================
// BM=64, BN=192, full K. 256 thr (8 warps 2x4), warp tile 32x48. 2 CTA/SM.
// smem: A 24KB @0, B 72KB @24576 -> 96KB.
#define SMEM_FULL 98304
template<int EPI>
__global__ __launch_bounds__(256, 2)
void gemm_full(const __half* __restrict__ A2, const __half* __restrict__ B2,
               const float* __restrict__ bias, float* __restrict__ outF,
               const float* __restrict__ addsrc, __half* __restrict__ outS,
               const float* __restrict__ g2, const float* __restrict__ b2,
               __half* __restrict__ xsOut) {
    extern __shared__ __align__(16) char sm_dyn[];
    uint32_t a_base = smem_to_u32(sm_dyn);
    uint32_t b_base = a_base + 24576;

    int tid = threadIdx.x, lane = tid & 31, wid = tid >> 5;
    int wm = wid >> 2, wn = wid & 3;
    int bm = blockIdx.y * 64, bn = blockIdx.x * 192;
    const int K = 192;

    // ---- load whole A (64x192) + B slice (192x192) ----
    {
        const __half* Ag = A2 + (size_t)bm * K;
        #pragma unroll
        for (int i = 0; i < 6; i++) {           // 1536 chunks
            int t = tid + i * 256, row = t / 24, c = t - row * 24;
            cp16(full_addr(a_base, row, c), Ag + (size_t)row * K + c * 8);
        }
        const __half* Bg = B2 + (size_t)bn * K;
        #pragma unroll
        for (int i = 0; i < 18; i++) {          // 4608 chunks
            int t = tid + i * 256, row = t / 24, c = t - row * 24;
            cp16(full_addr(b_base, row, c), Bg + (size_t)row * K + c * 8);
        }
    }
    cp_commit();
    cp_wait0();
    __syncthreads();

    // ---- 12 k-steps, 144 MMAs, no barriers ----
    float acc[2][6][4] = {};
    int arow = wm * 32 + (lane & 15);
    int bnrow = wn * 48 + (lane & 7) + ((lane >> 4) << 3);
    int bk8 = (lane >> 3) & 1;
    #pragma unroll
    for (int ks = 0; ks < 12; ks++) {
        uint32_t af[2][4];
        #pragma unroll
        for (int mt = 0; mt < 2; mt++)
            ldm4(af[mt][0], af[mt][1], af[mt][2], af[mt][3],
                 full_addr(a_base, arow + mt * 16, ks * 2 + (lane >> 4)));
        uint32_t bf[6][2];
        #pragma unroll
        for (int pr = 0; pr < 3; pr++)
            ldm4(bf[2 * pr][0], bf[2 * pr][1], bf[2 * pr + 1][0], bf[2 * pr + 1][1],
                 full_addr(b_base, bnrow + pr * 16, ks * 2 + bk8));
        #pragma unroll
        for (int mt = 0; mt < 2; mt++)
            #pragma unroll
            for (int nt = 0; nt < 6; nt++)
                mma16816(acc[mt][nt][0], acc[mt][nt][1], acc[mt][nt][2], acc[mt][nt][3],
                         af[mt][0], af[mt][1], af[mt][2], af[mt][3],
                         bf[nt][0], bf[nt][1]);
    }
    __syncthreads();   // A/B tiles dead; smem reusable by EPI==2 reduction

    float2 bcol[6];
    #pragma unroll
    for (int nt = 0; nt < 6; nt++) {
        int col = bn + wn * 48 + nt * 8 + 2 * (lane & 3);
        bcol[nt] = *(const float2*)&bias[col];
    }

    if constexpr (EPI == 2) {
        float* red  = (float*)sm_dyn;          // [64][17]
        float* redq = red + 64 * 17;
        int slot = wn * 4 + (lane & 3);

        #pragma unroll
        for (int mt = 0; mt < 2; mt++) {
            #pragma unroll
            for (int half = 0; half < 2; half++) {
                int rl = wm * 32 + mt * 16 + (lane >> 2) + half * 8;
                int row = bm + rl;
                int win = row / NTOK, n = row - win * NTOK;
                int b = win >> 8, wi = win & 255;
                int hh = (wi >> 4) * WSZ + n / WSZ;
                int ww = (wi & 15) * WSZ + n % WSZ;
                int p = hh + 3; if (p >= IMG) p -= IMG;
                int q = ww + 3; if (q >= IMG) q -= IMG;
                size_t pixbase = (size_t)((b * IMG + p) * IMG + q) * CC;
                float s = 0.f, sq2 = 0.f;
                #pragma unroll
                for (int nt = 0; nt < 6; nt++) {
                    int col = wn * 48 + nt * 8 + 2 * (lane & 3);
                    float2 sc = *(const float2*)&addsrc[pixbase + col];
                    float vx = acc[mt][nt][half * 2] + bcol[nt].x + sc.x;
                    float vy = acc[mt][nt][half * 2 + 1] + bcol[nt].y + sc.y;
                    acc[mt][nt][half * 2] = vx;
                    acc[mt][nt][half * 2 + 1] = vy;
                    *(float2*)&outF[pixbase + col] = make_float2(vx, vy);
                    s += vx + vy;
                    sq2 += vx * vx + vy * vy;
                }
                red [rl * 17 + slot] = s;
                redq[rl * 17 + slot] = sq2;
            }
        }
        __syncthreads();
        if (tid < 64) {
            float s = 0.f, qq = 0.f;
            #pragma unroll
            for (int i = 0; i < 16; i++) { s += red[tid * 17 + i]; qq += redq[tid * 17 + i]; }
            float mean = s * (1.f / 192.f);
            float var = qq * (1.f / 192.f) - mean * mean;
            red [tid * 17 + 16] = mean;
            redq[tid * 17 + 16] = rsqrtf(var + 1e-5f);
        }
        __syncthreads();
        #pragma unroll
        for (int mt = 0; mt < 2; mt++) {
            #pragma unroll
            for (int half = 0; half < 2; half++) {
                int rl = wm * 32 + mt * 16 + (lane >> 2) + half * 8;
                int row = bm + rl;
                int win = row / NTOK, n = row - win * NTOK;
                int b = win >> 8, wi = win & 255;
                int hh = (wi >> 4) * WSZ + n / WSZ;
                int ww = (wi & 15) * WSZ + n % WSZ;
                int p = hh + 3; if (p >= IMG) p -= IMG;
                int q = ww + 3; if (q >= IMG) q -= IMG;
                size_t pixbase = (size_t)((b * IMG + p) * IMG + q) * CC;
                float mean = red [rl * 17 + 16];
                float rstd = redq[rl * 17 + 16];
                #pragma unroll
                for (int nt = 0; nt < 6; nt++) {
                    int col = wn * 48 + nt * 8 + 2 * (lane & 3);
                    float2 gv = *(const float2*)&g2[col];
                    float2 bv = *(const float2*)&b2[col];
                    float yx = (acc[mt][nt][half * 2] - mean) * rstd * gv.x + bv.x;
                    float yy = (acc[mt][nt][half * 2 + 1] - mean) * rstd * gv.y + bv.y;
                    *(__half2*)&xsOut[pixbase + col] = __floats2half2_rn(yx, yy);
                }
            }
        }
    } else {
        #pragma unroll
        for (int mt = 0; mt < 2; mt++) {
            #pragma unroll
            for (int half = 0; half < 2; half++) {
                int row = bm + wm * 32 + mt * 16 + (lane >> 2) + half * 8;
                if constexpr (EPI == 1) {
                    int t3 = bn / 192;
                    float scale = (t3 == 0) ? 0.17677669529663687f : 1.f;
                    __half* dst = (t3 == 0) ? g_q : ((t3 == 1) ? g_k : g_v);
                    int win = row / NTOK, n = row - win * NTOK;
                    #pragma unroll
                    for (int nt = 0; nt < 6; nt++) {
                        int col = wn * 48 + nt * 8 + 2 * (lane & 3);
                        int head = col >> 5, dd = col & 31;
                        float vx = (acc[mt][nt][half * 2] + bcol[nt].x) * scale;
                        float vy = (acc[mt][nt][half * 2 + 1] + bcol[nt].y) * scale;
                        *(__half2*)&dst[(((size_t)win * NHEADS + head) * NTOK + n) * DHEAD + dd] =
                            __floats2half2_rn(vx, vy);
                    }
                } else {  // EPI == 3: gelu -> fp16
                    size_t rb = (size_t)row * HID;
                    #pragma unroll
                    for (int nt = 0; nt < 6; nt++) {
                        int col = bn + wn * 48 + nt * 8 + 2 * (lane & 3);
                        float gx = gelu_exact(acc[mt][nt][half * 2] + bcol[nt].x);
                        float gy = gelu_exact(acc[mt][nt][half * 2 + 1] + bcol[nt].y);
                        *(__half2*)&outS[rb + col] = __floats2half2_rn(gx, gy);
                    }
                }
            }
        }
    }
}

// ================= gemm_pipe (fc2: K=768): 3-stage BK=32 pipeline =================
#define SMEM_PIPE 49152
__global__ __launch_bounds__(256, 2)
void gemm_pipe(const __half* __restrict__ A2, const __half* __restrict__ B2,
               const float* __restrict__ bias, float* __restrict__ outF,
               const float* __restrict__ addsrc, int K) {
    extern __shared__ __align__(16) char sm_dyn[];
    uint32_t a_base = smem_to_u32(sm_dyn);
    uint32_t b_base = a_base + 12288;

    int tid = threadIdx.x, lane = tid & 31, wid = tid >> 5;
    int wm = wid >> 2, wn = wid & 3;
    int bm = blockIdx.y * 64, bn = blockIdx.x * 192;
    const int NC = K >> 5;

    float acc[2][6][4] = {};

    auto issue = [&](int buf, int cc) {
        const __half* Ag = A2 + (size_t)bm * K + cc * 32;
        const __half* Bg = B2 + (size_t)bn * K + cc * 32;
        uint32_t ab = a_base + buf * 4096;
        uint32_t bb = b_base + buf * 12288;
        {
            int row = tid >> 2, c = tid & 3;
            cp16(tile_addr(ab, row, c), Ag + (size_t)row * K + c * 8);
        }
        #pragma unroll
        for (int i = 0; i < 3; i++) {
            int t = tid + i * 256, row = t >> 2, c = t & 3;
            cp16(tile_addr(bb, row, c), Bg + (size_t)row * K + c * 8);
        }
        cp_commit();
    };

    issue(0, 0);
    issue(1, 1);

    for (int cc = 0; cc < NC; cc++) {
        int buf = cc % 3;
        if (cc + 1 < NC) cp_wait1(); else cp_wait0();
        __syncthreads();
        if (cc + 2 < NC) issue((cc + 2) % 3, cc + 2);

        uint32_t ab = a_base + buf * 4096;
        uint32_t bb = b_base + buf * 12288;
        int arow = wm * 32 + (lane & 15);
        int bnrow = wn * 48 + (lane & 7) + ((lane >> 4) << 3);
        int bk8 = (lane >> 3) & 1;
        #pragma unroll
        for (int ks = 0; ks < 2; ks++) {
            uint32_t af[2][4];
            #pragma unroll
            for (int mt = 0; mt < 2; mt++)
                ldm4(af[mt][0], af[mt][1], af[mt][2], af[mt][3],
                     tile_addr(ab, arow + mt * 16, ks * 2 + (lane >> 4)));
            uint32_t bf[6][2];
            #pragma unroll
            for (int pr = 0; pr < 3; pr++)
                ldm4(bf[2 * pr][0], bf[2 * pr][1], bf[2 * pr + 1][0], bf[2 * pr + 1][1],
                     tile_addr(bb, bnrow + pr * 16, ks * 2 + bk8));
            #pragma unroll
            for (int mt = 0; mt < 2; mt++)
                #pragma unroll
                for (int nt = 0; nt < 6; nt++)
                    mma16816(acc[mt][nt][0], acc[mt][nt][1], acc[mt][nt][2], acc[mt][nt][3],
                             af[mt][0], af[mt][1], af[mt][2], af[mt][3],
                             bf[nt][0], bf[nt][1]);
        }
    }

    float2 bcol[6];
    #pragma unroll
    for (int nt = 0; nt < 6; nt++) {
        int col = bn + wn * 48 + nt * 8 + 2 * (lane & 3);
        bcol[nt] = *(const float2*)&bias[col];
    }
    #pragma unroll
    for (int mt = 0; mt < 2; mt++) {
        #pragma unroll
        for (int half = 0; half < 2; half++) {
            int row = bm + wm * 32 + mt * 16 + (lane >> 2) + half * 8;
            size_t rb = (size_t)row * 192;
            #pragma unroll
            for (int nt = 0; nt < 6; nt++) {
                int col = bn + wn * 48 + nt * 8 + 2 * (lane & 3);
                float2 s = *(const float2*)&addsrc[rb + col];
                float vx = acc[mt][nt][half * 2] + bcol[nt].x + s.x;
                float vy = acc[mt][nt][half * 2 + 1] + bcol[nt].y + s.y;
                *(float2*)&outF[rb + col] = make_float2(vx, vy);
            }
        }
    }
}

// ---------------- tensor-core windowed attention: 256 thr, 2 heads in parallel ----------------
__global__ __launch_bounds__(256) void attn_mma(__half* __restrict__ outs) {
    int win = blockIdx.x;
    int wi = win & 255;
    int cls = (((wi >> 4) == 15) ? 2 : 0) + (((wi & 15) == 15) ? 1 : 0);
    __shared__ __align__(16) __half sQ[2][64 * 40], sK[2][64 * 40], sV[2][64 * 40];
    __shared__ __align__(16) __half sC[2][64 * 56];
    int tid = threadIdx.x;
    int wg = tid >> 7;
    int t = tid & 127;
    int lane = t & 31, wmg = t >> 5;
    int g = lane >> 3, r8 = lane & 7;
    int mr = wmg * 16;
    uint32_t qbase = smem_to_u32(sQ[wg]), kbase = smem_to_u32(sK[wg]);
    uint32_t vbase = smem_to_u32(sV[wg]), cbase = smem_to_u32(sC[wg]);

    uint4 z = make_uint4(0, 0, 0, 0);
    for (int i = tid; i < 640; i += 256) {
        ((uint4*)sQ)[i] = z; ((uint4*)sK)[i] = z; ((uint4*)sV)[i] = z;
    }
    __syncthreads();

    for (int h2 = 0; h2 < 3; h2++) {
        int h = h2 * 2 + wg;
        {
            const uint4* qg = (const uint4*)(g_q + (size_t)(win * NHEADS + h) * (NTOK * DHEAD));
            const uint4* kg = (const uint4*)(g_k + (size_t)(win * NHEADS + h) * (NTOK * DHEAD));
            const uint4* vg = (const uint4*)(g_v + (size_t)(win * NHEADS + h) * (NTOK * DHEAD));
            for (int i = t; i < 196; i += 128) {
                int r = i >> 2, c = i & 3;
                *(uint4*)(sQ[wg] + r * 40 + c * 8) = qg[i];
                *(uint4*)(sK[wg] + r * 40 + c * 8) = kg[i];
                *(uint4*)(sV[wg] + r * 40 + c * 8) = vg[i];
            }
            const uint4* cg = (const uint4*)(g_cmb + (size_t)(cls * NHEADS + h) * (64 * 56));
            for (int i = t; i < 448; i += 128) ((uint4*)sC[wg])[i] = cg[i];
        }
        __syncthreads();

        uint32_t qf[2][4];
        #pragma unroll
        for (int ks = 0; ks < 2; ks++) {
            int row = mr + (g & 1) * 8 + r8;
            int col = ks * 16 + (g >> 1) * 8;
            ldm4(qf[ks][0], qf[ks][1], qf[ks][2], qf[ks][3], qbase + row * 80 + col * 2);
        }

        float sacc[7][4] = {};
        #pragma unroll
        for (int ks = 0; ks < 2; ks++) {
            #pragma unroll
            for (int np = 0; np < 4; np++) {
                int row = np * 16 + ((g >> 1) & 1) * 8 + r8;
                int col = ks * 16 + (g & 1) * 8;
                uint32_t b0, b1, b2, b3;
                ldm4(b0, b1, b2, b3, kbase + row * 80 + col * 2);
                mma16816(sacc[2 * np][0], sacc[2 * np][1], sacc[2 * np][2], sacc[2 * np][3],
                         qf[ks][0], qf[ks][1], qf[ks][2], qf[ks][3], b0, b1);
                if (np < 3)
                    mma16816(sacc[2 * np + 1][0], sacc[2 * np + 1][1], sacc[2 * np + 1][2], sacc[2 * np + 1][3],
                             qf[ks][0], qf[ks][1], qf[ks][2], qf[ks][3], b2, b3);
            }
        }

        #pragma unroll
        for (int np = 0; np < 4; np++) {
            int row = mr + (g & 1) * 8 + r8;
            int colc = 2 * np + ((g >> 1) & 1); if (colc > 6) colc = 6;
            uint32_t c0, c1, c2, c3;
            ldm4(c0, c1, c2, c3, cbase + row * 112 + colc * 8 * 2);
            float2 f;
            f = __half22float2(*(__half2*)&c0); sacc[2 * np][0] += f.x; sacc[2 * np][1] += f.y;
            f = __half22float2(*(__half2*)&c1); sacc[2 * np][2] += f.x; sacc[2 * np][3] += f.y;
            if (np < 3) {
                f = __half22float2(*(__half2*)&c2); sacc[2 * np + 1][0] += f.x; sacc[2 * np + 1][1] += f.y;
                f = __half22float2(*(__half2*)&c3); sacc[2 * np + 1][2] += f.x; sacc[2 * np + 1][3] += f.y;
            }
        }

        float mx0 = -1e30f, mx8 = -1e30f;
        #pragma unroll
        for (int nt = 0; nt < 7; nt++) {
            mx0 = fmaxf(mx0, fmaxf(sacc[nt][0], sacc[nt][1]));
            mx8 = fmaxf(mx8, fmaxf(sacc[nt][2], sacc[nt][3]));
        }
        #pragma unroll
        for (int o = 1; o <= 2; o <<= 1) {
            mx0 = fmaxf(mx0, __shfl_xor_sync(0xffffffffu, mx0, o));
            mx8 = fmaxf(mx8, __shfl_xor_sync(0xffffffffu, mx8, o));
        }
        float s0 = 0.f, s8 = 0.f;
        #pragma unroll
        for (int nt = 0; nt < 7; nt++) {
            sacc[nt][0] = __expf(sacc[nt][0] - mx0); s0 += sacc[nt][0];
            sacc[nt][1] = __expf(sacc[nt][1] - mx0); s0 += sacc[nt][1];
            sacc[nt][2] = __expf(sacc[nt][2] - mx8); s8 += sacc[nt][2];
            sacc[nt][3] = __expf(sacc[nt][3] - mx8); s8 += sacc[nt][3];
        }
        #pragma unroll
        for (int o = 1; o <= 2; o <<= 1) {
            s0 += __shfl_xor_sync(0xffffffffu, s0, o);
            s8 += __shfl_xor_sync(0xffffffffu, s8, o);
        }
        float inv0 = 1.f / s0, inv8 = 1.f / s8;
        #pragma unroll
        for (int nt = 0; nt < 7; nt++) {
            sacc[nt][0] *= inv0; sacc[nt][1] *= inv0;
            sacc[nt][2] *= inv8; sacc[nt][3] *= inv8;
        }

        float oacc[4][4] = {};
        #pragma unroll
        for (int kt = 0; kt < 4; kt++) {
            uint32_t a0 = f22u(sacc[2 * kt][0], sacc[2 * kt][1]);
            uint32_t a1 = f22u(sacc[2 * kt][2], sacc[2 * kt][3]);
            uint32_t a2 = 0, a3 = 0;
            if (kt < 3) {
                a2 = f22u(sacc[2 * kt + 1][0], sacc[2 * kt + 1][1]);
                a3 = f22u(sacc[2 * kt + 1][2], sacc[2 * kt + 1][3]);
            }
            #pragma unroll
            for (int dp = 0; dp < 2; dp++) {
                int row = kt * 16 + (g & 1) * 8 + r8;
                int col = dp * 16 + ((g >> 1) & 1) * 8;
                uint32_t b0, b1, b2, b3;
                ldm4t(b0, b1, b2, b3, vbase + row * 80 + col * 2);
                mma16816(oacc[2 * dp][0], oacc[2 * dp][1], oacc[2 * dp][2], oacc[2 * dp][3],
                         a0, a1, a2, a3, b0, b1);
                mma16816(oacc[2 * dp + 1][0], oacc[2 * dp + 1][1], oacc[2 * dp + 1][2], oacc[2 * dp + 1][3],
                         a0, a1, a2, a3, b2, b3);
            }
        }

        int r0 = mr + (lane >> 2);
        int cbase2 = h * DHEAD + 2 * (lane & 3);
        if (r0 < NTOK) {
            size_t ob = ((size_t)win * NTOK + r0) * CC + cbase2;
            #pragma unroll
            for (int dn = 0; dn < 4; dn++)
                *(__half2*)&outs[ob + dn * 8] = __floats2half2_rn(oacc[dn][0], oacc[dn][1]);
        }
        int r1 = r0 + 8;
        if (r1 < NTOK) {
            size_t ob = ((size_t)win * NTOK + r1) * CC + cbase2;
            #pragma unroll
            for (int dn = 0; dn < 4; dn++)
                *(__half2*)&outs[ob + dn * 8] = __floats2half2_rn(oacc[dn][2], oacc[dn][3]);
        }
        __syncthreads();
    }
}

// ---------------- launch ----------------
extern "C" void kernel_launch(void* const* d_in, const int* in_sizes, int n_in,
                              void* d_out, int out_size) {
    const float* x      = (const float*)d_in[0];
    const float* amask  = (const float*)d_in[1];
    const float* n1g    = (const float*)d_in[2];
    const float* n1b    = (const float*)d_in[3];
    const float* qkv_w  = (const float*)d_in[4];
    const float* qkv_b  = (const float*)d_in[5];
    const float* rpb    = (const float*)d_in[6];
    const float* proj_w = (const float*)d_in[7];
    const float* proj_b = (const float*)d_in[8];
    const float* n2g    = (const float*)d_in[9];
    const float* n2b    = (const float*)d_in[10];
    const float* fc1_w  = (const float*)d_in[11];
    const float* fc1_b  = (const float*)d_in[12];
    const float* fc2_w  = (const float*)d_in[13];
    const float* fc2_b  = (const float*)d_in[14];
    float* out = (float*)d_out;

    __half *xs, *aos, *hs, *wqkv, *wproj, *wfc1, *wfc2;
    float *x2;
    cudaGetSymbolAddress((void**)&xs,    g_xs);
    cudaGetSymbolAddress((void**)&aos,   g_aos);
    cudaGetSymbolAddress((void**)&hs,    g_hs);
    cudaGetSymbolAddress((void**)&x2,    g_x2);
    cudaGetSymbolAddress((void**)&wqkv,  g_wqkv);
    cudaGetSymbolAddress((void**)&wproj, g_wproj);
    cudaGetSymbolAddress((void**)&wfc1,  g_wfc1);
    cudaGetSymbolAddress((void**)&wfc2,  g_wfc2);

    cudaFuncSetAttribute(gemm_full<1>, cudaFuncAttributeMaxDynamicSharedMemorySize, SMEM_FULL);
    cudaFuncSetAttribute(gemm_full<2>, cudaFuncAttributeMaxDynamicSharedMemorySize, SMEM_FULL);
    cudaFuncSetAttribute(gemm_full<3>, cudaFuncAttributeMaxDynamicSharedMemorySize, SMEM_FULL);
    cudaFuncSetAttribute(gemm_pipe,    cudaFuncAttributeMaxDynamicSharedMemorySize, SMEM_PIPE);

    const int MB = MROWS / 64;  // 3136

    prep_all<<<1728, 256>>>(qkv_w, proj_w, fc1_w, fc2_w);
    prep_cmb<<<24, 256>>>(amask, rpb);
    ln1_kernel<<<MROWS / 8, 256>>>(x, n1g, n1b, xs);
    gemm_full<1><<<dim3(3, MB), 256, SMEM_FULL>>>(xs, wqkv, qkv_b, nullptr, nullptr, nullptr,
                                                  nullptr, nullptr, nullptr);
    attn_mma<<<NWIN, 256>>>(aos);
    gemm_full<2><<<dim3(1, MB), 256, SMEM_FULL>>>(aos, wproj, proj_b, x2, x, nullptr,
                                                  n2g, n2b, xs);
    gemm_full<3><<<dim3(4, MB), 256, SMEM_FULL>>>(xs, wfc1, fc1_b, nullptr, nullptr, hs,
                                                  nullptr, nullptr, nullptr);
    gemm_pipe<<<dim3(1, MB), 256, SMEM_PIPE>>>(hs, wfc2, fc2_b, out, x2, 768);
}